// round 2
// baseline (speedup 1.0000x reference)
#include <cuda_runtime.h>
#include <math.h>

#define BSZ   8
#define SEQ   4096
#define NTOK  3000
#define DIN   128
#define DM    512
#define DFF   2048
#define DOUT  64
#define DH    128
#define MTOT  (BSZ*SEQ)              // 32768 rows
#define SCALE 0.08838834764831845f   // 1/sqrt(128)

// ---------------- scratch (static device globals: no allocation) -------------
__device__ float g_xp[MTOT*DIN];
__device__ float g_h[MTOT*DM];
__device__ float g_ln[MTOT*DM];
__device__ float g_q[MTOT*DM];
__device__ float g_k[MTOT*DM];
__device__ float g_v[MTOT*DM];
__device__ float g_attn[MTOT*DM];
__device__ float g_ff[MTOT*DFF];
__device__ float g_of[MTOT*DOUT];
__device__ float g_kmax[BSZ*3*DH];
__device__ float g_klse[BSZ*3*DH];
__device__ float g_ctxp[BSZ*3*8*DH*DH];
__device__ float g_ctx[BSZ*3*DH*DH];

// ---------------- pad x (8,3000,128) -> (8,4096,128) ------------------------
__global__ void pad_x_kernel(const float* __restrict__ x) {
    int idx = blockIdx.x*256 + threadIdx.x;
    const int total = MTOT*DIN/4;
    if (idx >= total) return;
    int row = idx >> 5;            // 32 float4 per row
    int c4  = idx & 31;
    int b = row / SEQ, t = row - b*SEQ;
    float4 val = make_float4(0.f,0.f,0.f,0.f);
    if (t < NTOK)
        val = reinterpret_cast<const float4*>(x)[(size_t)(b*NTOK + t)*32 + c4];
    reinterpret_cast<float4*>(g_xp)[idx] = val;
}

// ---------------- generic tiled SGEMM: C = act(A@B + bias) + res -------------
// 128x128 block tile, BK=16, 256 threads, 8x8 per thread.
__global__ __launch_bounds__(256) void sgemm_kernel(
    const float* __restrict__ A, const float* __restrict__ B,
    const float* __restrict__ bias, const float* __restrict__ res,
    float* __restrict__ C, int M, int N, int K, int act)
{
    __shared__ float As[16][132];
    __shared__ float Bs[16][128];
    int tid = threadIdx.x;
    int bm = blockIdx.y << 7, bn = blockIdx.x << 7;
    int tx = tid & 15, ty = tid >> 4;
    int arow = tid >> 2, acol = (tid & 3) << 2;
    int brow = tid >> 5, bcol = (tid & 31) << 2;
    float acc[8][8];
    #pragma unroll
    for (int i=0;i<8;i++)
        #pragma unroll
        for (int j=0;j<8;j++) acc[i][j]=0.f;

    for (int k0=0; k0<K; k0+=16) {
        #pragma unroll
        for (int rr=0; rr<2; rr++) {
            int r = arow + rr*64;
            float4 a = *reinterpret_cast<const float4*>(A + (size_t)(bm+r)*K + k0 + acol);
            As[acol+0][r]=a.x; As[acol+1][r]=a.y; As[acol+2][r]=a.z; As[acol+3][r]=a.w;
        }
        #pragma unroll
        for (int rr=0; rr<2; rr++) {
            int r = brow + rr*8;
            int gc = bn + bcol;
            float4 bv = make_float4(0.f,0.f,0.f,0.f);
            if (gc < N) bv = *reinterpret_cast<const float4*>(B + (size_t)(k0+r)*N + gc);
            *reinterpret_cast<float4*>(&Bs[r][bcol]) = bv;
        }
        __syncthreads();
        #pragma unroll
        for (int kk=0; kk<16; kk++) {
            float af[8], bf[8];
            *reinterpret_cast<float4*>(&af[0]) = *reinterpret_cast<const float4*>(&As[kk][ty*8]);
            *reinterpret_cast<float4*>(&af[4]) = *reinterpret_cast<const float4*>(&As[kk][ty*8+4]);
            *reinterpret_cast<float4*>(&bf[0]) = *reinterpret_cast<const float4*>(&Bs[kk][tx*8]);
            *reinterpret_cast<float4*>(&bf[4]) = *reinterpret_cast<const float4*>(&Bs[kk][tx*8+4]);
            #pragma unroll
            for (int i=0;i<8;i++)
                #pragma unroll
                for (int j=0;j<8;j++)
                    acc[i][j] = fmaf(af[i], bf[j], acc[i][j]);
        }
        __syncthreads();
    }
    #pragma unroll
    for (int i=0;i<8;i++) {
        int row = bm + ty*8 + i;
        #pragma unroll
        for (int j=0;j<8;j++) {
            int col = bn + tx*8 + j;
            if (col < N) {
                float v = acc[i][j];
                if (bias) v += bias[col];
                if (act == 1) v = tanhf(v);
                else if (act == 2) v = 0.5f*v*(1.f + erff(v*0.7071067811865476f));
                if (res) v += res[(size_t)row*N + col];
                C[(size_t)row*N + col] = v;
            }
        }
    }
}

// ---------------- LayerNorm over rows of length 512 (1 warp / row) ----------
__global__ void ln_kernel(const float* __restrict__ in, const float* __restrict__ gam,
                          const float* __restrict__ bet, float* __restrict__ out) {
    int gw = (blockIdx.x*blockDim.x + threadIdx.x) >> 5;
    int lane = threadIdx.x & 31;
    if (gw >= MTOT) return;
    const float4* rp = reinterpret_cast<const float4*>(in + (size_t)gw*DM);
    float4 v[4];
    float s=0.f, s2=0.f;
    #pragma unroll
    for (int i=0;i<4;i++) {
        v[i] = rp[lane + 32*i];
        s  += v[i].x+v[i].y+v[i].z+v[i].w;
        s2 += v[i].x*v[i].x + v[i].y*v[i].y + v[i].z*v[i].z + v[i].w*v[i].w;
    }
    #pragma unroll
    for (int o=16;o;o>>=1) { s += __shfl_xor_sync(~0u,s,o); s2 += __shfl_xor_sync(~0u,s2,o); }
    float mu  = s*(1.f/512.f);
    float var = s2*(1.f/512.f) - mu*mu;
    float r = rsqrtf(var + 1e-5f);
    float4* op = reinterpret_cast<float4*>(out + (size_t)gw*DM);
    #pragma unroll
    for (int i=0;i<4;i++) {
        int c = (lane + 32*i)*4;
        float4 g4 = *reinterpret_cast<const float4*>(gam + c);
        float4 b4 = *reinterpret_cast<const float4*>(bet + c);
        float4 o4;
        o4.x = (v[i].x-mu)*r*g4.x + b4.x;
        o4.y = (v[i].y-mu)*r*g4.y + b4.y;
        o4.z = (v[i].z-mu)*r*g4.z + b4.z;
        o4.w = (v[i].w-mu)*r*g4.w + b4.w;
        op[lane + 32*i] = o4;
    }
}

// ---------------- local attention, head 0, window 128 with look-around ------
// grid: b*32win*4qchunk; block 1024 = 32 warps; 1 warp per query.
__global__ __launch_bounds__(1024) void local_attn_kernel() {
    __shared__ float tile[64][DH];      // 32 KB: K chunk, then V chunk
    __shared__ float scores[32][64];    // 8 KB
    int bx = blockIdx.x;
    int b   = bx >> 7;
    int win = (bx >> 2) & 31;
    int qc  = bx & 3;
    int warp = threadIdx.x >> 5, lane = threadIdx.x & 31;
    int qt = win*128 + qc*32 + warp;
    size_t qoff = (size_t)(b*SEQ + qt)*DM;  // head 0 = cols 0..127
    float4 q4 = *reinterpret_cast<const float4*>(g_q + qoff + lane*4);
    float m = -1e30f, l = 0.f;
    float4 acc = make_float4(0.f,0.f,0.f,0.f);
    int kbase = win*128 - 128;
    for (int ch=0; ch<6; ch++) {
        int t0 = kbase + ch*64;
        __syncthreads();
        #pragma unroll
        for (int it=0; it<2; it++) {               // load K chunk
            int idx = it*1024 + threadIdx.x;
            int r = idx >> 5, c4 = idx & 31;
            int t = t0 + r;
            float4 kv = make_float4(0.f,0.f,0.f,0.f);
            if (t >= 0 && t < SEQ)
                kv = *reinterpret_cast<const float4*>(g_k + (size_t)(b*SEQ+t)*DM + c4*4);
            *reinterpret_cast<float4*>(&tile[r][c4*4]) = kv;
        }
        __syncthreads();
        for (int j=0; j<64; j++) {                 // scores
            float4 kv = *reinterpret_cast<const float4*>(&tile[j][lane*4]);
            float s = q4.x*kv.x + q4.y*kv.y + q4.z*kv.z + q4.w*kv.w;
            #pragma unroll
            for (int o=16;o;o>>=1) s += __shfl_xor_sync(~0u,s,o);
            if (lane == (j & 31)) {
                int t = t0 + j;
                scores[warp][j] = (t >= 0 && t < SEQ) ? s*SCALE : -1e38f;
            }
        }
        __syncthreads();
        #pragma unroll
        for (int it=0; it<2; it++) {               // load V chunk (same tile)
            int idx = it*1024 + threadIdx.x;
            int r = idx >> 5, c4 = idx & 31;
            int t = t0 + r;
            float4 vv = make_float4(0.f,0.f,0.f,0.f);
            if (t >= 0 && t < SEQ)
                vv = *reinterpret_cast<const float4*>(g_v + (size_t)(b*SEQ+t)*DM + c4*4);
            *reinterpret_cast<float4*>(&tile[r][c4*4]) = vv;
        }
        __syncthreads();
        float cm = fmaxf(scores[warp][lane], scores[warp][lane+32]);
        #pragma unroll
        for (int o=16;o;o>>=1) cm = fmaxf(cm, __shfl_xor_sync(~0u,cm,o));
        float mn = fmaxf(m, cm);
        float corr = expf(m - mn);
        l *= corr; acc.x*=corr; acc.y*=corr; acc.z*=corr; acc.w*=corr;
        for (int j=0; j<64; j++) {
            float p = expf(scores[warp][j] - mn);
            l += p;
            float4 vv = *reinterpret_cast<const float4*>(&tile[j][lane*4]);
            acc.x = fmaf(p, vv.x, acc.x);
            acc.y = fmaf(p, vv.y, acc.y);
            acc.z = fmaf(p, vv.z, acc.z);
            acc.w = fmaf(p, vv.w, acc.w);
        }
        m = mn;
    }
    float inv = 1.f/l;
    float4 o4 = make_float4(acc.x*inv, acc.y*inv, acc.z*inv, acc.w*inv);
    *reinterpret_cast<float4*>(g_attn + qoff + lane*4) = o4;
}

// ---------------- k column softmax stats (heads 1..3) -----------------------
// grid (24, 4); block (32,8). Online max/sum-exp over t.
__global__ void kstats_kernel() {
    int bh = blockIdx.x;
    int b = bh/3, hh = bh%3 + 1;
    int d = blockIdx.y*32 + threadIdx.x;
    int ty = threadIdx.y;
    int col = hh*DH + d;
    float m = -1e30f, l = 0.f;
    for (int t = ty; t < SEQ; t += 8) {
        float val = g_k[(size_t)(b*SEQ+t)*DM + col];
        if (val > m) { l = l*expf(m - val) + 1.f; m = val; }
        else l += expf(val - m);
    }
    __shared__ float sm[8][32], sl[8][32];
    sm[ty][threadIdx.x] = m; sl[ty][threadIdx.x] = l;
    __syncthreads();
    if (ty == 0) {
        #pragma unroll
        for (int r=1;r<8;r++) {
            float m2 = sm[r][threadIdx.x], l2 = sl[r][threadIdx.x];
            float M = fmaxf(m, m2);
            l = l*expf(m - M) + l2*expf(m2 - M);
            m = M;
        }
        g_kmax[bh*DH + d] = m;
        g_klse[bh*DH + d] = l;
    }
}

// ---------------- ctx partial: ctx[d][e] = sum_t k'[t,d] v[t,e] (K-split 8) --
__global__ __launch_bounds__(256) void ctx_partial_kernel() {
    __shared__ float kt[32][132];
    __shared__ float vt[32][132];
    __shared__ float smax[DH], sinv[DH];
    int bh = blockIdx.x, ks = blockIdx.y;
    int b = bh/3, hh = bh%3 + 1;
    if (threadIdx.x < DH) {
        smax[threadIdx.x] = g_kmax[bh*DH + threadIdx.x];
        sinv[threadIdx.x] = 1.f/g_klse[bh*DH + threadIdx.x];
    }
    int tx = threadIdx.x & 15, ty = threadIdx.x >> 4;
    float acc[8][8];
    #pragma unroll
    for (int i=0;i<8;i++)
        #pragma unroll
        for (int j=0;j<8;j++) acc[i][j]=0.f;

    for (int t0=0; t0<512; t0+=32) {
        __syncthreads();
        #pragma unroll
        for (int i=0;i<4;i++) {
            int idx = i*256 + threadIdx.x;
            int r = idx >> 5, c4 = idx & 31;
            int t = ks*512 + t0 + r;
            size_t off = (size_t)(b*SEQ+t)*DM + hh*DH + c4*4;
            float4 kv = *reinterpret_cast<const float4*>(g_k + off);
            float4 vv = *reinterpret_cast<const float4*>(g_v + off);
            int d0 = c4*4;
            kt[r][d0+0] = expf(kv.x - smax[d0+0])*sinv[d0+0];
            kt[r][d0+1] = expf(kv.y - smax[d0+1])*sinv[d0+1];
            kt[r][d0+2] = expf(kv.z - smax[d0+2])*sinv[d0+2];
            kt[r][d0+3] = expf(kv.w - smax[d0+3])*sinv[d0+3];
            *reinterpret_cast<float4*>(&vt[r][d0]) = vv;
        }
        __syncthreads();
        #pragma unroll
        for (int kk=0; kk<32; kk++) {
            float a[8], bb[8];
            *reinterpret_cast<float4*>(&a[0])  = *reinterpret_cast<const float4*>(&kt[kk][ty*8]);
            *reinterpret_cast<float4*>(&a[4])  = *reinterpret_cast<const float4*>(&kt[kk][ty*8+4]);
            *reinterpret_cast<float4*>(&bb[0]) = *reinterpret_cast<const float4*>(&vt[kk][tx*8]);
            *reinterpret_cast<float4*>(&bb[4]) = *reinterpret_cast<const float4*>(&vt[kk][tx*8+4]);
            #pragma unroll
            for (int i=0;i<8;i++)
                #pragma unroll
                for (int j=0;j<8;j++)
                    acc[i][j] = fmaf(a[i], bb[j], acc[i][j]);
        }
    }
    float* op = g_ctxp + ((size_t)bh*8 + ks)*DH*DH;
    #pragma unroll
    for (int i=0;i<8;i++)
        #pragma unroll
        for (int j=0;j<8;j+=4) {
            float4 o4 = make_float4(acc[i][j],acc[i][j+1],acc[i][j+2],acc[i][j+3]);
            *reinterpret_cast<float4*>(op + (size_t)(ty*8+i)*DH + tx*8 + j) = o4;
        }
}

__global__ void ctx_reduce_kernel() {
    int idx = blockIdx.x*256 + threadIdx.x;
    if (idx >= BSZ*3*DH*DH) return;
    int bh = idx / (DH*DH);
    int de = idx - bh*DH*DH;
    float s = 0.f;
    #pragma unroll
    for (int ks=0;ks<8;ks++) s += g_ctxp[((size_t)bh*8+ks)*DH*DH + de];
    g_ctx[idx] = s;
}

// ---------------- linear-attn output: out = softmax(q)*scale @ ctx ----------
// grid (24, 128); block 256 = 8 warps; each warp does 4 tokens.
__global__ __launch_bounds__(256) void lin_out_kernel() {
    __shared__ float sctx[64][DH];   // 32 KB, two phases over d
    int bh = blockIdx.x;
    int b = bh/3, hh = bh%3 + 1;
    int warp = threadIdx.x >> 5, lane = threadIdx.x & 31;
    const float* ctxp = g_ctx + (size_t)bh*DH*DH;
    float pr[4][4], o[4][4];
    int tbase = blockIdx.y*32 + warp*4;
    #pragma unroll
    for (int tt=0;tt<4;tt++) {
        int t = tbase + tt;
        const float* qp = g_q + (size_t)(b*SEQ+t)*DM + hh*DH;
        float4 q4 = *reinterpret_cast<const float4*>(qp + lane*4);
        float mx = fmaxf(fmaxf(q4.x,q4.y),fmaxf(q4.z,q4.w));
        #pragma unroll
        for (int s=16;s;s>>=1) mx = fmaxf(mx, __shfl_xor_sync(~0u,mx,s));
        float e0=expf(q4.x-mx), e1=expf(q4.y-mx), e2=expf(q4.z-mx), e3=expf(q4.w-mx);
        float sm = e0+e1+e2+e3;
        #pragma unroll
        for (int s=16;s;s>>=1) sm += __shfl_xor_sync(~0u,sm,s);
        float inv = SCALE/sm;
        pr[tt][0]=e0*inv; pr[tt][1]=e1*inv; pr[tt][2]=e2*inv; pr[tt][3]=e3*inv;
        o[tt][0]=0.f; o[tt][1]=0.f; o[tt][2]=0.f; o[tt][3]=0.f;
    }
    for (int ph=0; ph<2; ph++) {
        __syncthreads();
        #pragma unroll
        for (int i=0;i<8;i++) {
            int idx = i*256 + threadIdx.x;
            int r = idx >> 5, c4 = idx & 31;
            *reinterpret_cast<float4*>(&sctx[r][c4*4]) =
                *reinterpret_cast<const float4*>(ctxp + (size_t)(ph*64+r)*DH + c4*4);
        }
        __syncthreads();
        #pragma unroll
        for (int dl=0; dl<16; dl++) {
            int src = ph*16 + dl;
            #pragma unroll
            for (int tt=0;tt<4;tt++) {
                float b0 = __shfl_sync(~0u, pr[tt][0], src);
                float b1 = __shfl_sync(~0u, pr[tt][1], src);
                float b2 = __shfl_sync(~0u, pr[tt][2], src);
                float b3 = __shfl_sync(~0u, pr[tt][3], src);
                float4 c0 = *reinterpret_cast<const float4*>(&sctx[dl*4+0][lane*4]);
                float4 c1 = *reinterpret_cast<const float4*>(&sctx[dl*4+1][lane*4]);
                float4 c2 = *reinterpret_cast<const float4*>(&sctx[dl*4+2][lane*4]);
                float4 c3 = *reinterpret_cast<const float4*>(&sctx[dl*4+3][lane*4]);
                o[tt][0] += b0*c0.x + b1*c1.x + b2*c2.x + b3*c3.x;
                o[tt][1] += b0*c0.y + b1*c1.y + b2*c2.y + b3*c3.y;
                o[tt][2] += b0*c0.z + b1*c1.z + b2*c2.z + b3*c3.z;
                o[tt][3] += b0*c0.w + b1*c1.w + b2*c2.w + b3*c3.w;
            }
        }
    }
    #pragma unroll
    for (int tt=0;tt<4;tt++) {
        int t = tbase + tt;
        float4 o4 = make_float4(o[tt][0],o[tt][1],o[tt][2],o[tt][3]);
        *reinterpret_cast<float4*>(g_attn + (size_t)(b*SEQ+t)*DM + hh*DH + lane*4) = o4;
    }
}

// ---------------- final slice (drop padded rows) -----------------------------
__global__ void slice_kernel(float* __restrict__ out) {
    int idx = blockIdx.x*256 + threadIdx.x;
    const int total = BSZ*NTOK*(DOUT/4);
    if (idx >= total) return;
    int row = idx >> 4;     // 16 float4 per row
    int c4  = idx & 15;
    int b = row / NTOK, t = row - b*NTOK;
    reinterpret_cast<float4*>(out)[idx] =
        reinterpret_cast<const float4*>(g_of)[(size_t)(b*SEQ+t)*16 + c4];
}

// ---------------- host ---------------------------------------------------
static inline void sgemm(const float* A, const float* B, const float* bias,
                         const float* res, float* C, int M, int N, int K, int act) {
    dim3 grid((N+127)/128, M/128);
    sgemm_kernel<<<grid,256>>>(A,B,bias,res,C,M,N,K,act);
}

extern "C" void kernel_launch(void* const* d_in, const int* in_sizes, int n_in,
                              void* d_out, int out_size) {
    const float* x    = (const float*)d_in[0];
    const float* W1   = (const float*)d_in[1];
    const float* b1   = (const float*)d_in[2];
    const float* ln1g = (const float*)d_in[3];
    const float* ln1b = (const float*)d_in[4];
    const float* Wq   = (const float*)d_in[5];
    const float* Wk   = (const float*)d_in[6];
    const float* Wv   = (const float*)d_in[7];
    const float* Wo   = (const float*)d_in[8];
    const float* bo   = (const float*)d_in[9];
    const float* ln2g = (const float*)d_in[10];
    const float* ln2b = (const float*)d_in[11];
    const float* Wf1  = (const float*)d_in[12];
    const float* bf1  = (const float*)d_in[13];
    const float* Wf2  = (const float*)d_in[14];
    const float* bf2  = (const float*)d_in[15];
    const float* W2   = (const float*)d_in[16];
    const float* b2   = (const float*)d_in[17];
    float* out = (float*)d_out;

    float *xp,*h,*ln,*q,*k,*v,*attn,*ff,*of;
    cudaGetSymbolAddress((void**)&xp,   g_xp);
    cudaGetSymbolAddress((void**)&h,    g_h);
    cudaGetSymbolAddress((void**)&ln,   g_ln);
    cudaGetSymbolAddress((void**)&q,    g_q);
    cudaGetSymbolAddress((void**)&k,    g_k);
    cudaGetSymbolAddress((void**)&v,    g_v);
    cudaGetSymbolAddress((void**)&attn, g_attn);
    cudaGetSymbolAddress((void**)&ff,   g_ff);
    cudaGetSymbolAddress((void**)&of,   g_of);

    // 1. pad
    pad_x_kernel<<<(MTOT*DIN/4 + 255)/256, 256>>>(x);
    // 2. h = tanh(xp @ W1 + b1)
    sgemm(xp, W1, b1, nullptr, h, MTOT, DM, DIN, 1);
    // 3. ln1
    ln_kernel<<<MTOT/8, 256>>>(h, ln1g, ln1b, ln);
    // 4. q,k,v
    sgemm(ln, Wq, nullptr, nullptr, q, MTOT, DM, DM, 0);
    sgemm(ln, Wk, nullptr, nullptr, k, MTOT, DM, DM, 0);
    sgemm(ln, Wv, nullptr, nullptr, v, MTOT, DM, DM, 0);
    // 5. local attention (head 0)
    local_attn_kernel<<<BSZ*32*4, 1024>>>();
    // 6. linear attention (heads 1..3)
    kstats_kernel<<<dim3(BSZ*3,4), dim3(32,8)>>>();
    ctx_partial_kernel<<<dim3(BSZ*3,8), 256>>>();
    ctx_reduce_kernel<<<(BSZ*3*DH*DH + 255)/256, 256>>>();
    lin_out_kernel<<<dim3(BSZ*3, SEQ/32), 256>>>();
    // 7. h = h + attn @ Wo + bo
    sgemm(attn, Wo, bo, h, h, MTOT, DM, DM, 0);
    // 8. ln2
    ln_kernel<<<MTOT/8, 256>>>(h, ln2g, ln2b, ln);
    // 9. ff = gelu(ln @ Wf1 + bf1)
    sgemm(ln, Wf1, bf1, nullptr, ff, MTOT, DFF, DM, 2);
    // 10. h = h + ff @ Wf2 + bf2
    sgemm(ff, Wf2, bf2, h, h, MTOT, DM, DFF, 0);
    // 11. of = h @ W2 + b2
    sgemm(h, W2, b2, nullptr, of, MTOT, DOUT, DM, 0);
    // 12. slice out first 3000 tokens
    slice_kernel<<<(BSZ*NTOK*(DOUT/4) + 255)/256, 256>>>(out);
}

// round 4
// speedup vs baseline: 2.0749x; 2.0749x over previous
#include <cuda_runtime.h>
#include <cuda_bf16.h>
#include <math.h>
#include <stdint.h>

#define BSZ   8
#define SEQ   4096
#define NTOK  3000
#define DIN   128
#define DM    512
#define DFF   2048
#define DOUT  64
#define DH    128
#define MTOT  (BSZ*SEQ)              // 32768 rows
#define SCALE 0.08838834764831845f   // 1/sqrt(128)
#define GEMM_SMEM 81920              // 2 stages x 4 arrays x 128 x 80B

typedef __nv_bfloat16 bf16;

// ---------------- scratch (static device globals: no allocation) -------------
__device__ float g_h[MTOT*DM];
__device__ float g_q[MTOT*DM];
__device__ float g_k[MTOT*DM];
__device__ float g_v[MTOT*DM];
__device__ float g_attn[MTOT*DM];
__device__ float g_of[MTOT*DOUT];
__device__ float g_kmax[BSZ*3*DH];
__device__ float g_klse[BSZ*3*DH];
__device__ float g_ctxp[BSZ*3*8*DH*DH];
__device__ float g_ctx[BSZ*3*DH*DH];
// bf16 split activation buffers (reused across stages)
__device__ bf16 g_sh[MTOT*DM];
__device__ bf16 g_sl[MTOT*DM];
__device__ bf16 g_s2h[MTOT*DFF];
__device__ bf16 g_s2l[MTOT*DFF];
// transposed + split weights [N][K] bf16 hi/lo
__device__ bf16 g_w1h[DM*DIN],  g_w1l[DM*DIN];
__device__ bf16 g_wqh[DM*DM],   g_wql[DM*DM];
__device__ bf16 g_wkh[DM*DM],   g_wkl[DM*DM];
__device__ bf16 g_wvh[DM*DM],   g_wvl[DM*DM];
__device__ bf16 g_woh[DM*DM],   g_wol[DM*DM];
__device__ bf16 g_wf1h[DFF*DM], g_wf1l[DFF*DM];
__device__ bf16 g_wf2h[DM*DFF], g_wf2l[DM*DFF];
__device__ bf16 g_w2h[DOUT*DM], g_w2l[DOUT*DM];

// ---------------- helpers ----------------
__device__ __forceinline__ uint32_t smem_u32(const void* p) {
    uint32_t a;
    asm("{ .reg .u64 t; cvta.to.shared.u64 t, %1; cvt.u32.u64 %0, t; }" : "=r"(a) : "l"(p));
    return a;
}
__device__ __forceinline__ void split2(float x, float y, uint32_t& hi, uint32_t& lo) {
    __nv_bfloat162 h = __floats2bfloat162_rn(x, y);
    __nv_bfloat162 l = __floats2bfloat162_rn(x - __low2float(h), y - __high2float(h));
    hi = *reinterpret_cast<uint32_t*>(&h);
    lo = *reinterpret_cast<uint32_t*>(&l);
}

#define LDSM_X4(r0,r1,r2,r3,addr) \
    asm volatile("ldmatrix.sync.aligned.m8n8.x4.shared.b16 {%0,%1,%2,%3}, [%4];" \
        : "=r"(r0),"=r"(r1),"=r"(r2),"=r"(r3) : "r"(addr))
#define LDSM_X2(r0,r1,addr) \
    asm volatile("ldmatrix.sync.aligned.m8n8.x2.shared.b16 {%0,%1}, [%2];" \
        : "=r"(r0),"=r"(r1) : "r"(addr))
#define MMA16816(d, a0,a1,a2,a3, b0,b1) \
    asm volatile("mma.sync.aligned.m16n8k16.row.col.f32.bf16.bf16.f32 " \
        "{%0,%1,%2,%3},{%4,%5,%6,%7},{%8,%9},{%0,%1,%2,%3};" \
        : "+f"((d)[0]),"+f"((d)[1]),"+f"((d)[2]),"+f"((d)[3]) \
        : "r"(a0),"r"(a1),"r"(a2),"r"(a3),"r"(b0),"r"(b1))
#define CP_ASYNC16(dst, src, sz) \
    asm volatile("cp.async.cg.shared.global [%0], [%1], 16, %2;" :: "r"(dst), "l"(src), "r"(sz))
#define CP_COMMIT()  asm volatile("cp.async.commit_group;" ::: "memory")
#define CP_WAIT0()   asm volatile("cp.async.wait_group 0;" ::: "memory")
#define CP_WAIT1()   asm volatile("cp.async.wait_group 1;" ::: "memory")

// ---------------- weight transpose + bf16 split: T[n][k] = split(W[k][n]) ----
__global__ void transpose_split_kernel(const float* __restrict__ W,
                                       bf16* __restrict__ Th, bf16* __restrict__ Tl,
                                       int K, int N) {
    __shared__ float t[32][33];
    int bx = blockIdx.x * 32, by = blockIdx.y * 32;
    int x = bx + threadIdx.x;
    #pragma unroll
    for (int i = 0; i < 32; i += 8) {
        int y = by + threadIdx.y + i;
        if (x < N && y < K) t[threadIdx.y + i][threadIdx.x] = W[(size_t)y * N + x];
    }
    __syncthreads();
    int xk = by + threadIdx.x;
    #pragma unroll
    for (int i = 0; i < 32; i += 8) {
        int yn = bx + threadIdx.y + i;
        if (xk < K && yn < N) {
            float v = t[threadIdx.x][threadIdx.y + i];
            bf16 h = __float2bfloat16_rn(v);
            Th[(size_t)yn * K + xk] = h;
            Tl[(size_t)yn * K + xk] = __float2bfloat16_rn(v - __bfloat162float(h));
        }
    }
}

// ---------------- pad + split x -> g_sh/g_sl [MTOT][128] bf16 ----------------
__global__ void pad_split_kernel(const float* __restrict__ x) {
    int idx = blockIdx.x*256 + threadIdx.x;
    const int total = MTOT*DIN/4;
    if (idx >= total) return;
    int row = idx >> 5;
    int c4  = idx & 31;
    int b = row / SEQ, t = row - b*SEQ;
    float4 val = make_float4(0.f,0.f,0.f,0.f);
    if (t < NTOK)
        val = reinterpret_cast<const float4*>(x)[(size_t)(b*NTOK + t)*32 + c4];
    uint2 hv, lv;
    split2(val.x, val.y, hv.x, lv.x);
    split2(val.z, val.w, hv.y, lv.y);
    *reinterpret_cast<uint2*>(g_sh + (size_t)idx*4) = hv;
    *reinterpret_cast<uint2*>(g_sl + (size_t)idx*4) = lv;
}

// ---------------- split f32 [MTOT][DM] -> hi/lo bf16 -------------------------
__global__ void split_kernel(const float* __restrict__ in) {
    int idx = blockIdx.x*256 + threadIdx.x;
    const int total = MTOT*DM/4;
    if (idx >= total) return;
    float4 v = reinterpret_cast<const float4*>(in)[idx];
    uint2 hv, lv;
    split2(v.x, v.y, hv.x, lv.x);
    split2(v.z, v.w, hv.y, lv.y);
    *reinterpret_cast<uint2*>(g_sh + (size_t)idx*4) = hv;
    *reinterpret_cast<uint2*>(g_sl + (size_t)idx*4) = lv;
}

// ---------------- bf16-split tensor-core GEMM --------------------------------
// C[M,N] = act(Ah+Al @ (Bh+Bl)^T + bias) + res, A[M,K] hi/lo, B[N,K] hi/lo.
// CTA 128x128, K-chunk 32, cp.async double buffer, mma.sync m16n8k16 bf16,
// 3-term split product. Output: f32 C, or bf16 hi/lo split (Chi/Clo).
__global__ __launch_bounds__(256) void tc_gemm_kernel(
    const bf16* __restrict__ Ah, const bf16* __restrict__ Al,
    const bf16* __restrict__ Bh, const bf16* __restrict__ Bl,
    const float* __restrict__ bias, const float* __restrict__ res,
    float* __restrict__ C, bf16* __restrict__ Chi, bf16* __restrict__ Clo,
    int M, int N, int K, int act)
{
    extern __shared__ __align__(16) char smc[];
    uint32_t sbase = smem_u32(smc);
    int tid = threadIdx.x;
    int bm = blockIdx.y << 7, bn = blockIdx.x << 7;
    int lane = tid & 31, w = tid >> 5;
    int wm = w & 1, wn = w >> 1;        // warp grid 2(m) x 4(n), warp tile 64x32
    int grp = lane >> 2, qp = lane & 3;

    uint32_t a_off = (uint32_t)(wm*64 + (lane & 15))*80 + ((lane >> 4) << 4);
    uint32_t b_off = (uint32_t)(wn*32 + (lane & 7))*80 + (((lane >> 3) & 1) << 4);

    float acc[4][4][4];
    #pragma unroll
    for (int i=0;i<4;i++)
        #pragma unroll
        for (int j=0;j<4;j++)
            #pragma unroll
            for (int r=0;r<4;r++) acc[i][j][r] = 0.f;

    const int NC = K >> 5;

    // stage loader: 4 arrays x 128 rows x 2 x 16B chunks, 8 cp.async per thread
    #define STAGE_LOAD(c_, buf_) do { \
        int k0 = (c_) << 5; \
        uint32_t sb = sbase + (buf_)*40960; \
        _Pragma("unroll") \
        for (int i_ = 0; i_ < 8; i_++) { \
            int idx_ = i_*256 + tid; \
            int arr_ = idx_ >> 9; \
            int j_ = idx_ & 511; \
            int r_ = j_ >> 2, cc_ = j_ & 3; \
            uint32_t daddr_ = sb + arr_*10240 + r_*80 + cc_*16; \
            const bf16* g_; int sz_ = 16; \
            if (arr_ == 0)      g_ = Ah + (size_t)(bm + r_)*K + k0 + cc_*8; \
            else if (arr_ == 1) g_ = Al + (size_t)(bm + r_)*K + k0 + cc_*8; \
            else { \
                int rowv_ = bn + r_; \
                const bf16* base_ = (arr_ == 2) ? Bh : Bl; \
                if (rowv_ < N) g_ = base_ + (size_t)rowv_*K + k0 + cc_*8; \
                else { g_ = base_; sz_ = 0; } \
            } \
            CP_ASYNC16(daddr_, g_, sz_); \
        } \
        CP_COMMIT(); \
    } while (0)

    STAGE_LOAD(0, 0);

    for (int c = 0; c < NC; c++) {
        if (c + 1 < NC) {
            STAGE_LOAD(c + 1, (c + 1) & 1);
            CP_WAIT1();
        } else {
            CP_WAIT0();
        }
        __syncthreads();

        uint32_t sA  = sbase + (c & 1)*40960;
        uint32_t sAl = sA + 10240, sB = sA + 20480, sBl = sA + 30720;

        #pragma unroll
        for (int ks = 0; ks < 2; ks++) {
            uint32_t ko = ks << 5;
            uint32_t bh[4][2], bl[4][2];
            #pragma unroll
            for (int nt = 0; nt < 4; nt++) {
                LDSM_X2(bh[nt][0], bh[nt][1], sB  + b_off + nt*640 + ko);
                LDSM_X2(bl[nt][0], bl[nt][1], sBl + b_off + nt*640 + ko);
            }
            uint32_t a[4][4];
            #pragma unroll
            for (int mt = 0; mt < 4; mt++)
                LDSM_X4(a[mt][0], a[mt][1], a[mt][2], a[mt][3], sA + a_off + mt*1280 + ko);
            #pragma unroll
            for (int mt = 0; mt < 4; mt++)
                #pragma unroll
                for (int nt = 0; nt < 4; nt++) {
                    MMA16816(acc[mt][nt], a[mt][0],a[mt][1],a[mt][2],a[mt][3], bh[nt][0],bh[nt][1]);
                    MMA16816(acc[mt][nt], a[mt][0],a[mt][1],a[mt][2],a[mt][3], bl[nt][0],bl[nt][1]);
                }
            #pragma unroll
            for (int mt = 0; mt < 4; mt++)
                LDSM_X4(a[mt][0], a[mt][1], a[mt][2], a[mt][3], sAl + a_off + mt*1280 + ko);
            #pragma unroll
            for (int mt = 0; mt < 4; mt++)
                #pragma unroll
                for (int nt = 0; nt < 4; nt++)
                    MMA16816(acc[mt][nt], a[mt][0],a[mt][1],a[mt][2],a[mt][3], bh[nt][0],bh[nt][1]);
        }
        __syncthreads();
    }
    #undef STAGE_LOAD

    // ---- epilogue ----
    #pragma unroll
    for (int mt = 0; mt < 4; mt++) {
        #pragma unroll
        for (int nt = 0; nt < 4; nt++) {
            int c0 = bn + wn*32 + nt*8 + qp*2;
            if (c0 >= N) continue;
            int rbase = bm + wm*64 + mt*16 + grp;
            float bs0 = 0.f, bs1 = 0.f;
            if (bias) { bs0 = bias[c0]; bs1 = bias[c0 + 1]; }
            #pragma unroll
            for (int half = 0; half < 2; half++) {
                int r = rbase + half*8;
                float v0 = acc[mt][nt][half*2 + 0] + bs0;
                float v1 = acc[mt][nt][half*2 + 1] + bs1;
                if (act == 1) { v0 = tanhf(v0); v1 = tanhf(v1); }
                else if (act == 2) {
                    v0 = 0.5f*v0*(1.f + erff(v0*0.7071067811865476f));
                    v1 = 0.5f*v1*(1.f + erff(v1*0.7071067811865476f));
                }
                if (res) {
                    v0 += res[(size_t)r*N + c0];
                    v1 += res[(size_t)r*N + c0 + 1];
                }
                if (Chi) {
                    uint32_t hv, lv;
                    split2(v0, v1, hv, lv);
                    *reinterpret_cast<uint32_t*>(Chi + (size_t)r*N + c0) = hv;
                    *reinterpret_cast<uint32_t*>(Clo + (size_t)r*N + c0) = lv;
                } else {
                    float2 o; o.x = v0; o.y = v1;
                    *reinterpret_cast<float2*>(C + (size_t)r*N + c0) = o;
                }
            }
        }
    }
}

// ---------------- LayerNorm (row=512) -> bf16 hi/lo split --------------------
__global__ void ln_kernel(const float* __restrict__ in, const float* __restrict__ gam,
                          const float* __restrict__ bet) {
    int gw = (blockIdx.x*blockDim.x + threadIdx.x) >> 5;
    int lane = threadIdx.x & 31;
    if (gw >= MTOT) return;
    const float4* rp = reinterpret_cast<const float4*>(in + (size_t)gw*DM);
    float4 v[4];
    float s=0.f, s2=0.f;
    #pragma unroll
    for (int i=0;i<4;i++) {
        v[i] = rp[lane + 32*i];
        s  += v[i].x+v[i].y+v[i].z+v[i].w;
        s2 += v[i].x*v[i].x + v[i].y*v[i].y + v[i].z*v[i].z + v[i].w*v[i].w;
    }
    #pragma unroll
    for (int o=16;o;o>>=1) { s += __shfl_xor_sync(~0u,s,o); s2 += __shfl_xor_sync(~0u,s2,o); }
    float mu  = s*(1.f/512.f);
    float var = s2*(1.f/512.f) - mu*mu;
    float r = rsqrtf(var + 1e-5f);
    #pragma unroll
    for (int i=0;i<4;i++) {
        int c = (lane + 32*i)*4;
        float4 g4 = *reinterpret_cast<const float4*>(gam + c);
        float4 b4 = *reinterpret_cast<const float4*>(bet + c);
        float o0 = (v[i].x-mu)*r*g4.x + b4.x;
        float o1 = (v[i].y-mu)*r*g4.y + b4.y;
        float o2 = (v[i].z-mu)*r*g4.z + b4.z;
        float o3 = (v[i].w-mu)*r*g4.w + b4.w;
        uint2 hv, lv;
        split2(o0, o1, hv.x, lv.x);
        split2(o2, o3, hv.y, lv.y);
        size_t off = (size_t)gw*DM + c;
        *reinterpret_cast<uint2*>(g_sh + off) = hv;
        *reinterpret_cast<uint2*>(g_sl + off) = lv;
    }
}

// ---------------- local attention, head 0, window 128 with look-around ------
__global__ __launch_bounds__(1024) void local_attn_kernel() {
    __shared__ float tile[64][DH];
    __shared__ float scores[32][64];
    int bx = blockIdx.x;
    int b   = bx >> 7;
    int win = (bx >> 2) & 31;
    int qc  = bx & 3;
    int warp = threadIdx.x >> 5, lane = threadIdx.x & 31;
    int qt = win*128 + qc*32 + warp;
    size_t qoff = (size_t)(b*SEQ + qt)*DM;
    float4 q4 = *reinterpret_cast<const float4*>(g_q + qoff + lane*4);
    float m = -1e30f, l = 0.f;
    float4 acc = make_float4(0.f,0.f,0.f,0.f);
    int kbase = win*128 - 128;
    for (int ch=0; ch<6; ch++) {
        int t0 = kbase + ch*64;
        __syncthreads();
        #pragma unroll
        for (int it=0; it<2; it++) {
            int idx = it*1024 + threadIdx.x;
            int r = idx >> 5, c4 = idx & 31;
            int t = t0 + r;
            float4 kv = make_float4(0.f,0.f,0.f,0.f);
            if (t >= 0 && t < SEQ)
                kv = *reinterpret_cast<const float4*>(g_k + (size_t)(b*SEQ+t)*DM + c4*4);
            *reinterpret_cast<float4*>(&tile[r][c4*4]) = kv;
        }
        __syncthreads();
        for (int j=0; j<64; j++) {
            float4 kv = *reinterpret_cast<const float4*>(&tile[j][lane*4]);
            float s = q4.x*kv.x + q4.y*kv.y + q4.z*kv.z + q4.w*kv.w;
            #pragma unroll
            for (int o=16;o;o>>=1) s += __shfl_xor_sync(~0u,s,o);
            if (lane == (j & 31)) {
                int t = t0 + j;
                scores[warp][j] = (t >= 0 && t < SEQ) ? s*SCALE : -1e38f;
            }
        }
        __syncthreads();
        #pragma unroll
        for (int it=0; it<2; it++) {
            int idx = it*1024 + threadIdx.x;
            int r = idx >> 5, c4 = idx & 31;
            int t = t0 + r;
            float4 vv = make_float4(0.f,0.f,0.f,0.f);
            if (t >= 0 && t < SEQ)
                vv = *reinterpret_cast<const float4*>(g_v + (size_t)(b*SEQ+t)*DM + c4*4);
            *reinterpret_cast<float4*>(&tile[r][c4*4]) = vv;
        }
        __syncthreads();
        float cm = fmaxf(scores[warp][lane], scores[warp][lane+32]);
        #pragma unroll
        for (int o=16;o;o>>=1) cm = fmaxf(cm, __shfl_xor_sync(~0u,cm,o));
        float mn = fmaxf(m, cm);
        float corr = expf(m - mn);
        l *= corr; acc.x*=corr; acc.y*=corr; acc.z*=corr; acc.w*=corr;
        for (int j=0; j<64; j++) {
            float p = expf(scores[warp][j] - mn);
            l += p;
            float4 vv = *reinterpret_cast<const float4*>(&tile[j][lane*4]);
            acc.x = fmaf(p, vv.x, acc.x);
            acc.y = fmaf(p, vv.y, acc.y);
            acc.z = fmaf(p, vv.z, acc.z);
            acc.w = fmaf(p, vv.w, acc.w);
        }
        m = mn;
    }
    float inv = 1.f/l;
    float4 o4 = make_float4(acc.x*inv, acc.y*inv, acc.z*inv, acc.w*inv);
    *reinterpret_cast<float4*>(g_attn + qoff + lane*4) = o4;
}

// ---------------- k column softmax stats (heads 1..3) -----------------------
__global__ void kstats_kernel() {
    int bh = blockIdx.x;
    int b = bh/3, hh = bh%3 + 1;
    int d = blockIdx.y*32 + threadIdx.x;
    int ty = threadIdx.y;
    int col = hh*DH + d;
    float m = -1e30f, l = 0.f;
    for (int t = ty; t < SEQ; t += 8) {
        float val = g_k[(size_t)(b*SEQ+t)*DM + col];
        if (val > m) { l = l*expf(m - val) + 1.f; m = val; }
        else l += expf(val - m);
    }
    __shared__ float sm[8][32], sl[8][32];
    sm[ty][threadIdx.x] = m; sl[ty][threadIdx.x] = l;
    __syncthreads();
    if (ty == 0) {
        #pragma unroll
        for (int r=1;r<8;r++) {
            float m2 = sm[r][threadIdx.x], l2 = sl[r][threadIdx.x];
            float M = fmaxf(m, m2);
            l = l*expf(m - M) + l2*expf(m2 - M);
            m = M;
        }
        g_kmax[bh*DH + d] = m;
        g_klse[bh*DH + d] = l;
    }
}

// ---------------- ctx partial: ctx[d][e] = sum_t k'[t,d] v[t,e] (K-split 8) --
__global__ __launch_bounds__(256) void ctx_partial_kernel() {
    __shared__ float kt[32][132];
    __shared__ float vt[32][132];
    __shared__ float smax[DH], sinv[DH];
    int bh = blockIdx.x, ks = blockIdx.y;
    int b = bh/3, hh = bh%3 + 1;
    if (threadIdx.x < DH) {
        smax[threadIdx.x] = g_kmax[bh*DH + threadIdx.x];
        sinv[threadIdx.x] = 1.f/g_klse[bh*DH + threadIdx.x];
    }
    int tx = threadIdx.x & 15, ty = threadIdx.x >> 4;
    float acc[8][8];
    #pragma unroll
    for (int i=0;i<8;i++)
        #pragma unroll
        for (int j=0;j<8;j++) acc[i][j]=0.f;

    for (int t0=0; t0<512; t0+=32) {
        __syncthreads();
        #pragma unroll
        for (int i=0;i<4;i++) {
            int idx = i*256 + threadIdx.x;
            int r = idx >> 5, c4 = idx & 31;
            int t = ks*512 + t0 + r;
            size_t off = (size_t)(b*SEQ+t)*DM + hh*DH + c4*4;
            float4 kv = *reinterpret_cast<const float4*>(g_k + off);
            float4 vv = *reinterpret_cast<const float4*>(g_v + off);
            int d0 = c4*4;
            kt[r][d0+0] = expf(kv.x - smax[d0+0])*sinv[d0+0];
            kt[r][d0+1] = expf(kv.y - smax[d0+1])*sinv[d0+1];
            kt[r][d0+2] = expf(kv.z - smax[d0+2])*sinv[d0+2];
            kt[r][d0+3] = expf(kv.w - smax[d0+3])*sinv[d0+3];
            *reinterpret_cast<float4*>(&vt[r][d0]) = vv;
        }
        __syncthreads();
        #pragma unroll
        for (int kk=0; kk<32; kk++) {
            float a[8], bb[8];
            *reinterpret_cast<float4*>(&a[0])  = *reinterpret_cast<const float4*>(&kt[kk][ty*8]);
            *reinterpret_cast<float4*>(&a[4])  = *reinterpret_cast<const float4*>(&kt[kk][ty*8+4]);
            *reinterpret_cast<float4*>(&bb[0]) = *reinterpret_cast<const float4*>(&vt[kk][tx*8]);
            *reinterpret_cast<float4*>(&bb[4]) = *reinterpret_cast<const float4*>(&vt[kk][tx*8+4]);
            #pragma unroll
            for (int i=0;i<8;i++)
                #pragma unroll
                for (int j=0;j<8;j++)
                    acc[i][j] = fmaf(a[i], bb[j], acc[i][j]);
        }
    }
    float* op = g_ctxp + ((size_t)bh*8 + ks)*DH*DH;
    #pragma unroll
    for (int i=0;i<8;i++)
        #pragma unroll
        for (int j=0;j<8;j+=4) {
            float4 o4 = make_float4(acc[i][j],acc[i][j+1],acc[i][j+2],acc[i][j+3]);
            *reinterpret_cast<float4*>(op + (size_t)(ty*8+i)*DH + tx*8 + j) = o4;
        }
}

__global__ void ctx_reduce_kernel() {
    int idx = blockIdx.x*256 + threadIdx.x;
    if (idx >= BSZ*3*DH*DH) return;
    int bh = idx / (DH*DH);
    int de = idx - bh*DH*DH;
    float s = 0.f;
    #pragma unroll
    for (int ks=0;ks<8;ks++) s += g_ctxp[((size_t)bh*8+ks)*DH*DH + de];
    g_ctx[idx] = s;
}

// ---------------- linear-attn output: out = softmax(q)*scale @ ctx ----------
__global__ __launch_bounds__(256) void lin_out_kernel() {
    __shared__ float sctx[64][DH];
    int bh = blockIdx.x;
    int b = bh/3, hh = bh%3 + 1;
    int warp = threadIdx.x >> 5, lane = threadIdx.x & 31;
    const float* ctxp = g_ctx + (size_t)bh*DH*DH;
    float pr[4][4], o[4][4];
    int tbase = blockIdx.y*32 + warp*4;
    #pragma unroll
    for (int tt=0;tt<4;tt++) {
        int t = tbase + tt;
        const float* qp = g_q + (size_t)(b*SEQ+t)*DM + hh*DH;
        float4 q4 = *reinterpret_cast<const float4*>(qp + lane*4);
        float mx = fmaxf(fmaxf(q4.x,q4.y),fmaxf(q4.z,q4.w));
        #pragma unroll
        for (int s=16;s;s>>=1) mx = fmaxf(mx, __shfl_xor_sync(~0u,mx,s));
        float e0=expf(q4.x-mx), e1=expf(q4.y-mx), e2=expf(q4.z-mx), e3=expf(q4.w-mx);
        float sm = e0+e1+e2+e3;
        #pragma unroll
        for (int s=16;s;s>>=1) sm += __shfl_xor_sync(~0u,sm,s);
        float inv = SCALE/sm;
        pr[tt][0]=e0*inv; pr[tt][1]=e1*inv; pr[tt][2]=e2*inv; pr[tt][3]=e3*inv;
        o[tt][0]=0.f; o[tt][1]=0.f; o[tt][2]=0.f; o[tt][3]=0.f;
    }
    for (int ph=0; ph<2; ph++) {
        __syncthreads();
        #pragma unroll
        for (int i=0;i<8;i++) {
            int idx = i*256 + threadIdx.x;
            int r = idx >> 5, c4 = idx & 31;
            *reinterpret_cast<float4*>(&sctx[r][c4*4]) =
                *reinterpret_cast<const float4*>(ctxp + (size_t)(ph*64+r)*DH + c4*4);
        }
        __syncthreads();
        #pragma unroll
        for (int dl=0; dl<16; dl++) {
            int src = ph*16 + dl;
            #pragma unroll
            for (int tt=0;tt<4;tt++) {
                float b0 = __shfl_sync(~0u, pr[tt][0], src);
                float b1 = __shfl_sync(~0u, pr[tt][1], src);
                float b2 = __shfl_sync(~0u, pr[tt][2], src);
                float b3 = __shfl_sync(~0u, pr[tt][3], src);
                float4 c0 = *reinterpret_cast<const float4*>(&sctx[dl*4+0][lane*4]);
                float4 c1 = *reinterpret_cast<const float4*>(&sctx[dl*4+1][lane*4]);
                float4 c2 = *reinterpret_cast<const float4*>(&sctx[dl*4+2][lane*4]);
                float4 c3 = *reinterpret_cast<const float4*>(&sctx[dl*4+3][lane*4]);
                o[tt][0] += b0*c0.x + b1*c1.x + b2*c2.x + b3*c3.x;
                o[tt][1] += b0*c0.y + b1*c1.y + b2*c2.y + b3*c3.y;
                o[tt][2] += b0*c0.z + b1*c1.z + b2*c2.z + b3*c3.z;
                o[tt][3] += b0*c0.w + b1*c1.w + b2*c2.w + b3*c3.w;
            }
        }
    }
    #pragma unroll
    for (int tt=0;tt<4;tt++) {
        int t = tbase + tt;
        float4 o4 = make_float4(o[tt][0],o[tt][1],o[tt][2],o[tt][3]);
        *reinterpret_cast<float4*>(g_attn + (size_t)(b*SEQ+t)*DM + hh*DH + lane*4) = o4;
    }
}

// ---------------- final slice (drop padded rows) -----------------------------
__global__ void slice_kernel(float* __restrict__ out) {
    int idx = blockIdx.x*256 + threadIdx.x;
    const int total = BSZ*NTOK*(DOUT/4);
    if (idx >= total) return;
    int row = idx >> 4;
    int c4  = idx & 15;
    int b = row / NTOK, t = row - b*NTOK;
    reinterpret_cast<float4*>(out)[idx] =
        reinterpret_cast<const float4*>(g_of)[(size_t)(b*SEQ+t)*16 + c4];
}

// ---------------- host ---------------------------------------------------
static inline void tc_gemm(const bf16* Ah, const bf16* Al, const bf16* Bh, const bf16* Bl,
                           const float* bias, const float* res,
                           float* C, bf16* Chi, bf16* Clo,
                           int M, int N, int K, int act) {
    dim3 grid((N + 127) / 128, M / 128);
    tc_gemm_kernel<<<grid, 256, GEMM_SMEM>>>(Ah, Al, Bh, Bl, bias, res, C, Chi, Clo,
                                             M, N, K, act);
}

extern "C" void kernel_launch(void* const* d_in, const int* in_sizes, int n_in,
                              void* d_out, int out_size) {
    const float* x    = (const float*)d_in[0];
    const float* W1   = (const float*)d_in[1];
    const float* b1   = (const float*)d_in[2];
    const float* ln1g = (const float*)d_in[3];
    const float* ln1b = (const float*)d_in[4];
    const float* Wq   = (const float*)d_in[5];
    const float* Wk   = (const float*)d_in[6];
    const float* Wv   = (const float*)d_in[7];
    const float* Wo   = (const float*)d_in[8];
    const float* bo   = (const float*)d_in[9];
    const float* ln2g = (const float*)d_in[10];
    const float* ln2b = (const float*)d_in[11];
    const float* Wf1  = (const float*)d_in[12];
    const float* bf1  = (const float*)d_in[13];
    const float* Wf2  = (const float*)d_in[14];
    const float* bf2  = (const float*)d_in[15];
    const float* W2   = (const float*)d_in[16];
    const float* b2   = (const float*)d_in[17];
    float* out = (float*)d_out;

    static int smem_set = 0;
    if (!smem_set) {
        cudaFuncSetAttribute(tc_gemm_kernel, cudaFuncAttributeMaxDynamicSharedMemorySize, GEMM_SMEM);
        smem_set = 1;
    }

    float *h,*q,*k,*v,*attn,*of;
    bf16 *sh,*sl,*s2h,*s2l;
    bf16 *w1h,*w1l,*wqh,*wql,*wkh,*wkl,*wvh,*wvl,*woh,*wol,*wf1h,*wf1l,*wf2h,*wf2l,*w2h,*w2l;
    cudaGetSymbolAddress((void**)&h,    g_h);
    cudaGetSymbolAddress((void**)&q,    g_q);
    cudaGetSymbolAddress((void**)&k,    g_k);
    cudaGetSymbolAddress((void**)&v,    g_v);
    cudaGetSymbolAddress((void**)&attn, g_attn);
    cudaGetSymbolAddress((void**)&of,   g_of);
    cudaGetSymbolAddress((void**)&sh,   g_sh);
    cudaGetSymbolAddress((void**)&sl,   g_sl);
    cudaGetSymbolAddress((void**)&s2h,  g_s2h);
    cudaGetSymbolAddress((void**)&s2l,  g_s2l);
    cudaGetSymbolAddress((void**)&w1h,  g_w1h);   cudaGetSymbolAddress((void**)&w1l,  g_w1l);
    cudaGetSymbolAddress((void**)&wqh,  g_wqh);   cudaGetSymbolAddress((void**)&wql,  g_wql);
    cudaGetSymbolAddress((void**)&wkh,  g_wkh);   cudaGetSymbolAddress((void**)&wkl,  g_wkl);
    cudaGetSymbolAddress((void**)&wvh,  g_wvh);   cudaGetSymbolAddress((void**)&wvl,  g_wvl);
    cudaGetSymbolAddress((void**)&woh,  g_woh);   cudaGetSymbolAddress((void**)&wol,  g_wol);
    cudaGetSymbolAddress((void**)&wf1h, g_wf1h);  cudaGetSymbolAddress((void**)&wf1l, g_wf1l);
    cudaGetSymbolAddress((void**)&wf2h, g_wf2h);  cudaGetSymbolAddress((void**)&wf2l, g_wf2l);
    cudaGetSymbolAddress((void**)&w2h,  g_w2h);   cudaGetSymbolAddress((void**)&w2l,  g_w2l);

    // weight transposes + bf16 splits ([K,N] -> [N,K] hi/lo)
    dim3 tb(32, 8);
    transpose_split_kernel<<<dim3(DM/32,  DIN/32), tb>>>(W1,  w1h,  w1l,  DIN, DM);
    transpose_split_kernel<<<dim3(DM/32,  DM/32),  tb>>>(Wq,  wqh,  wql,  DM,  DM);
    transpose_split_kernel<<<dim3(DM/32,  DM/32),  tb>>>(Wk,  wkh,  wkl,  DM,  DM);
    transpose_split_kernel<<<dim3(DM/32,  DM/32),  tb>>>(Wv,  wvh,  wvl,  DM,  DM);
    transpose_split_kernel<<<dim3(DM/32,  DM/32),  tb>>>(Wo,  woh,  wol,  DM,  DM);
    transpose_split_kernel<<<dim3(DFF/32, DM/32),  tb>>>(Wf1, wf1h, wf1l, DM,  DFF);
    transpose_split_kernel<<<dim3(DM/32,  DFF/32), tb>>>(Wf2, wf2h, wf2l, DFF, DM);
    transpose_split_kernel<<<dim3(DOUT/32,DM/32),  tb>>>(W2,  w2h,  w2l,  DM,  DOUT);

    // 1. pad + split x into s (bf16 hi/lo, [MTOT,128])
    pad_split_kernel<<<(MTOT*DIN/4 + 255)/256, 256>>>(x);
    // 2. h = tanh(x @ W1 + b1)   (f32 out)
    tc_gemm(sh, sl, w1h, w1l, b1, nullptr, h, nullptr, nullptr, MTOT, DM, DIN, 1);
    // 3. ln1 -> split s
    ln_kernel<<<MTOT/8, 256>>>(h, ln1g, ln1b);
    // 4. q,k,v (f32 out)
    tc_gemm(sh, sl, wqh, wql, nullptr, nullptr, q, nullptr, nullptr, MTOT, DM, DM, 0);
    tc_gemm(sh, sl, wkh, wkl, nullptr, nullptr, k, nullptr, nullptr, MTOT, DM, DM, 0);
    tc_gemm(sh, sl, wvh, wvl, nullptr, nullptr, v, nullptr, nullptr, MTOT, DM, DM, 0);
    // 5. local attention (head 0)
    local_attn_kernel<<<BSZ*32*4, 1024>>>();
    // 6. linear attention (heads 1..3)
    kstats_kernel<<<dim3(BSZ*3,4), dim3(32,8)>>>();
    ctx_partial_kernel<<<dim3(BSZ*3,8), 256>>>();
    ctx_reduce_kernel<<<(BSZ*3*DH*DH + 255)/256, 256>>>();
    lin_out_kernel<<<dim3(BSZ*3, SEQ/32), 256>>>();
    // 7. split(attn) -> s; h = h + attn @ Wo + bo (f32)
    split_kernel<<<(MTOT*DM/4 + 255)/256, 256>>>(attn);
    tc_gemm(sh, sl, woh, wol, bo, h, h, nullptr, nullptr, MTOT, DM, DM, 0);
    // 8. ln2 -> split s
    ln_kernel<<<MTOT/8, 256>>>(h, ln2g, ln2b);
    // 9. ff = gelu(ln2 @ Wf1 + bf1) -> split s2 (bf16)
    tc_gemm(sh, sl, wf1h, wf1l, bf1, nullptr, nullptr, s2h, s2l, MTOT, DFF, DM, 2);
    // 10. hn = h + ff @ Wf2 + bf2 -> split s (bf16)
    tc_gemm(s2h, s2l, wf2h, wf2l, bf2, h, nullptr, sh, sl, MTOT, DM, DFF, 0);
    // 11. of = hn @ W2 + b2 (f32)
    tc_gemm(sh, sl, w2h, w2l, b2, nullptr, of, nullptr, nullptr, MTOT, DOUT, DM, 0);
    // 12. slice
    slice_kernel<<<(BSZ*NTOK*(DOUT/4) + 255)/256, 256>>>(out);
}

// round 5
// speedup vs baseline: 2.2462x; 1.0826x over previous
#include <cuda_runtime.h>
#include <cuda_bf16.h>
#include <math.h>
#include <stdint.h>

#define BSZ   8
#define SEQ   4096
#define NTOK  3000
#define DIN   128
#define DM    512
#define DFF   2048
#define DOUT  64
#define DH    128
#define MTOT  (BSZ*SEQ)              // 32768 rows
#define SCALE 0.08838834764831845f   // 1/sqrt(128)
#define GEMM_SMEM (3*32768)          // 3 stages x 4 arrays x 128 x 64B (swizzled)

typedef __nv_bfloat16 bf16;

// ---------------- scratch (static device globals: no allocation) -------------
__device__ float g_h[MTOT*DM];
__device__ float g_q[MTOT*DM];
__device__ float g_k[MTOT*DM];
__device__ float g_v[MTOT*DM];
__device__ float g_of[MTOT*DOUT];
__device__ float g_kmax[BSZ*3*DH];
__device__ float g_klse[BSZ*3*DH];
__device__ float g_ctxp[BSZ*3*8*DH*DH];
__device__ float g_ctx[BSZ*3*DH*DH];
// bf16 split activation buffers (reused across stages)
__device__ bf16 g_sh[MTOT*DM];
__device__ bf16 g_sl[MTOT*DM];
__device__ bf16 g_s2h[MTOT*DFF];
__device__ bf16 g_s2l[MTOT*DFF];
// transposed + split weights [N][K] bf16 hi/lo
__device__ bf16 g_w1h[DM*DIN],  g_w1l[DM*DIN];
__device__ bf16 g_wqh[DM*DM],   g_wql[DM*DM];
__device__ bf16 g_wkh[DM*DM],   g_wkl[DM*DM];
__device__ bf16 g_wvh[DM*DM],   g_wvl[DM*DM];
__device__ bf16 g_woh[DM*DM],   g_wol[DM*DM];
__device__ bf16 g_wf1h[DFF*DM], g_wf1l[DFF*DM];
__device__ bf16 g_wf2h[DM*DFF], g_wf2l[DM*DFF];
__device__ bf16 g_w2h[DOUT*DM], g_w2l[DOUT*DM];

// ---------------- helpers ----------------
__device__ __forceinline__ uint32_t smem_u32(const void* p) {
    uint32_t a;
    asm("{ .reg .u64 t; cvta.to.shared.u64 t, %1; cvt.u32.u64 %0, t; }" : "=r"(a) : "l"(p));
    return a;
}
__device__ __forceinline__ void split2(float x, float y, uint32_t& hi, uint32_t& lo) {
    __nv_bfloat162 h = __floats2bfloat162_rn(x, y);
    __nv_bfloat162 l = __floats2bfloat162_rn(x - __low2float(h), y - __high2float(h));
    hi = *reinterpret_cast<uint32_t*>(&h);
    lo = *reinterpret_cast<uint32_t*>(&l);
}

#define LDSM_X4(r0,r1,r2,r3,addr) \
    asm volatile("ldmatrix.sync.aligned.m8n8.x4.shared.b16 {%0,%1,%2,%3}, [%4];" \
        : "=r"(r0),"=r"(r1),"=r"(r2),"=r"(r3) : "r"(addr))
#define MMA16816(d, a0,a1,a2,a3, b0,b1) \
    asm volatile("mma.sync.aligned.m16n8k16.row.col.f32.bf16.bf16.f32 " \
        "{%0,%1,%2,%3},{%4,%5,%6,%7},{%8,%9},{%0,%1,%2,%3};" \
        : "+f"((d)[0]),"+f"((d)[1]),"+f"((d)[2]),"+f"((d)[3]) \
        : "r"(a0),"r"(a1),"r"(a2),"r"(a3),"r"(b0),"r"(b1))
#define CP_ASYNC16(dst, src, sz) \
    asm volatile("cp.async.cg.shared.global [%0], [%1], 16, %2;" :: "r"(dst), "l"(src), "r"(sz))
#define CP_COMMIT()  asm volatile("cp.async.commit_group;" ::: "memory")
#define CP_WAIT0()   asm volatile("cp.async.wait_group 0;" ::: "memory")
#define CP_WAIT1()   asm volatile("cp.async.wait_group 1;" ::: "memory")

// ---------------- weight transpose + bf16 split: T[n][k] = split(W[k][n]) ----
__global__ void transpose_split_kernel(const float* __restrict__ W,
                                       bf16* __restrict__ Th, bf16* __restrict__ Tl,
                                       int K, int N) {
    __shared__ float t[32][33];
    int bx = blockIdx.x * 32, by = blockIdx.y * 32;
    int x = bx + threadIdx.x;
    #pragma unroll
    for (int i = 0; i < 32; i += 8) {
        int y = by + threadIdx.y + i;
        if (x < N && y < K) t[threadIdx.y + i][threadIdx.x] = W[(size_t)y * N + x];
    }
    __syncthreads();
    int xk = by + threadIdx.x;
    #pragma unroll
    for (int i = 0; i < 32; i += 8) {
        int yn = bx + threadIdx.y + i;
        if (xk < K && yn < N) {
            float v = t[threadIdx.x][threadIdx.y + i];
            bf16 h = __float2bfloat16_rn(v);
            Th[(size_t)yn * K + xk] = h;
            Tl[(size_t)yn * K + xk] = __float2bfloat16_rn(v - __bfloat162float(h));
        }
    }
}

// ---------------- pad + split x -> g_sh/g_sl [MTOT][128] bf16 ----------------
__global__ void pad_split_kernel(const float* __restrict__ x) {
    int idx = blockIdx.x*256 + threadIdx.x;
    const int total = MTOT*DIN/4;
    if (idx >= total) return;
    int row = idx >> 5;
    int c4  = idx & 31;
    int b = row / SEQ, t = row - b*SEQ;
    float4 val = make_float4(0.f,0.f,0.f,0.f);
    if (t < NTOK)
        val = reinterpret_cast<const float4*>(x)[(size_t)(b*NTOK + t)*32 + c4];
    uint2 hv, lv;
    split2(val.x, val.y, hv.x, lv.x);
    split2(val.z, val.w, hv.y, lv.y);
    *reinterpret_cast<uint2*>(g_sh + (size_t)idx*4) = hv;
    *reinterpret_cast<uint2*>(g_sl + (size_t)idx*4) = lv;
}

// ---------------- bf16-split tensor-core GEMM --------------------------------
// C[M,N] = act(Ah+Al @ (Bh+Bl)^T + bias) + res, A[M,K] hi/lo, B[N,K] hi/lo.
// CTA 128x128, K-chunk 32, 3-stage cp.async pipeline, XOR-swizzled 64B rows,
// mma.sync m16n8k16 bf16, 3-term split product.
__global__ __launch_bounds__(256, 2) void tc_gemm_kernel(
    const bf16* __restrict__ Ah, const bf16* __restrict__ Al,
    const bf16* __restrict__ Bh, const bf16* __restrict__ Bl,
    const float* __restrict__ bias, const float* __restrict__ res,
    float* __restrict__ C, bf16* __restrict__ Chi, bf16* __restrict__ Clo,
    int M, int N, int K, int act)
{
    extern __shared__ __align__(1024) char smc[];
    uint32_t sbase = smem_u32(smc);
    int tid = threadIdx.x;
    int bm = blockIdx.y << 7, bn = blockIdx.x << 7;
    int lane = tid & 31, w = tid >> 5;
    int wm = w & 1, wn = w >> 1;        // warp grid 2(m) x 4(n), warp tile 64x32
    int grp = lane >> 2, qp = lane & 3;

    // swizzle: addr(row, chunk16B) = row*64 + ((chunk ^ ((row>>1)&3))<<4)
    uint32_t swz = (lane >> 1) & 3;
    uint32_t a_base = (uint32_t)(wm*64 + (lane & 15))*64 + (((uint32_t)(lane >> 4) ^ swz) << 4);
    uint32_t b_base = (uint32_t)(wn*32 + ((lane >> 4) & 1)*8 + (lane & 7))*64
                    + ((((uint32_t)(lane >> 3) & 1) ^ swz) << 4);

    float acc[4][4][4];
    #pragma unroll
    for (int i=0;i<4;i++)
        #pragma unroll
        for (int j=0;j<4;j++)
            #pragma unroll
            for (int r=0;r<4;r++) acc[i][j][r] = 0.f;

    const int NC = K >> 5;

    // stage loader: arrays Ah@0, Al@8192, Bh@16384, Bl@24576 (each 128x64B swizzled)
    #define STAGE_LOAD(c_, buf_) do { \
        int k0 = (c_) << 5; \
        uint32_t sb = sbase + (uint32_t)(buf_)*32768u; \
        _Pragma("unroll") \
        for (int i_ = 0; i_ < 8; i_++) { \
            const int arr_ = i_ >> 1; \
            int j_ = ((i_ & 1) << 8) + tid; \
            int r_ = j_ >> 2, cc_ = j_ & 3; \
            uint32_t dst_ = sb + arr_*8192u + (uint32_t)r_*64u \
                          + ((uint32_t)(cc_ ^ ((r_ >> 1) & 3)) << 4); \
            const bf16* g_; int sz_ = 16; \
            if (arr_ == 0)      g_ = Ah + (size_t)(bm + r_)*K + k0 + cc_*8; \
            else if (arr_ == 1) g_ = Al + (size_t)(bm + r_)*K + k0 + cc_*8; \
            else { \
                int rowv_ = bn + r_; \
                const bf16* base_ = (arr_ == 2) ? Bh : Bl; \
                if (rowv_ < N) g_ = base_ + (size_t)rowv_*K + k0 + cc_*8; \
                else { g_ = base_; sz_ = 0; } \
            } \
            CP_ASYNC16(dst_, g_, sz_); \
        } \
        CP_COMMIT(); \
    } while (0)

    STAGE_LOAD(0, 0);
    if (NC > 1) STAGE_LOAD(1, 1);

    int buf = 0, bufn = 2;
    for (int c = 0; c < NC; c++) {
        if (c + 1 < NC) CP_WAIT1(); else CP_WAIT0();
        __syncthreads();
        if (c + 2 < NC) {
            STAGE_LOAD(c + 2, bufn);
            bufn = (bufn == 2) ? 0 : bufn + 1;
        }
        uint32_t sA  = sbase + (uint32_t)buf*32768u;
        uint32_t sAl = sA + 8192u, sB = sA + 16384u, sBl = sA + 24576u;
        buf = (buf == 2) ? 0 : buf + 1;

        #pragma unroll
        for (int ks = 0; ks < 2; ks++) {
            uint32_t kx = ks ? 32u : 0u;
            uint32_t bh[4][2], bl[4][2], a[4][4];
            #pragma unroll
            for (int p = 0; p < 2; p++) {
                LDSM_X4(bh[2*p][0], bh[2*p][1], bh[2*p+1][0], bh[2*p+1][1],
                        sB  + ((b_base + p*1024u) ^ kx));
                LDSM_X4(bl[2*p][0], bl[2*p][1], bl[2*p+1][0], bl[2*p+1][1],
                        sBl + ((b_base + p*1024u) ^ kx));
            }
            #pragma unroll
            for (int mt = 0; mt < 4; mt++)
                LDSM_X4(a[mt][0], a[mt][1], a[mt][2], a[mt][3],
                        sA + ((a_base + mt*1024u) ^ kx));
            #pragma unroll
            for (int mt = 0; mt < 4; mt++)
                #pragma unroll
                for (int nt = 0; nt < 4; nt++) {
                    MMA16816(acc[mt][nt], a[mt][0],a[mt][1],a[mt][2],a[mt][3], bh[nt][0],bh[nt][1]);
                    MMA16816(acc[mt][nt], a[mt][0],a[mt][1],a[mt][2],a[mt][3], bl[nt][0],bl[nt][1]);
                }
            #pragma unroll
            for (int mt = 0; mt < 4; mt++)
                LDSM_X4(a[mt][0], a[mt][1], a[mt][2], a[mt][3],
                        sAl + ((a_base + mt*1024u) ^ kx));
            #pragma unroll
            for (int mt = 0; mt < 4; mt++)
                #pragma unroll
                for (int nt = 0; nt < 4; nt++)
                    MMA16816(acc[mt][nt], a[mt][0],a[mt][1],a[mt][2],a[mt][3], bh[nt][0],bh[nt][1]);
        }
    }
    #undef STAGE_LOAD

    // ---- epilogue ----
    #pragma unroll
    for (int mt = 0; mt < 4; mt++) {
        #pragma unroll
        for (int nt = 0; nt < 4; nt++) {
            int c0 = bn + wn*32 + nt*8 + qp*2;
            if (c0 >= N) continue;
            int rbase = bm + wm*64 + mt*16 + grp;
            float bs0 = 0.f, bs1 = 0.f;
            if (bias) { bs0 = bias[c0]; bs1 = bias[c0 + 1]; }
            #pragma unroll
            for (int half = 0; half < 2; half++) {
                int r = rbase + half*8;
                float v0 = acc[mt][nt][half*2 + 0] + bs0;
                float v1 = acc[mt][nt][half*2 + 1] + bs1;
                if (act == 1) { v0 = tanhf(v0); v1 = tanhf(v1); }
                else if (act == 2) {
                    v0 = 0.5f*v0*(1.f + erff(v0*0.7071067811865476f));
                    v1 = 0.5f*v1*(1.f + erff(v1*0.7071067811865476f));
                }
                if (res) {
                    v0 += res[(size_t)r*N + c0];
                    v1 += res[(size_t)r*N + c0 + 1];
                }
                if (Chi) {
                    uint32_t hv, lv;
                    split2(v0, v1, hv, lv);
                    *reinterpret_cast<uint32_t*>(Chi + (size_t)r*N + c0) = hv;
                    *reinterpret_cast<uint32_t*>(Clo + (size_t)r*N + c0) = lv;
                } else {
                    float2 o; o.x = v0; o.y = v1;
                    *reinterpret_cast<float2*>(C + (size_t)r*N + c0) = o;
                }
            }
        }
    }
}

// ---------------- LayerNorm (row=512) -> bf16 hi/lo split --------------------
__global__ void ln_kernel(const float* __restrict__ in, const float* __restrict__ gam,
                          const float* __restrict__ bet) {
    int gw = (blockIdx.x*blockDim.x + threadIdx.x) >> 5;
    int lane = threadIdx.x & 31;
    if (gw >= MTOT) return;
    const float4* rp = reinterpret_cast<const float4*>(in + (size_t)gw*DM);
    float4 v[4];
    float s=0.f, s2=0.f;
    #pragma unroll
    for (int i=0;i<4;i++) {
        v[i] = rp[lane + 32*i];
        s  += v[i].x+v[i].y+v[i].z+v[i].w;
        s2 += v[i].x*v[i].x + v[i].y*v[i].y + v[i].z*v[i].z + v[i].w*v[i].w;
    }
    #pragma unroll
    for (int o=16;o;o>>=1) { s += __shfl_xor_sync(~0u,s,o); s2 += __shfl_xor_sync(~0u,s2,o); }
    float mu  = s*(1.f/512.f);
    float var = s2*(1.f/512.f) - mu*mu;
    float r = rsqrtf(var + 1e-5f);
    #pragma unroll
    for (int i=0;i<4;i++) {
        int c = (lane + 32*i)*4;
        float4 g4 = *reinterpret_cast<const float4*>(gam + c);
        float4 b4 = *reinterpret_cast<const float4*>(bet + c);
        float o0 = (v[i].x-mu)*r*g4.x + b4.x;
        float o1 = (v[i].y-mu)*r*g4.y + b4.y;
        float o2 = (v[i].z-mu)*r*g4.z + b4.z;
        float o3 = (v[i].w-mu)*r*g4.w + b4.w;
        uint2 hv, lv;
        split2(o0, o1, hv.x, lv.x);
        split2(o2, o3, hv.y, lv.y);
        size_t off = (size_t)gw*DM + c;
        *reinterpret_cast<uint2*>(g_sh + off) = hv;
        *reinterpret_cast<uint2*>(g_sl + off) = lv;
    }
}

// ---------------- local attention, head 0, window 128 with look-around ------
// writes bf16 hi/lo split directly into g_sh/g_sl (cols 0..127)
__global__ __launch_bounds__(1024) void local_attn_kernel() {
    __shared__ float tile[64][DH];
    __shared__ float scores[32][64];
    int bx = blockIdx.x;
    int b   = bx >> 7;
    int win = (bx >> 2) & 31;
    int qc  = bx & 3;
    int warp = threadIdx.x >> 5, lane = threadIdx.x & 31;
    int qt = win*128 + qc*32 + warp;
    size_t qoff = (size_t)(b*SEQ + qt)*DM;
    float4 q4 = *reinterpret_cast<const float4*>(g_q + qoff + lane*4);
    float m = -1e30f, l = 0.f;
    float4 acc = make_float4(0.f,0.f,0.f,0.f);
    int kbase = win*128 - 128;
    for (int ch=0; ch<6; ch++) {
        int t0 = kbase + ch*64;
        __syncthreads();
        #pragma unroll
        for (int it=0; it<2; it++) {
            int idx = it*1024 + threadIdx.x;
            int r = idx >> 5, c4 = idx & 31;
            int t = t0 + r;
            float4 kv = make_float4(0.f,0.f,0.f,0.f);
            if (t >= 0 && t < SEQ)
                kv = *reinterpret_cast<const float4*>(g_k + (size_t)(b*SEQ+t)*DM + c4*4);
            *reinterpret_cast<float4*>(&tile[r][c4*4]) = kv;
        }
        __syncthreads();
        for (int j=0; j<64; j++) {
            float4 kv = *reinterpret_cast<const float4*>(&tile[j][lane*4]);
            float s = q4.x*kv.x + q4.y*kv.y + q4.z*kv.z + q4.w*kv.w;
            #pragma unroll
            for (int o=16;o;o>>=1) s += __shfl_xor_sync(~0u,s,o);
            if (lane == (j & 31)) {
                int t = t0 + j;
                scores[warp][j] = (t >= 0 && t < SEQ) ? s*SCALE : -1e38f;
            }
        }
        __syncthreads();
        #pragma unroll
        for (int it=0; it<2; it++) {
            int idx = it*1024 + threadIdx.x;
            int r = idx >> 5, c4 = idx & 31;
            int t = t0 + r;
            float4 vv = make_float4(0.f,0.f,0.f,0.f);
            if (t >= 0 && t < SEQ)
                vv = *reinterpret_cast<const float4*>(g_v + (size_t)(b*SEQ+t)*DM + c4*4);
            *reinterpret_cast<float4*>(&tile[r][c4*4]) = vv;
        }
        __syncthreads();
        float cm = fmaxf(scores[warp][lane], scores[warp][lane+32]);
        #pragma unroll
        for (int o=16;o;o>>=1) cm = fmaxf(cm, __shfl_xor_sync(~0u,cm,o));
        float mn = fmaxf(m, cm);
        float corr = expf(m - mn);
        l *= corr; acc.x*=corr; acc.y*=corr; acc.z*=corr; acc.w*=corr;
        for (int j=0; j<64; j++) {
            float p = expf(scores[warp][j] - mn);
            l += p;
            float4 vv = *reinterpret_cast<const float4*>(&tile[j][lane*4]);
            acc.x = fmaf(p, vv.x, acc.x);
            acc.y = fmaf(p, vv.y, acc.y);
            acc.z = fmaf(p, vv.z, acc.z);
            acc.w = fmaf(p, vv.w, acc.w);
        }
        m = mn;
    }
    float inv = 1.f/l;
    uint2 hv, lv;
    split2(acc.x*inv, acc.y*inv, hv.x, lv.x);
    split2(acc.z*inv, acc.w*inv, hv.y, lv.y);
    *reinterpret_cast<uint2*>(g_sh + qoff + lane*4) = hv;
    *reinterpret_cast<uint2*>(g_sl + qoff + lane*4) = lv;
}

// ---------------- k column softmax stats (heads 1..3) -----------------------
__global__ void kstats_kernel() {
    int bh = blockIdx.x;
    int b = bh/3, hh = bh%3 + 1;
    int d = blockIdx.y*32 + threadIdx.x;
    int ty = threadIdx.y;
    int col = hh*DH + d;
    float m = -1e30f, l = 0.f;
    for (int t = ty; t < SEQ; t += 8) {
        float val = g_k[(size_t)(b*SEQ+t)*DM + col];
        if (val > m) { l = l*expf(m - val) + 1.f; m = val; }
        else l += expf(val - m);
    }
    __shared__ float sm[8][32], sl[8][32];
    sm[ty][threadIdx.x] = m; sl[ty][threadIdx.x] = l;
    __syncthreads();
    if (ty == 0) {
        #pragma unroll
        for (int r=1;r<8;r++) {
            float m2 = sm[r][threadIdx.x], l2 = sl[r][threadIdx.x];
            float M = fmaxf(m, m2);
            l = l*expf(m - M) + l2*expf(m2 - M);
            m = M;
        }
        g_kmax[bh*DH + d] = m;
        g_klse[bh*DH + d] = l;
    }
}

// ---------------- ctx partial: ctx[d][e] = sum_t k'[t,d] v[t,e] (K-split 8) --
__global__ __launch_bounds__(256) void ctx_partial_kernel() {
    __shared__ float kt[32][132];
    __shared__ float vt[32][132];
    __shared__ float smax[DH], sinv[DH];
    int bh = blockIdx.x, ks = blockIdx.y;
    int b = bh/3, hh = bh%3 + 1;
    if (threadIdx.x < DH) {
        smax[threadIdx.x] = g_kmax[bh*DH + threadIdx.x];
        sinv[threadIdx.x] = 1.f/g_klse[bh*DH + threadIdx.x];
    }
    int tx = threadIdx.x & 15, ty = threadIdx.x >> 4;
    float acc[8][8];
    #pragma unroll
    for (int i=0;i<8;i++)
        #pragma unroll
        for (int j=0;j<8;j++) acc[i][j]=0.f;

    for (int t0=0; t0<512; t0+=32) {
        __syncthreads();
        #pragma unroll
        for (int i=0;i<4;i++) {
            int idx = i*256 + threadIdx.x;
            int r = idx >> 5, c4 = idx & 31;
            int t = ks*512 + t0 + r;
            size_t off = (size_t)(b*SEQ+t)*DM + hh*DH + c4*4;
            float4 kv = *reinterpret_cast<const float4*>(g_k + off);
            float4 vv = *reinterpret_cast<const float4*>(g_v + off);
            int d0 = c4*4;
            kt[r][d0+0] = expf(kv.x - smax[d0+0])*sinv[d0+0];
            kt[r][d0+1] = expf(kv.y - smax[d0+1])*sinv[d0+1];
            kt[r][d0+2] = expf(kv.z - smax[d0+2])*sinv[d0+2];
            kt[r][d0+3] = expf(kv.w - smax[d0+3])*sinv[d0+3];
            *reinterpret_cast<float4*>(&vt[r][d0]) = vv;
        }
        __syncthreads();
        #pragma unroll
        for (int kk=0; kk<32; kk++) {
            float a[8], bb[8];
            *reinterpret_cast<float4*>(&a[0])  = *reinterpret_cast<const float4*>(&kt[kk][ty*8]);
            *reinterpret_cast<float4*>(&a[4])  = *reinterpret_cast<const float4*>(&kt[kk][ty*8+4]);
            *reinterpret_cast<float4*>(&bb[0]) = *reinterpret_cast<const float4*>(&vt[kk][tx*8]);
            *reinterpret_cast<float4*>(&bb[4]) = *reinterpret_cast<const float4*>(&vt[kk][tx*8+4]);
            #pragma unroll
            for (int i=0;i<8;i++)
                #pragma unroll
                for (int j=0;j<8;j++)
                    acc[i][j] = fmaf(a[i], bb[j], acc[i][j]);
        }
    }
    float* op = g_ctxp + ((size_t)bh*8 + ks)*DH*DH;
    #pragma unroll
    for (int i=0;i<8;i++)
        #pragma unroll
        for (int j=0;j<8;j+=4) {
            float4 o4 = make_float4(acc[i][j],acc[i][j+1],acc[i][j+2],acc[i][j+3]);
            *reinterpret_cast<float4*>(op + (size_t)(ty*8+i)*DH + tx*8 + j) = o4;
        }
}

__global__ void ctx_reduce_kernel() {
    int idx = blockIdx.x*256 + threadIdx.x;
    if (idx >= BSZ*3*DH*DH) return;
    int bh = idx / (DH*DH);
    int de = idx - bh*DH*DH;
    float s = 0.f;
    #pragma unroll
    for (int ks=0;ks<8;ks++) s += g_ctxp[((size_t)bh*8+ks)*DH*DH + de];
    g_ctx[idx] = s;
}

// ---------------- linear-attn output -> split bf16 directly ------------------
__global__ __launch_bounds__(256) void lin_out_kernel() {
    __shared__ float sctx[64][DH];
    int bh = blockIdx.x;
    int b = bh/3, hh = bh%3 + 1;
    int warp = threadIdx.x >> 5, lane = threadIdx.x & 31;
    const float* ctxp = g_ctx + (size_t)bh*DH*DH;
    float pr[4][4], o[4][4];
    int tbase = blockIdx.y*32 + warp*4;
    #pragma unroll
    for (int tt=0;tt<4;tt++) {
        int t = tbase + tt;
        const float* qp = g_q + (size_t)(b*SEQ+t)*DM + hh*DH;
        float4 q4 = *reinterpret_cast<const float4*>(qp + lane*4);
        float mx = fmaxf(fmaxf(q4.x,q4.y),fmaxf(q4.z,q4.w));
        #pragma unroll
        for (int s=16;s;s>>=1) mx = fmaxf(mx, __shfl_xor_sync(~0u,mx,s));
        float e0=expf(q4.x-mx), e1=expf(q4.y-mx), e2=expf(q4.z-mx), e3=expf(q4.w-mx);
        float sm = e0+e1+e2+e3;
        #pragma unroll
        for (int s=16;s;s>>=1) sm += __shfl_xor_sync(~0u,sm,s);
        float inv = SCALE/sm;
        pr[tt][0]=e0*inv; pr[tt][1]=e1*inv; pr[tt][2]=e2*inv; pr[tt][3]=e3*inv;
        o[tt][0]=0.f; o[tt][1]=0.f; o[tt][2]=0.f; o[tt][3]=0.f;
    }
    for (int ph=0; ph<2; ph++) {
        __syncthreads();
        #pragma unroll
        for (int i=0;i<8;i++) {
            int idx = i*256 + threadIdx.x;
            int r = idx >> 5, c4 = idx & 31;
            *reinterpret_cast<float4*>(&sctx[r][c4*4]) =
                *reinterpret_cast<const float4*>(ctxp + (size_t)(ph*64+r)*DH + c4*4);
        }
        __syncthreads();
        #pragma unroll
        for (int dl=0; dl<16; dl++) {
            int src = ph*16 + dl;
            #pragma unroll
            for (int tt=0;tt<4;tt++) {
                float b0 = __shfl_sync(~0u, pr[tt][0], src);
                float b1 = __shfl_sync(~0u, pr[tt][1], src);
                float b2 = __shfl_sync(~0u, pr[tt][2], src);
                float b3 = __shfl_sync(~0u, pr[tt][3], src);
                float4 c0 = *reinterpret_cast<const float4*>(&sctx[dl*4+0][lane*4]);
                float4 c1 = *reinterpret_cast<const float4*>(&sctx[dl*4+1][lane*4]);
                float4 c2 = *reinterpret_cast<const float4*>(&sctx[dl*4+2][lane*4]);
                float4 c3 = *reinterpret_cast<const float4*>(&sctx[dl*4+3][lane*4]);
                o[tt][0] += b0*c0.x + b1*c1.x + b2*c2.x + b3*c3.x;
                o[tt][1] += b0*c0.y + b1*c1.y + b2*c2.y + b3*c3.y;
                o[tt][2] += b0*c0.z + b1*c1.z + b2*c2.z + b3*c3.z;
                o[tt][3] += b0*c0.w + b1*c1.w + b2*c2.w + b3*c3.w;
            }
        }
    }
    #pragma unroll
    for (int tt=0;tt<4;tt++) {
        int t = tbase + tt;
        size_t off = (size_t)(b*SEQ+t)*DM + hh*DH + lane*4;
        uint2 hv, lv;
        split2(o[tt][0], o[tt][1], hv.x, lv.x);
        split2(o[tt][2], o[tt][3], hv.y, lv.y);
        *reinterpret_cast<uint2*>(g_sh + off) = hv;
        *reinterpret_cast<uint2*>(g_sl + off) = lv;
    }
}

// ---------------- final slice (drop padded rows) -----------------------------
__global__ void slice_kernel(float* __restrict__ out) {
    int idx = blockIdx.x*256 + threadIdx.x;
    const int total = BSZ*NTOK*(DOUT/4);
    if (idx >= total) return;
    int row = idx >> 4;
    int c4  = idx & 15;
    int b = row / NTOK, t = row - b*NTOK;
    reinterpret_cast<float4*>(out)[idx] =
        reinterpret_cast<const float4*>(g_of)[(size_t)(b*SEQ+t)*16 + c4];
}

// ---------------- host ---------------------------------------------------
static inline void tc_gemm(const bf16* Ah, const bf16* Al, const bf16* Bh, const bf16* Bl,
                           const float* bias, const float* res,
                           float* C, bf16* Chi, bf16* Clo,
                           int M, int N, int K, int act) {
    dim3 grid((N + 127) / 128, M / 128);
    tc_gemm_kernel<<<grid, 256, GEMM_SMEM>>>(Ah, Al, Bh, Bl, bias, res, C, Chi, Clo,
                                             M, N, K, act);
}

extern "C" void kernel_launch(void* const* d_in, const int* in_sizes, int n_in,
                              void* d_out, int out_size) {
    const float* x    = (const float*)d_in[0];
    const float* W1   = (const float*)d_in[1];
    const float* b1   = (const float*)d_in[2];
    const float* ln1g = (const float*)d_in[3];
    const float* ln1b = (const float*)d_in[4];
    const float* Wq   = (const float*)d_in[5];
    const float* Wk   = (const float*)d_in[6];
    const float* Wv   = (const float*)d_in[7];
    const float* Wo   = (const float*)d_in[8];
    const float* bo   = (const float*)d_in[9];
    const float* ln2g = (const float*)d_in[10];
    const float* ln2b = (const float*)d_in[11];
    const float* Wf1  = (const float*)d_in[12];
    const float* bf1  = (const float*)d_in[13];
    const float* Wf2  = (const float*)d_in[14];
    const float* bf2  = (const float*)d_in[15];
    const float* W2   = (const float*)d_in[16];
    const float* b2   = (const float*)d_in[17];
    float* out = (float*)d_out;

    static int smem_set = 0;
    if (!smem_set) {
        cudaFuncSetAttribute(tc_gemm_kernel, cudaFuncAttributeMaxDynamicSharedMemorySize, GEMM_SMEM);
        smem_set = 1;
    }

    float *h,*q,*k,*v,*of;
    bf16 *sh,*sl,*s2h,*s2l;
    bf16 *w1h,*w1l,*wqh,*wql,*wkh,*wkl,*wvh,*wvl,*woh,*wol,*wf1h,*wf1l,*wf2h,*wf2l,*w2h,*w2l;
    cudaGetSymbolAddress((void**)&h,    g_h);
    cudaGetSymbolAddress((void**)&q,    g_q);
    cudaGetSymbolAddress((void**)&k,    g_k);
    cudaGetSymbolAddress((void**)&v,    g_v);
    cudaGetSymbolAddress((void**)&of,   g_of);
    cudaGetSymbolAddress((void**)&sh,   g_sh);
    cudaGetSymbolAddress((void**)&sl,   g_sl);
    cudaGetSymbolAddress((void**)&s2h,  g_s2h);
    cudaGetSymbolAddress((void**)&s2l,  g_s2l);
    cudaGetSymbolAddress((void**)&w1h,  g_w1h);   cudaGetSymbolAddress((void**)&w1l,  g_w1l);
    cudaGetSymbolAddress((void**)&wqh,  g_wqh);   cudaGetSymbolAddress((void**)&wql,  g_wql);
    cudaGetSymbolAddress((void**)&wkh,  g_wkh);   cudaGetSymbolAddress((void**)&wkl,  g_wkl);
    cudaGetSymbolAddress((void**)&wvh,  g_wvh);   cudaGetSymbolAddress((void**)&wvl,  g_wvl);
    cudaGetSymbolAddress((void**)&woh,  g_woh);   cudaGetSymbolAddress((void**)&wol,  g_wol);
    cudaGetSymbolAddress((void**)&wf1h, g_wf1h);  cudaGetSymbolAddress((void**)&wf1l, g_wf1l);
    cudaGetSymbolAddress((void**)&wf2h, g_wf2h);  cudaGetSymbolAddress((void**)&wf2l, g_wf2l);
    cudaGetSymbolAddress((void**)&w2h,  g_w2h);   cudaGetSymbolAddress((void**)&w2l,  g_w2l);

    // weight transposes + bf16 splits ([K,N] -> [N,K] hi/lo)
    dim3 tb(32, 8);
    transpose_split_kernel<<<dim3(DM/32,  DIN/32), tb>>>(W1,  w1h,  w1l,  DIN, DM);
    transpose_split_kernel<<<dim3(DM/32,  DM/32),  tb>>>(Wq,  wqh,  wql,  DM,  DM);
    transpose_split_kernel<<<dim3(DM/32,  DM/32),  tb>>>(Wk,  wkh,  wkl,  DM,  DM);
    transpose_split_kernel<<<dim3(DM/32,  DM/32),  tb>>>(Wv,  wvh,  wvl,  DM,  DM);
    transpose_split_kernel<<<dim3(DM/32,  DM/32),  tb>>>(Wo,  woh,  wol,  DM,  DM);
    transpose_split_kernel<<<dim3(DFF/32, DM/32),  tb>>>(Wf1, wf1h, wf1l, DM,  DFF);
    transpose_split_kernel<<<dim3(DM/32,  DFF/32), tb>>>(Wf2, wf2h, wf2l, DFF, DM);
    transpose_split_kernel<<<dim3(DOUT/32,DM/32),  tb>>>(W2,  w2h,  w2l,  DM,  DOUT);

    // 1. pad + split x into s (bf16 hi/lo, [MTOT,128])
    pad_split_kernel<<<(MTOT*DIN/4 + 255)/256, 256>>>(x);
    // 2. h = tanh(x @ W1 + b1)   (f32 out)
    tc_gemm(sh, sl, w1h, w1l, b1, nullptr, h, nullptr, nullptr, MTOT, DM, DIN, 1);
    // 3. ln1 -> split s
    ln_kernel<<<MTOT/8, 256>>>(h, ln1g, ln1b);
    // 4. q,k,v (f32 out)
    tc_gemm(sh, sl, wqh, wql, nullptr, nullptr, q, nullptr, nullptr, MTOT, DM, DM, 0);
    tc_gemm(sh, sl, wkh, wkl, nullptr, nullptr, k, nullptr, nullptr, MTOT, DM, DM, 0);
    tc_gemm(sh, sl, wvh, wvl, nullptr, nullptr, v, nullptr, nullptr, MTOT, DM, DM, 0);
    // 5. local attention (head 0) -> writes split directly into s
    local_attn_kernel<<<BSZ*32*4, 1024>>>();
    // 6. linear attention (heads 1..3) -> writes split directly into s
    kstats_kernel<<<dim3(BSZ*3,4), dim3(32,8)>>>();
    ctx_partial_kernel<<<dim3(BSZ*3,8), 256>>>();
    ctx_reduce_kernel<<<(BSZ*3*DH*DH + 255)/256, 256>>>();
    lin_out_kernel<<<dim3(BSZ*3, SEQ/32), 256>>>();
    // 7. h = h + attn @ Wo + bo (f32)
    tc_gemm(sh, sl, woh, wol, bo, h, h, nullptr, nullptr, MTOT, DM, DM, 0);
    // 8. ln2 -> split s
    ln_kernel<<<MTOT/8, 256>>>(h, ln2g, ln2b);
    // 9. ff = gelu(ln2 @ Wf1 + bf1) -> split s2 (bf16)
    tc_gemm(sh, sl, wf1h, wf1l, bf1, nullptr, nullptr, s2h, s2l, MTOT, DFF, DM, 2);
    // 10. hn = h + ff @ Wf2 + bf2 -> split s (bf16)
    tc_gemm(s2h, s2l, wf2h, wf2l, bf2, h, nullptr, sh, sl, MTOT, DM, DFF, 0);
    // 11. of = hn @ W2 + b2 (f32)
    tc_gemm(sh, sl, w2h, w2l, b2, nullptr, of, nullptr, nullptr, MTOT, DOUT, DM, 0);
    // 12. slice
    slice_kernel<<<(BSZ*NTOK*(DOUT/4) + 255)/256, 256>>>(out);
}

// round 6
// speedup vs baseline: 2.6721x; 1.1896x over previous
#include <cuda_runtime.h>
#include <cuda_bf16.h>
#include <math.h>
#include <stdint.h>

#define BSZ   8
#define SEQ   4096
#define NTOK  3000
#define DIN   128
#define DM    512
#define DFF   2048
#define DOUT  64
#define DH    128
#define MTOT  (BSZ*SEQ)
#define MTPB  24                     // M-tiles per batch: ceil(3000/128)
#define SCALE 0.08838834764831845f   // 1/sqrt(128)
#define GEMM_SMEM (3*32768)          // 3 stages x 4 arrays x 128 x 64B (swizzled)

typedef __nv_bfloat16 bf16;

// ---------------- scratch (static device globals: no allocation) -------------
__device__ float g_h[MTOT*DM];
__device__ float g_q[MTOT*DM];
__device__ float g_k[MTOT*DM];
__device__ float g_v[MTOT*DM];
__device__ float g_of[MTOT*DOUT];
__device__ float g_kmax[BSZ*3*DH];
__device__ float g_klse[BSZ*3*DH];
__device__ float g_ctxp[BSZ*3*8*DH*DH];
__device__ float g_ctx[BSZ*3*DH*DH];
__device__ float g_lnpad[DM];
__device__ float g_kpad[DM];
__device__ float g_vpad[DM];
// bf16 split activation buffers (reused across stages)
__device__ bf16 g_sh[MTOT*DM];
__device__ bf16 g_sl[MTOT*DM];
__device__ bf16 g_s2h[MTOT*DFF];
__device__ bf16 g_s2l[MTOT*DFF];
// transposed + split weights [N][K] bf16 hi/lo
__device__ bf16 g_w1h[DM*DIN],  g_w1l[DM*DIN];
__device__ bf16 g_wqh[DM*DM],   g_wql[DM*DM];
__device__ bf16 g_wkh[DM*DM],   g_wkl[DM*DM];
__device__ bf16 g_wvh[DM*DM],   g_wvl[DM*DM];
__device__ bf16 g_woh[DM*DM],   g_wol[DM*DM];
__device__ bf16 g_wf1h[DFF*DM], g_wf1l[DFF*DM];
__device__ bf16 g_wf2h[DM*DFF], g_wf2l[DM*DFF];
__device__ bf16 g_w2h[DOUT*DM], g_w2l[DOUT*DM];

// ---------------- helpers ----------------
__device__ __forceinline__ uint32_t smem_u32(const void* p) {
    uint32_t a;
    asm("{ .reg .u64 t; cvta.to.shared.u64 t, %1; cvt.u32.u64 %0, t; }" : "=r"(a) : "l"(p));
    return a;
}
__device__ __forceinline__ void split2(float x, float y, uint32_t& hi, uint32_t& lo) {
    __nv_bfloat162 h = __floats2bfloat162_rn(x, y);
    __nv_bfloat162 l = __floats2bfloat162_rn(x - __low2float(h), y - __high2float(h));
    hi = *reinterpret_cast<uint32_t*>(&h);
    lo = *reinterpret_cast<uint32_t*>(&l);
}

#define LDSM_X4(r0,r1,r2,r3,addr) \
    asm volatile("ldmatrix.sync.aligned.m8n8.x4.shared.b16 {%0,%1,%2,%3}, [%4];" \
        : "=r"(r0),"=r"(r1),"=r"(r2),"=r"(r3) : "r"(addr))
#define MMA16816(d, a0,a1,a2,a3, b0,b1) \
    asm volatile("mma.sync.aligned.m16n8k16.row.col.f32.bf16.bf16.f32 " \
        "{%0,%1,%2,%3},{%4,%5,%6,%7},{%8,%9},{%0,%1,%2,%3};" \
        : "+f"((d)[0]),"+f"((d)[1]),"+f"((d)[2]),"+f"((d)[3]) \
        : "r"(a0),"r"(a1),"r"(a2),"r"(a3),"r"(b0),"r"(b1))
#define CP_ASYNC16(dst, src, sz) \
    asm volatile("cp.async.cg.shared.global [%0], [%1], 16, %2;" :: "r"(dst), "l"(src), "r"(sz))
#define CP_COMMIT()  asm volatile("cp.async.commit_group;" ::: "memory")
#define CP_WAIT0()   asm volatile("cp.async.wait_group 0;" ::: "memory")
#define CP_WAIT1()   asm volatile("cp.async.wait_group 1;" ::: "memory")

// ---------------- weight transpose + bf16 split: T[n][k] = split(W[k][n]) ----
__global__ void transpose_split_kernel(const float* __restrict__ W,
                                       bf16* __restrict__ Th, bf16* __restrict__ Tl,
                                       int K, int N) {
    __shared__ float t[32][33];
    int bx = blockIdx.x * 32, by = blockIdx.y * 32;
    int x = bx + threadIdx.x;
    #pragma unroll
    for (int i = 0; i < 32; i += 8) {
        int y = by + threadIdx.y + i;
        if (x < N && y < K) t[threadIdx.y + i][threadIdx.x] = W[(size_t)y * N + x];
    }
    __syncthreads();
    int xk = by + threadIdx.x;
    #pragma unroll
    for (int i = 0; i < 32; i += 8) {
        int yn = bx + threadIdx.y + i;
        if (xk < K && yn < N) {
            float v = t[threadIdx.x][threadIdx.y + i];
            bf16 h = __float2bfloat16_rn(v);
            Th[(size_t)yn * K + xk] = h;
            Tl[(size_t)yn * K + xk] = __float2bfloat16_rn(v - __bfloat162float(h));
        }
    }
}

// ---------------- pad + split x (real rows only) -> g_sh/g_sl ----------------
__global__ void pad_split_kernel(const float* __restrict__ x) {
    int idx = blockIdx.x*256 + threadIdx.x;
    const int total = BSZ*NTOK*(DIN/4);
    if (idx >= total) return;
    int rr = idx >> 5;             // real row index
    int c4 = idx & 31;
    int b = rr / NTOK, t = rr - b*NTOK;
    float4 val = reinterpret_cast<const float4*>(x)[(size_t)rr*32 + c4];
    uint2 hv, lv;
    split2(val.x, val.y, hv.x, lv.x);
    split2(val.z, val.w, hv.y, lv.y);
    size_t off = ((size_t)(b*SEQ + t)*DIN + c4*4);
    *reinterpret_cast<uint2*>(g_sh + off) = hv;
    *reinterpret_cast<uint2*>(g_sl + off) = lv;
}

// ---------------- pad-row LN: lnpad = LN(tanh(b1)) ---------------------------
__global__ void pad_ln_kernel(const float* __restrict__ b1, const float* __restrict__ gam,
                              const float* __restrict__ bet) {
    __shared__ float ss[16], ss2[16], stat[2];
    int t = threadIdx.x;           // 512 threads
    float h = tanhf(b1[t]);
    float s = h, s2 = h*h;
    #pragma unroll
    for (int o=16;o;o>>=1) { s += __shfl_xor_sync(~0u,s,o); s2 += __shfl_xor_sync(~0u,s2,o); }
    if ((t & 31) == 0) { ss[t>>5] = s; ss2[t>>5] = s2; }
    __syncthreads();
    if (t == 0) {
        float S=0.f, S2=0.f;
        #pragma unroll
        for (int i=0;i<16;i++) { S += ss[i]; S2 += ss2[i]; }
        float mu = S*(1.f/512.f);
        float var = S2*(1.f/512.f) - mu*mu;
        stat[0] = mu; stat[1] = rsqrtf(var + 1e-5f);
    }
    __syncthreads();
    g_lnpad[t] = (h - stat[0])*stat[1]*gam[t] + bet[t];
}

// ---------------- pad-row k/v: kpad = lnpad @ Wk, vpad = lnpad @ Wv ----------
__global__ void pad_kv_kernel(const float* __restrict__ Wk, const float* __restrict__ Wv) {
    int d = blockIdx.x*256 + threadIdx.x;     // 0..1023
    if (d >= 2*DM) return;
    const float* W = (d < DM) ? Wk : Wv;
    int dd = d & (DM-1);
    float s = 0.f;
    for (int kk = 0; kk < DM; kk++) s += g_lnpad[kk] * W[(size_t)kk*DM + dd];
    if (d < DM) g_kpad[dd] = s; else g_vpad[dd] = s;
}

// ---------------- broadcast pad k/v rows into g_k/g_v ------------------------
__global__ void padfill_kernel() {
    int idx = blockIdx.x*256 + threadIdx.x;
    const int per = (SEQ-NTOK)*(DM/4);        // 140288 per batch
    if (idx >= BSZ*per) return;
    int b = idx / per, r = idx - b*per;
    int t = NTOK + r/(DM/4), c4 = r % (DM/4);
    size_t off = (size_t)(b*SEQ + t)*DM + c4*4;
    *reinterpret_cast<float4*>(g_k + off) = *reinterpret_cast<const float4*>(g_kpad + c4*4);
    *reinterpret_cast<float4*>(g_v + off) = *reinterpret_cast<const float4*>(g_vpad + c4*4);
}

// ---------------- bf16-split tensor-core GEMM (real rows only) ---------------
// M-tile mapping: blockIdx.y -> (batch, t0), rows b*SEQ+t0 .. +127, valid t<NTOK.
__global__ __launch_bounds__(256, 2) void tc_gemm_kernel(
    const bf16* __restrict__ Ah, const bf16* __restrict__ Al,
    const bf16* __restrict__ Bh, const bf16* __restrict__ Bl,
    const float* __restrict__ bias, const float* __restrict__ res,
    float* __restrict__ C, bf16* __restrict__ Chi, bf16* __restrict__ Clo,
    int N, int K, int act)
{
    extern __shared__ __align__(1024) char smc[];
    uint32_t sbase = smem_u32(smc);
    int tid = threadIdx.x;
    int mtile = blockIdx.y;
    int bb = mtile / MTPB, t0 = (mtile - bb*MTPB) << 7;
    int bm = bb*SEQ + t0;
    int alim = NTOK - t0;                 // A rows r < alim are valid
    int rowlim = bm + alim;
    int bn = blockIdx.x << 7;
    int lane = tid & 31, w = tid >> 5;
    int wm = w & 1, wn = w >> 1;
    int grp = lane >> 2, qp = lane & 3;

    uint32_t swz = (lane >> 1) & 3;
    uint32_t a_base = (uint32_t)(wm*64 + (lane & 15))*64 + (((uint32_t)(lane >> 4) ^ swz) << 4);
    uint32_t b_base = (uint32_t)(wn*32 + ((lane >> 4) & 1)*8 + (lane & 7))*64
                    + ((((uint32_t)(lane >> 3) & 1) ^ swz) << 4);

    float acc[4][4][4];
    #pragma unroll
    for (int i=0;i<4;i++)
        #pragma unroll
        for (int j=0;j<4;j++)
            #pragma unroll
            for (int r=0;r<4;r++) acc[i][j][r] = 0.f;

    const int NC = K >> 5;

    #define STAGE_LOAD(c_, buf_) do { \
        int k0 = (c_) << 5; \
        uint32_t sb = sbase + (uint32_t)(buf_)*32768u; \
        _Pragma("unroll") \
        for (int i_ = 0; i_ < 8; i_++) { \
            const int arr_ = i_ >> 1; \
            int j_ = ((i_ & 1) << 8) + tid; \
            int r_ = j_ >> 2, cc_ = j_ & 3; \
            uint32_t dst_ = sb + arr_*8192u + (uint32_t)r_*64u \
                          + ((uint32_t)(cc_ ^ ((r_ >> 1) & 3)) << 4); \
            const bf16* g_; int sz_ = 16; \
            if (arr_ <= 1) { \
                const bf16* base_ = arr_ ? Al : Ah; \
                if (r_ < alim) g_ = base_ + (size_t)(bm + r_)*K + k0 + cc_*8; \
                else { g_ = base_; sz_ = 0; } \
            } else { \
                int rowv_ = bn + r_; \
                const bf16* base_ = (arr_ == 2) ? Bh : Bl; \
                if (rowv_ < N) g_ = base_ + (size_t)rowv_*K + k0 + cc_*8; \
                else { g_ = base_; sz_ = 0; } \
            } \
            CP_ASYNC16(dst_, g_, sz_); \
        } \
        CP_COMMIT(); \
    } while (0)

    STAGE_LOAD(0, 0);
    if (NC > 1) STAGE_LOAD(1, 1);

    int buf = 0, bufn = 2;
    for (int c = 0; c < NC; c++) {
        if (c + 1 < NC) CP_WAIT1(); else CP_WAIT0();
        __syncthreads();
        if (c + 2 < NC) {
            STAGE_LOAD(c + 2, bufn);
            bufn = (bufn == 2) ? 0 : bufn + 1;
        }
        uint32_t sA  = sbase + (uint32_t)buf*32768u;
        uint32_t sAl = sA + 8192u, sB = sA + 16384u, sBl = sA + 24576u;
        buf = (buf == 2) ? 0 : buf + 1;

        #pragma unroll
        for (int ks = 0; ks < 2; ks++) {
            uint32_t kx = ks ? 32u : 0u;
            uint32_t bh[4][2], bl[4][2], a[4][4];
            #pragma unroll
            for (int p = 0; p < 2; p++) {
                LDSM_X4(bh[2*p][0], bh[2*p][1], bh[2*p+1][0], bh[2*p+1][1],
                        sB  + ((b_base + p*1024u) ^ kx));
                LDSM_X4(bl[2*p][0], bl[2*p][1], bl[2*p+1][0], bl[2*p+1][1],
                        sBl + ((b_base + p*1024u) ^ kx));
            }
            #pragma unroll
            for (int mt = 0; mt < 4; mt++)
                LDSM_X4(a[mt][0], a[mt][1], a[mt][2], a[mt][3],
                        sA + ((a_base + mt*1024u) ^ kx));
            #pragma unroll
            for (int mt = 0; mt < 4; mt++)
                #pragma unroll
                for (int nt = 0; nt < 4; nt++) {
                    MMA16816(acc[mt][nt], a[mt][0],a[mt][1],a[mt][2],a[mt][3], bh[nt][0],bh[nt][1]);
                    MMA16816(acc[mt][nt], a[mt][0],a[mt][1],a[mt][2],a[mt][3], bl[nt][0],bl[nt][1]);
                }
            #pragma unroll
            for (int mt = 0; mt < 4; mt++)
                LDSM_X4(a[mt][0], a[mt][1], a[mt][2], a[mt][3],
                        sAl + ((a_base + mt*1024u) ^ kx));
            #pragma unroll
            for (int mt = 0; mt < 4; mt++)
                #pragma unroll
                for (int nt = 0; nt < 4; nt++)
                    MMA16816(acc[mt][nt], a[mt][0],a[mt][1],a[mt][2],a[mt][3], bh[nt][0],bh[nt][1]);
        }
    }
    #undef STAGE_LOAD

    // ---- epilogue (store only valid rows) ----
    #pragma unroll
    for (int mt = 0; mt < 4; mt++) {
        #pragma unroll
        for (int nt = 0; nt < 4; nt++) {
            int c0 = bn + wn*32 + nt*8 + qp*2;
            if (c0 >= N) continue;
            int rbase = bm + wm*64 + mt*16 + grp;
            float bs0 = 0.f, bs1 = 0.f;
            if (bias) { bs0 = bias[c0]; bs1 = bias[c0 + 1]; }
            #pragma unroll
            for (int half = 0; half < 2; half++) {
                int r = rbase + half*8;
                if (r >= rowlim) continue;
                float v0 = acc[mt][nt][half*2 + 0] + bs0;
                float v1 = acc[mt][nt][half*2 + 1] + bs1;
                if (act == 1) { v0 = tanhf(v0); v1 = tanhf(v1); }
                else if (act == 2) {
                    v0 = 0.5f*v0*(1.f + erff(v0*0.7071067811865476f));
                    v1 = 0.5f*v1*(1.f + erff(v1*0.7071067811865476f));
                }
                if (res) {
                    v0 += res[(size_t)r*N + c0];
                    v1 += res[(size_t)r*N + c0 + 1];
                }
                if (Chi) {
                    uint32_t hv, lv;
                    split2(v0, v1, hv, lv);
                    *reinterpret_cast<uint32_t*>(Chi + (size_t)r*N + c0) = hv;
                    *reinterpret_cast<uint32_t*>(Clo + (size_t)r*N + c0) = lv;
                } else {
                    float2 o; o.x = v0; o.y = v1;
                    *reinterpret_cast<float2*>(C + (size_t)r*N + c0) = o;
                }
            }
        }
    }
}

// ---------------- LayerNorm (real rows) -> bf16 hi/lo split ------------------
__global__ void ln_kernel(const float* __restrict__ in, const float* __restrict__ gam,
                          const float* __restrict__ bet) {
    int gw = (blockIdx.x*blockDim.x + threadIdx.x) >> 5;
    int lane = threadIdx.x & 31;
    if (gw >= BSZ*NTOK) return;
    int b = gw / NTOK, t = gw - b*NTOK;
    size_t row = (size_t)(b*SEQ + t);
    const float4* rp = reinterpret_cast<const float4*>(in + row*DM);
    float4 v[4];
    float s=0.f, s2=0.f;
    #pragma unroll
    for (int i=0;i<4;i++) {
        v[i] = rp[lane + 32*i];
        s  += v[i].x+v[i].y+v[i].z+v[i].w;
        s2 += v[i].x*v[i].x + v[i].y*v[i].y + v[i].z*v[i].z + v[i].w*v[i].w;
    }
    #pragma unroll
    for (int o=16;o;o>>=1) { s += __shfl_xor_sync(~0u,s,o); s2 += __shfl_xor_sync(~0u,s2,o); }
    float mu  = s*(1.f/512.f);
    float var = s2*(1.f/512.f) - mu*mu;
    float r = rsqrtf(var + 1e-5f);
    #pragma unroll
    for (int i=0;i<4;i++) {
        int c = (lane + 32*i)*4;
        float4 g4 = *reinterpret_cast<const float4*>(gam + c);
        float4 b4 = *reinterpret_cast<const float4*>(bet + c);
        float o0 = (v[i].x-mu)*r*g4.x + b4.x;
        float o1 = (v[i].y-mu)*r*g4.y + b4.y;
        float o2 = (v[i].z-mu)*r*g4.z + b4.z;
        float o3 = (v[i].w-mu)*r*g4.w + b4.w;
        uint2 hv, lv;
        split2(o0, o1, hv.x, lv.x);
        split2(o2, o3, hv.y, lv.y);
        size_t off = row*DM + c;
        *reinterpret_cast<uint2*>(g_sh + off) = hv;
        *reinterpret_cast<uint2*>(g_sl + off) = lv;
    }
}

// ---------------- local attention, head 0 (real queries only) ---------------
__global__ __launch_bounds__(1024) void local_attn_kernel() {
    __shared__ float tile[64][DH];
    __shared__ float scores[32][64];
    int b   = blockIdx.x / 94;
    int blk = blockIdx.x - b*94;
    int win = blk >> 2;
    int qc  = blk & 3;
    int warp = threadIdx.x >> 5, lane = threadIdx.x & 31;
    int qt = win*128 + qc*32 + warp;
    size_t qoff = (size_t)(b*SEQ + qt)*DM;
    float4 q4 = *reinterpret_cast<const float4*>(g_q + qoff + lane*4);
    float m = -1e30f, l = 0.f;
    float4 acc = make_float4(0.f,0.f,0.f,0.f);
    int kbase = win*128 - 128;
    for (int ch=0; ch<6; ch++) {
        int t0 = kbase + ch*64;
        __syncthreads();
        #pragma unroll
        for (int it=0; it<2; it++) {
            int idx = it*1024 + threadIdx.x;
            int r = idx >> 5, c4 = idx & 31;
            int t = t0 + r;
            float4 kv = make_float4(0.f,0.f,0.f,0.f);
            if (t >= 0 && t < SEQ)
                kv = *reinterpret_cast<const float4*>(g_k + (size_t)(b*SEQ+t)*DM + c4*4);
            *reinterpret_cast<float4*>(&tile[r][c4*4]) = kv;
        }
        __syncthreads();
        for (int j=0; j<64; j++) {
            float4 kv = *reinterpret_cast<const float4*>(&tile[j][lane*4]);
            float s = q4.x*kv.x + q4.y*kv.y + q4.z*kv.z + q4.w*kv.w;
            #pragma unroll
            for (int o=16;o;o>>=1) s += __shfl_xor_sync(~0u,s,o);
            if (lane == (j & 31)) {
                int t = t0 + j;
                scores[warp][j] = (t >= 0 && t < SEQ) ? s*SCALE : -1e38f;
            }
        }
        __syncthreads();
        #pragma unroll
        for (int it=0; it<2; it++) {
            int idx = it*1024 + threadIdx.x;
            int r = idx >> 5, c4 = idx & 31;
            int t = t0 + r;
            float4 vv = make_float4(0.f,0.f,0.f,0.f);
            if (t >= 0 && t < SEQ)
                vv = *reinterpret_cast<const float4*>(g_v + (size_t)(b*SEQ+t)*DM + c4*4);
            *reinterpret_cast<float4*>(&tile[r][c4*4]) = vv;
        }
        __syncthreads();
        float cm = fmaxf(scores[warp][lane], scores[warp][lane+32]);
        #pragma unroll
        for (int o=16;o;o>>=1) cm = fmaxf(cm, __shfl_xor_sync(~0u,cm,o));
        float mn = fmaxf(m, cm);
        float corr = expf(m - mn);
        l *= corr; acc.x*=corr; acc.y*=corr; acc.z*=corr; acc.w*=corr;
        for (int j=0; j<64; j++) {
            float p = expf(scores[warp][j] - mn);
            l += p;
            float4 vv = *reinterpret_cast<const float4*>(&tile[j][lane*4]);
            acc.x = fmaf(p, vv.x, acc.x);
            acc.y = fmaf(p, vv.y, acc.y);
            acc.z = fmaf(p, vv.z, acc.z);
            acc.w = fmaf(p, vv.w, acc.w);
        }
        m = mn;
    }
    float inv = 1.f/l;
    uint2 hv, lv;
    split2(acc.x*inv, acc.y*inv, hv.x, lv.x);
    split2(acc.z*inv, acc.w*inv, hv.y, lv.y);
    *reinterpret_cast<uint2*>(g_sh + qoff + lane*4) = hv;
    *reinterpret_cast<uint2*>(g_sl + qoff + lane*4) = lv;
}

// ---------------- k column softmax stats (heads 1..3) -----------------------
__global__ void kstats_kernel() {
    int bh = blockIdx.x;
    int b = bh/3, hh = bh%3 + 1;
    int d = blockIdx.y*32 + threadIdx.x;
    int ty = threadIdx.y;
    int col = hh*DH + d;
    float m = -1e30f, l = 0.f;
    for (int t = ty; t < SEQ; t += 8) {
        float val = g_k[(size_t)(b*SEQ+t)*DM + col];
        if (val > m) { l = l*expf(m - val) + 1.f; m = val; }
        else l += expf(val - m);
    }
    __shared__ float sm[8][32], sl[8][32];
    sm[ty][threadIdx.x] = m; sl[ty][threadIdx.x] = l;
    __syncthreads();
    if (ty == 0) {
        #pragma unroll
        for (int r=1;r<8;r++) {
            float m2 = sm[r][threadIdx.x], l2 = sl[r][threadIdx.x];
            float M = fmaxf(m, m2);
            l = l*expf(m - M) + l2*expf(m2 - M);
            m = M;
        }
        g_kmax[bh*DH + d] = m;
        g_klse[bh*DH + d] = l;
    }
}

// ---------------- ctx partial: ctx[d][e] = sum_t k'[t,d] v[t,e] (K-split 8) --
__global__ __launch_bounds__(256) void ctx_partial_kernel() {
    __shared__ float kt[32][132];
    __shared__ float vt[32][132];
    __shared__ float smax[DH], sinv[DH];
    int bh = blockIdx.x, ks = blockIdx.y;
    int b = bh/3, hh = bh%3 + 1;
    if (threadIdx.x < DH) {
        smax[threadIdx.x] = g_kmax[bh*DH + threadIdx.x];
        sinv[threadIdx.x] = 1.f/g_klse[bh*DH + threadIdx.x];
    }
    int tx = threadIdx.x & 15, ty = threadIdx.x >> 4;
    float acc[8][8];
    #pragma unroll
    for (int i=0;i<8;i++)
        #pragma unroll
        for (int j=0;j<8;j++) acc[i][j]=0.f;

    for (int t0=0; t0<512; t0+=32) {
        __syncthreads();
        #pragma unroll
        for (int i=0;i<4;i++) {
            int idx = i*256 + threadIdx.x;
            int r = idx >> 5, c4 = idx & 31;
            int t = ks*512 + t0 + r;
            size_t off = (size_t)(b*SEQ+t)*DM + hh*DH + c4*4;
            float4 kv = *reinterpret_cast<const float4*>(g_k + off);
            float4 vv = *reinterpret_cast<const float4*>(g_v + off);
            int d0 = c4*4;
            kt[r][d0+0] = expf(kv.x - smax[d0+0])*sinv[d0+0];
            kt[r][d0+1] = expf(kv.y - smax[d0+1])*sinv[d0+1];
            kt[r][d0+2] = expf(kv.z - smax[d0+2])*sinv[d0+2];
            kt[r][d0+3] = expf(kv.w - smax[d0+3])*sinv[d0+3];
            *reinterpret_cast<float4*>(&vt[r][d0]) = vv;
        }
        __syncthreads();
        #pragma unroll
        for (int kk=0; kk<32; kk++) {
            float a[8], bb[8];
            *reinterpret_cast<float4*>(&a[0])  = *reinterpret_cast<const float4*>(&kt[kk][ty*8]);
            *reinterpret_cast<float4*>(&a[4])  = *reinterpret_cast<const float4*>(&kt[kk][ty*8+4]);
            *reinterpret_cast<float4*>(&bb[0]) = *reinterpret_cast<const float4*>(&vt[kk][tx*8]);
            *reinterpret_cast<float4*>(&bb[4]) = *reinterpret_cast<const float4*>(&vt[kk][tx*8+4]);
            #pragma unroll
            for (int i=0;i<8;i++)
                #pragma unroll
                for (int j=0;j<8;j++)
                    acc[i][j] = fmaf(a[i], bb[j], acc[i][j]);
        }
    }
    float* op = g_ctxp + ((size_t)bh*8 + ks)*DH*DH;
    #pragma unroll
    for (int i=0;i<8;i++)
        #pragma unroll
        for (int j=0;j<8;j+=4) {
            float4 o4 = make_float4(acc[i][j],acc[i][j+1],acc[i][j+2],acc[i][j+3]);
            *reinterpret_cast<float4*>(op + (size_t)(ty*8+i)*DH + tx*8 + j) = o4;
        }
}

__global__ void ctx_reduce_kernel() {
    int idx = blockIdx.x*256 + threadIdx.x;
    if (idx >= BSZ*3*DH*DH) return;
    int bh = idx / (DH*DH);
    int de = idx - bh*DH*DH;
    float s = 0.f;
    #pragma unroll
    for (int ks=0;ks<8;ks++) s += g_ctxp[((size_t)bh*8+ks)*DH*DH + de];
    g_ctx[idx] = s;
}

// ---------------- linear-attn output -> split bf16 directly ------------------
__global__ __launch_bounds__(256) void lin_out_kernel() {
    __shared__ float sctx[64][DH];
    int bh = blockIdx.x;
    int b = bh/3, hh = bh%3 + 1;
    int warp = threadIdx.x >> 5, lane = threadIdx.x & 31;
    const float* ctxp = g_ctx + (size_t)bh*DH*DH;
    float pr[4][4], o[4][4];
    int tbase = blockIdx.y*32 + warp*4;
    #pragma unroll
    for (int tt=0;tt<4;tt++) {
        int t = tbase + tt;
        const float* qp = g_q + (size_t)(b*SEQ+t)*DM + hh*DH;
        float4 q4 = *reinterpret_cast<const float4*>(qp + lane*4);
        float mx = fmaxf(fmaxf(q4.x,q4.y),fmaxf(q4.z,q4.w));
        #pragma unroll
        for (int s=16;s;s>>=1) mx = fmaxf(mx, __shfl_xor_sync(~0u,mx,s));
        float e0=expf(q4.x-mx), e1=expf(q4.y-mx), e2=expf(q4.z-mx), e3=expf(q4.w-mx);
        float sm = e0+e1+e2+e3;
        #pragma unroll
        for (int s=16;s;s>>=1) sm += __shfl_xor_sync(~0u,sm,s);
        float inv = SCALE/sm;
        pr[tt][0]=e0*inv; pr[tt][1]=e1*inv; pr[tt][2]=e2*inv; pr[tt][3]=e3*inv;
        o[tt][0]=0.f; o[tt][1]=0.f; o[tt][2]=0.f; o[tt][3]=0.f;
    }
    for (int ph=0; ph<2; ph++) {
        __syncthreads();
        #pragma unroll
        for (int i=0;i<8;i++) {
            int idx = i*256 + threadIdx.x;
            int r = idx >> 5, c4 = idx & 31;
            *reinterpret_cast<float4*>(&sctx[r][c4*4]) =
                *reinterpret_cast<const float4*>(ctxp + (size_t)(ph*64+r)*DH + c4*4);
        }
        __syncthreads();
        #pragma unroll
        for (int dl=0; dl<16; dl++) {
            int src = ph*16 + dl;
            #pragma unroll
            for (int tt=0;tt<4;tt++) {
                float b0 = __shfl_sync(~0u, pr[tt][0], src);
                float b1 = __shfl_sync(~0u, pr[tt][1], src);
                float b2 = __shfl_sync(~0u, pr[tt][2], src);
                float b3 = __shfl_sync(~0u, pr[tt][3], src);
                float4 c0 = *reinterpret_cast<const float4*>(&sctx[dl*4+0][lane*4]);
                float4 c1 = *reinterpret_cast<const float4*>(&sctx[dl*4+1][lane*4]);
                float4 c2 = *reinterpret_cast<const float4*>(&sctx[dl*4+2][lane*4]);
                float4 c3 = *reinterpret_cast<const float4*>(&sctx[dl*4+3][lane*4]);
                o[tt][0] += b0*c0.x + b1*c1.x + b2*c2.x + b3*c3.x;
                o[tt][1] += b0*c0.y + b1*c1.y + b2*c2.y + b3*c3.y;
                o[tt][2] += b0*c0.z + b1*c1.z + b2*c2.z + b3*c3.z;
                o[tt][3] += b0*c0.w + b1*c1.w + b2*c2.w + b3*c3.w;
            }
        }
    }
    #pragma unroll
    for (int tt=0;tt<4;tt++) {
        int t = tbase + tt;
        size_t off = (size_t)(b*SEQ+t)*DM + hh*DH + lane*4;
        uint2 hv, lv;
        split2(o[tt][0], o[tt][1], hv.x, lv.x);
        split2(o[tt][2], o[tt][3], hv.y, lv.y);
        *reinterpret_cast<uint2*>(g_sh + off) = hv;
        *reinterpret_cast<uint2*>(g_sl + off) = lv;
    }
}

// ---------------- final slice (drop padded rows) -----------------------------
__global__ void slice_kernel(float* __restrict__ out) {
    int idx = blockIdx.x*256 + threadIdx.x;
    const int total = BSZ*NTOK*(DOUT/4);
    if (idx >= total) return;
    int row = idx >> 4;
    int c4  = idx & 15;
    int b = row / NTOK, t = row - b*NTOK;
    reinterpret_cast<float4*>(out)[idx] =
        reinterpret_cast<const float4*>(g_of)[(size_t)(b*SEQ+t)*16 + c4];
}

// ---------------- host ---------------------------------------------------
static inline void tc_gemm(const bf16* Ah, const bf16* Al, const bf16* Bh, const bf16* Bl,
                           const float* bias, const float* res,
                           float* C, bf16* Chi, bf16* Clo,
                           int N, int K, int act) {
    dim3 grid((N + 127) / 128, BSZ*MTPB);
    tc_gemm_kernel<<<grid, 256, GEMM_SMEM>>>(Ah, Al, Bh, Bl, bias, res, C, Chi, Clo,
                                             N, K, act);
}

extern "C" void kernel_launch(void* const* d_in, const int* in_sizes, int n_in,
                              void* d_out, int out_size) {
    const float* x    = (const float*)d_in[0];
    const float* W1   = (const float*)d_in[1];
    const float* b1   = (const float*)d_in[2];
    const float* ln1g = (const float*)d_in[3];
    const float* ln1b = (const float*)d_in[4];
    const float* Wq   = (const float*)d_in[5];
    const float* Wk   = (const float*)d_in[6];
    const float* Wv   = (const float*)d_in[7];
    const float* Wo   = (const float*)d_in[8];
    const float* bo   = (const float*)d_in[9];
    const float* ln2g = (const float*)d_in[10];
    const float* ln2b = (const float*)d_in[11];
    const float* Wf1  = (const float*)d_in[12];
    const float* bf1  = (const float*)d_in[13];
    const float* Wf2  = (const float*)d_in[14];
    const float* bf2  = (const float*)d_in[15];
    const float* W2   = (const float*)d_in[16];
    const float* b2   = (const float*)d_in[17];
    float* out = (float*)d_out;

    static int smem_set = 0;
    if (!smem_set) {
        cudaFuncSetAttribute(tc_gemm_kernel, cudaFuncAttributeMaxDynamicSharedMemorySize, GEMM_SMEM);
        smem_set = 1;
    }

    float *h,*q,*k,*v,*of;
    bf16 *sh,*sl,*s2h,*s2l;
    bf16 *w1h,*w1l,*wqh,*wql,*wkh,*wkl,*wvh,*wvl,*woh,*wol,*wf1h,*wf1l,*wf2h,*wf2l,*w2h,*w2l;
    cudaGetSymbolAddress((void**)&h,    g_h);
    cudaGetSymbolAddress((void**)&q,    g_q);
    cudaGetSymbolAddress((void**)&k,    g_k);
    cudaGetSymbolAddress((void**)&v,    g_v);
    cudaGetSymbolAddress((void**)&of,   g_of);
    cudaGetSymbolAddress((void**)&sh,   g_sh);
    cudaGetSymbolAddress((void**)&sl,   g_sl);
    cudaGetSymbolAddress((void**)&s2h,  g_s2h);
    cudaGetSymbolAddress((void**)&s2l,  g_s2l);
    cudaGetSymbolAddress((void**)&w1h,  g_w1h);   cudaGetSymbolAddress((void**)&w1l,  g_w1l);
    cudaGetSymbolAddress((void**)&wqh,  g_wqh);   cudaGetSymbolAddress((void**)&wql,  g_wql);
    cudaGetSymbolAddress((void**)&wkh,  g_wkh);   cudaGetSymbolAddress((void**)&wkl,  g_wkl);
    cudaGetSymbolAddress((void**)&wvh,  g_wvh);   cudaGetSymbolAddress((void**)&wvl,  g_wvl);
    cudaGetSymbolAddress((void**)&woh,  g_woh);   cudaGetSymbolAddress((void**)&wol,  g_wol);
    cudaGetSymbolAddress((void**)&wf1h, g_wf1h);  cudaGetSymbolAddress((void**)&wf1l, g_wf1l);
    cudaGetSymbolAddress((void**)&wf2h, g_wf2h);  cudaGetSymbolAddress((void**)&wf2l, g_wf2l);
    cudaGetSymbolAddress((void**)&w2h,  g_w2h);   cudaGetSymbolAddress((void**)&w2l,  g_w2l);

    // weight transposes + bf16 splits ([K,N] -> [N,K] hi/lo)
    dim3 tb(32, 8);
    transpose_split_kernel<<<dim3(DM/32,  DIN/32), tb>>>(W1,  w1h,  w1l,  DIN, DM);
    transpose_split_kernel<<<dim3(DM/32,  DM/32),  tb>>>(Wq,  wqh,  wql,  DM,  DM);
    transpose_split_kernel<<<dim3(DM/32,  DM/32),  tb>>>(Wk,  wkh,  wkl,  DM,  DM);
    transpose_split_kernel<<<dim3(DM/32,  DM/32),  tb>>>(Wv,  wvh,  wvl,  DM,  DM);
    transpose_split_kernel<<<dim3(DM/32,  DM/32),  tb>>>(Wo,  woh,  wol,  DM,  DM);
    transpose_split_kernel<<<dim3(DFF/32, DM/32),  tb>>>(Wf1, wf1h, wf1l, DM,  DFF);
    transpose_split_kernel<<<dim3(DM/32,  DFF/32), tb>>>(Wf2, wf2h, wf2l, DFF, DM);
    transpose_split_kernel<<<dim3(DOUT/32,DM/32),  tb>>>(W2,  w2h,  w2l,  DM,  DOUT);

    // 1. split x (real rows only)
    pad_split_kernel<<<(BSZ*NTOK*(DIN/4) + 255)/256, 256>>>(x);
    // 2. h = tanh(x @ W1 + b1)  (real rows)
    tc_gemm(sh, sl, w1h, w1l, b1, nullptr, h, nullptr, nullptr, DM, DIN, 1);
    // 3. ln1 -> split s (real rows); pad-row ln vector
    ln_kernel<<<BSZ*NTOK/8, 256>>>(h, ln1g, ln1b);
    pad_ln_kernel<<<1, 512>>>(b1, ln1g, ln1b);
    // 4. q,k,v (real rows) + pad k/v rows
    tc_gemm(sh, sl, wqh, wql, nullptr, nullptr, q, nullptr, nullptr, DM, DM, 0);
    tc_gemm(sh, sl, wkh, wkl, nullptr, nullptr, k, nullptr, nullptr, DM, DM, 0);
    tc_gemm(sh, sl, wvh, wvl, nullptr, nullptr, v, nullptr, nullptr, DM, DM, 0);
    pad_kv_kernel<<<4, 256>>>(Wk, Wv);
    padfill_kernel<<<(BSZ*(SEQ-NTOK)*(DM/4) + 255)/256, 256>>>();
    // 5. local attention (head 0, real queries) -> split into s
    local_attn_kernel<<<BSZ*94, 1024>>>();
    // 6. linear attention (heads 1..3, real queries) -> split into s
    kstats_kernel<<<dim3(BSZ*3,4), dim3(32,8)>>>();
    ctx_partial_kernel<<<dim3(BSZ*3,8), 256>>>();
    ctx_reduce_kernel<<<(BSZ*3*DH*DH + 255)/256, 256>>>();
    lin_out_kernel<<<dim3(BSZ*3, 94), 256>>>();
    // 7. h = h + attn @ Wo + bo (real rows)
    tc_gemm(sh, sl, woh, wol, bo, h, h, nullptr, nullptr, DM, DM, 0);
    // 8. ln2 -> split s (real rows)
    ln_kernel<<<BSZ*NTOK/8, 256>>>(h, ln2g, ln2b);
    // 9. ff = gelu(ln2 @ Wf1 + bf1) -> split s2
    tc_gemm(sh, sl, wf1h, wf1l, bf1, nullptr, nullptr, s2h, s2l, DFF, DM, 2);
    // 10. hn = h + ff @ Wf2 + bf2 -> split s
    tc_gemm(s2h, s2l, wf2h, wf2l, bf2, h, nullptr, sh, sl, DM, DFF, 0);
    // 11. of = hn @ W2 + b2 (real rows)
    tc_gemm(sh, sl, w2h, w2l, b2, nullptr, of, nullptr, nullptr, DOUT, DM, 0);
    // 12. slice
    slice_kernel<<<(BSZ*NTOK*(DOUT/4) + 255)/256, 256>>>(out);
}

// round 7
// speedup vs baseline: 3.3874x; 1.2677x over previous
#include <cuda_runtime.h>
#include <cuda_fp16.h>
#include <math.h>
#include <stdint.h>

#define BSZ   8
#define SEQ   4096
#define NTOK  3000
#define DIN   128
#define DM    512
#define DFF   2048
#define DOUT  64
#define DH    128
#define MTOT  (BSZ*SEQ)
#define MTPB  24                     // M-tiles per batch: ceil(3000/128)
#define SCALE 0.08838834764831845f   // 1/sqrt(128)
#define GEMM_SMEM (3*24576)          // 3 stages x 3 arrays x 128 x 64B (swizzled)

typedef __half fp16;

// ---------------- scratch (static device globals: no allocation) -------------
__device__ float g_h[MTOT*DM];
__device__ float g_q[MTOT*DM];
__device__ float g_k[MTOT*DM];
__device__ float g_v[MTOT*DM];
__device__ float g_of[MTOT*DOUT];
__device__ float g_kmax[BSZ*3*DH];
__device__ float g_klse[BSZ*3*DH];
__device__ float g_ctxp[BSZ*3*8*DH*DH];
__device__ float g_ctx[BSZ*3*DH*DH];
__device__ float g_lnpad[DM];
__device__ float g_kpad[DM];
__device__ float g_vpad[DM];
// fp16 split activation buffers (hi/lo)
__device__ fp16 g_sh[MTOT*DM];
__device__ fp16 g_sl[MTOT*DM];
__device__ fp16 g_s2h[MTOT*DFF];
__device__ fp16 g_s2l[MTOT*DFF];
// transposed weights [N][K], single fp16
__device__ fp16 g_w1h[DM*DIN];
__device__ fp16 g_wqh[DM*DM];
__device__ fp16 g_wkh[DM*DM];
__device__ fp16 g_wvh[DM*DM];
__device__ fp16 g_woh[DM*DM];
__device__ fp16 g_wf1h[DFF*DM];
__device__ fp16 g_wf2h[DM*DFF];
__device__ fp16 g_w2h[DOUT*DM];

// ---------------- helpers ----------------
__device__ __forceinline__ uint32_t smem_u32(const void* p) {
    uint32_t a;
    asm("{ .reg .u64 t; cvta.to.shared.u64 t, %1; cvt.u32.u64 %0, t; }" : "=r"(a) : "l"(p));
    return a;
}
__device__ __forceinline__ void split2h(float x, float y, uint32_t& hi, uint32_t& lo) {
    __half2 h = __floats2half2_rn(x, y);
    __half2 l = __floats2half2_rn(x - __low2float(h), y - __high2float(h));
    hi = *reinterpret_cast<uint32_t*>(&h);
    lo = *reinterpret_cast<uint32_t*>(&l);
}

#define LDSM_X4(r0,r1,r2,r3,addr) \
    asm volatile("ldmatrix.sync.aligned.m8n8.x4.shared.b16 {%0,%1,%2,%3}, [%4];" \
        : "=r"(r0),"=r"(r1),"=r"(r2),"=r"(r3) : "r"(addr))
#define MMA16816(d, a0,a1,a2,a3, b0,b1) \
    asm volatile("mma.sync.aligned.m16n8k16.row.col.f32.f16.f16.f32 " \
        "{%0,%1,%2,%3},{%4,%5,%6,%7},{%8,%9},{%0,%1,%2,%3};" \
        : "+f"((d)[0]),"+f"((d)[1]),"+f"((d)[2]),"+f"((d)[3]) \
        : "r"(a0),"r"(a1),"r"(a2),"r"(a3),"r"(b0),"r"(b1))
#define CP_ASYNC16(dst, src, sz) \
    asm volatile("cp.async.cg.shared.global [%0], [%1], 16, %2;" :: "r"(dst), "l"(src), "r"(sz))
#define CP_COMMIT()  asm volatile("cp.async.commit_group;" ::: "memory")
#define CP_WAIT0()   asm volatile("cp.async.wait_group 0;" ::: "memory")
#define CP_WAIT1()   asm volatile("cp.async.wait_group 1;" ::: "memory")

// ---------------- weight transpose + fp16: T[n][k] = h(W[k][n]) --------------
__global__ void transpose_h_kernel(const float* __restrict__ W,
                                   fp16* __restrict__ Th, int K, int N) {
    __shared__ float t[32][33];
    int bx = blockIdx.x * 32, by = blockIdx.y * 32;
    int x = bx + threadIdx.x;
    #pragma unroll
    for (int i = 0; i < 32; i += 8) {
        int y = by + threadIdx.y + i;
        if (x < N && y < K) t[threadIdx.y + i][threadIdx.x] = W[(size_t)y * N + x];
    }
    __syncthreads();
    int xk = by + threadIdx.x;
    #pragma unroll
    for (int i = 0; i < 32; i += 8) {
        int yn = bx + threadIdx.y + i;
        if (xk < K && yn < N)
            Th[(size_t)yn * K + xk] = __float2half_rn(t[threadIdx.x][threadIdx.y + i]);
    }
}

// ---------------- split x (real rows only) -> g_sh/g_sl ----------------------
__global__ void pad_split_kernel(const float* __restrict__ x) {
    int idx = blockIdx.x*256 + threadIdx.x;
    const int total = BSZ*NTOK*(DIN/4);
    if (idx >= total) return;
    int rr = idx >> 5;
    int c4 = idx & 31;
    int b = rr / NTOK, t = rr - b*NTOK;
    float4 val = reinterpret_cast<const float4*>(x)[(size_t)rr*32 + c4];
    uint2 hv, lv;
    split2h(val.x, val.y, hv.x, lv.x);
    split2h(val.z, val.w, hv.y, lv.y);
    size_t off = ((size_t)(b*SEQ + t)*DIN + c4*4);
    *reinterpret_cast<uint2*>(g_sh + off) = hv;
    *reinterpret_cast<uint2*>(g_sl + off) = lv;
}

// ---------------- pad-row LN: lnpad = LN(tanh(b1)) ---------------------------
__global__ void pad_ln_kernel(const float* __restrict__ b1, const float* __restrict__ gam,
                              const float* __restrict__ bet) {
    __shared__ float ss[16], ss2[16], stat[2];
    int t = threadIdx.x;
    float h = tanhf(b1[t]);
    float s = h, s2 = h*h;
    #pragma unroll
    for (int o=16;o;o>>=1) { s += __shfl_xor_sync(~0u,s,o); s2 += __shfl_xor_sync(~0u,s2,o); }
    if ((t & 31) == 0) { ss[t>>5] = s; ss2[t>>5] = s2; }
    __syncthreads();
    if (t == 0) {
        float S=0.f, S2=0.f;
        #pragma unroll
        for (int i=0;i<16;i++) { S += ss[i]; S2 += ss2[i]; }
        float mu = S*(1.f/512.f);
        float var = S2*(1.f/512.f) - mu*mu;
        stat[0] = mu; stat[1] = rsqrtf(var + 1e-5f);
    }
    __syncthreads();
    g_lnpad[t] = (h - stat[0])*stat[1]*gam[t] + bet[t];
}

// ---------------- pad-row k/v ------------------------------------------------
__global__ void pad_kv_kernel(const float* __restrict__ Wk, const float* __restrict__ Wv) {
    int d = blockIdx.x*256 + threadIdx.x;
    if (d >= 2*DM) return;
    const float* W = (d < DM) ? Wk : Wv;
    int dd = d & (DM-1);
    float s = 0.f;
    for (int kk = 0; kk < DM; kk++) s += g_lnpad[kk] * W[(size_t)kk*DM + dd];
    if (d < DM) g_kpad[dd] = s; else g_vpad[dd] = s;
}

// ---------------- broadcast pad k/v rows -------------------------------------
__global__ void padfill_kernel() {
    int idx = blockIdx.x*256 + threadIdx.x;
    const int per = (SEQ-NTOK)*(DM/4);
    if (idx >= BSZ*per) return;
    int b = idx / per, r = idx - b*per;
    int t = NTOK + r/(DM/4), c4 = r % (DM/4);
    size_t off = (size_t)(b*SEQ + t)*DM + c4*4;
    *reinterpret_cast<float4*>(g_k + off) = *reinterpret_cast<const float4*>(g_kpad + c4*4);
    *reinterpret_cast<float4*>(g_v + off) = *reinterpret_cast<const float4*>(g_vpad + c4*4);
}

// ---------------- fp16 2-product tensor-core GEMM (real rows only) -----------
// C = act((Ah+Al) @ B^T + bias) + res. A hi/lo fp16, B single fp16 [N][K].
__global__ __launch_bounds__(256, 2) void tc_gemm_kernel(
    const fp16* __restrict__ Ah, const fp16* __restrict__ Al,
    const fp16* __restrict__ B,
    const float* __restrict__ bias, const float* __restrict__ res,
    float* __restrict__ C, fp16* __restrict__ Chi, fp16* __restrict__ Clo,
    int N, int K, int act)
{
    extern __shared__ __align__(1024) char smc[];
    uint32_t sbase = smem_u32(smc);
    int tid = threadIdx.x;
    int mtile = blockIdx.y;
    int bb = mtile / MTPB, t0 = (mtile - bb*MTPB) << 7;
    int bm = bb*SEQ + t0;
    int alim = NTOK - t0;
    int rowlim = bm + alim;
    int bn = blockIdx.x << 7;
    int lane = tid & 31, w = tid >> 5;
    int wm = w & 1, wn = w >> 1;
    int grp = lane >> 2, qp = lane & 3;

    uint32_t swz = (lane >> 1) & 3;
    uint32_t a_base = (uint32_t)(wm*64 + (lane & 15))*64 + (((uint32_t)(lane >> 4) ^ swz) << 4);
    uint32_t b_base = (uint32_t)(wn*32 + ((lane >> 4) & 1)*8 + (lane & 7))*64
                    + ((((uint32_t)(lane >> 3) & 1) ^ swz) << 4);

    float acc[4][4][4];
    #pragma unroll
    for (int i=0;i<4;i++)
        #pragma unroll
        for (int j=0;j<4;j++)
            #pragma unroll
            for (int r=0;r<4;r++) acc[i][j][r] = 0.f;

    const int NC = K >> 5;

    #define STAGE_LOAD(c_, buf_) do { \
        int k0 = (c_) << 5; \
        uint32_t sb = sbase + (uint32_t)(buf_)*24576u; \
        _Pragma("unroll") \
        for (int i_ = 0; i_ < 6; i_++) { \
            const int arr_ = i_ >> 1; \
            int j_ = ((i_ & 1) << 8) + tid; \
            int r_ = j_ >> 2, cc_ = j_ & 3; \
            uint32_t dst_ = sb + arr_*8192u + (uint32_t)r_*64u \
                          + ((uint32_t)(cc_ ^ ((r_ >> 1) & 3)) << 4); \
            const fp16* g_; int sz_ = 16; \
            if (arr_ <= 1) { \
                const fp16* base_ = arr_ ? Al : Ah; \
                if (r_ < alim) g_ = base_ + (size_t)(bm + r_)*K + k0 + cc_*8; \
                else { g_ = base_; sz_ = 0; } \
            } else { \
                int rowv_ = bn + r_; \
                if (rowv_ < N) g_ = B + (size_t)rowv_*K + k0 + cc_*8; \
                else { g_ = B; sz_ = 0; } \
            } \
            CP_ASYNC16(dst_, g_, sz_); \
        } \
        CP_COMMIT(); \
    } while (0)

    STAGE_LOAD(0, 0);
    if (NC > 1) STAGE_LOAD(1, 1);

    int buf = 0, bufn = 2;
    for (int c = 0; c < NC; c++) {
        if (c + 1 < NC) CP_WAIT1(); else CP_WAIT0();
        __syncthreads();
        if (c + 2 < NC) {
            STAGE_LOAD(c + 2, bufn);
            bufn = (bufn == 2) ? 0 : bufn + 1;
        }
        uint32_t sA  = sbase + (uint32_t)buf*24576u;
        uint32_t sAl = sA + 8192u, sB = sA + 16384u;
        buf = (buf == 2) ? 0 : buf + 1;

        #pragma unroll
        for (int ks = 0; ks < 2; ks++) {
            uint32_t kx = ks ? 32u : 0u;
            uint32_t bh[4][2], a[4][4];
            #pragma unroll
            for (int p = 0; p < 2; p++)
                LDSM_X4(bh[2*p][0], bh[2*p][1], bh[2*p+1][0], bh[2*p+1][1],
                        sB + ((b_base + p*1024u) ^ kx));
            #pragma unroll
            for (int mt = 0; mt < 4; mt++)
                LDSM_X4(a[mt][0], a[mt][1], a[mt][2], a[mt][3],
                        sA + ((a_base + mt*1024u) ^ kx));
            #pragma unroll
            for (int mt = 0; mt < 4; mt++)
                #pragma unroll
                for (int nt = 0; nt < 4; nt++)
                    MMA16816(acc[mt][nt], a[mt][0],a[mt][1],a[mt][2],a[mt][3], bh[nt][0],bh[nt][1]);
            #pragma unroll
            for (int mt = 0; mt < 4; mt++)
                LDSM_X4(a[mt][0], a[mt][1], a[mt][2], a[mt][3],
                        sAl + ((a_base + mt*1024u) ^ kx));
            #pragma unroll
            for (int mt = 0; mt < 4; mt++)
                #pragma unroll
                for (int nt = 0; nt < 4; nt++)
                    MMA16816(acc[mt][nt], a[mt][0],a[mt][1],a[mt][2],a[mt][3], bh[nt][0],bh[nt][1]);
        }
    }
    #undef STAGE_LOAD

    // ---- epilogue (valid rows only) ----
    #pragma unroll
    for (int mt = 0; mt < 4; mt++) {
        #pragma unroll
        for (int nt = 0; nt < 4; nt++) {
            int c0 = bn + wn*32 + nt*8 + qp*2;
            if (c0 >= N) continue;
            int rbase = bm + wm*64 + mt*16 + grp;
            float bs0 = 0.f, bs1 = 0.f;
            if (bias) { bs0 = bias[c0]; bs1 = bias[c0 + 1]; }
            #pragma unroll
            for (int half = 0; half < 2; half++) {
                int r = rbase + half*8;
                if (r >= rowlim) continue;
                float v0 = acc[mt][nt][half*2 + 0] + bs0;
                float v1 = acc[mt][nt][half*2 + 1] + bs1;
                if (act == 1) { v0 = tanhf(v0); v1 = tanhf(v1); }
                else if (act == 2) {
                    v0 = 0.5f*v0*(1.f + erff(v0*0.7071067811865476f));
                    v1 = 0.5f*v1*(1.f + erff(v1*0.7071067811865476f));
                }
                if (res) {
                    v0 += res[(size_t)r*N + c0];
                    v1 += res[(size_t)r*N + c0 + 1];
                }
                if (Chi) {
                    uint32_t hv, lv;
                    split2h(v0, v1, hv, lv);
                    *reinterpret_cast<uint32_t*>(Chi + (size_t)r*N + c0) = hv;
                    *reinterpret_cast<uint32_t*>(Clo + (size_t)r*N + c0) = lv;
                } else {
                    float2 o; o.x = v0; o.y = v1;
                    *reinterpret_cast<float2*>(C + (size_t)r*N + c0) = o;
                }
            }
        }
    }
}

// ---------------- LayerNorm (real rows) -> fp16 hi/lo split ------------------
__global__ void ln_kernel(const float* __restrict__ in, const float* __restrict__ gam,
                          const float* __restrict__ bet) {
    int gw = (blockIdx.x*blockDim.x + threadIdx.x) >> 5;
    int lane = threadIdx.x & 31;
    if (gw >= BSZ*NTOK) return;
    int b = gw / NTOK, t = gw - b*NTOK;
    size_t row = (size_t)(b*SEQ + t);
    const float4* rp = reinterpret_cast<const float4*>(in + row*DM);
    float4 v[4];
    float s=0.f, s2=0.f;
    #pragma unroll
    for (int i=0;i<4;i++) {
        v[i] = rp[lane + 32*i];
        s  += v[i].x+v[i].y+v[i].z+v[i].w;
        s2 += v[i].x*v[i].x + v[i].y*v[i].y + v[i].z*v[i].z + v[i].w*v[i].w;
    }
    #pragma unroll
    for (int o=16;o;o>>=1) { s += __shfl_xor_sync(~0u,s,o); s2 += __shfl_xor_sync(~0u,s2,o); }
    float mu  = s*(1.f/512.f);
    float var = s2*(1.f/512.f) - mu*mu;
    float r = rsqrtf(var + 1e-5f);
    #pragma unroll
    for (int i=0;i<4;i++) {
        int c = (lane + 32*i)*4;
        float4 g4 = *reinterpret_cast<const float4*>(gam + c);
        float4 b4 = *reinterpret_cast<const float4*>(bet + c);
        float o0 = (v[i].x-mu)*r*g4.x + b4.x;
        float o1 = (v[i].y-mu)*r*g4.y + b4.y;
        float o2 = (v[i].z-mu)*r*g4.z + b4.z;
        float o3 = (v[i].w-mu)*r*g4.w + b4.w;
        uint2 hv, lv;
        split2h(o0, o1, hv.x, lv.x);
        split2h(o2, o3, hv.y, lv.y);
        size_t off = row*DM + c;
        *reinterpret_cast<uint2*>(g_sh + off) = hv;
        *reinterpret_cast<uint2*>(g_sl + off) = lv;
    }
}

// ---------------- local attention, head 0 (dedup exp; real queries) ---------
__global__ __launch_bounds__(1024) void local_attn_kernel() {
    __shared__ float tile[64][DH];
    __shared__ float scores[32][64];
    int b   = blockIdx.x / 94;
    int blk = blockIdx.x - b*94;
    int win = blk >> 2;
    int qc  = blk & 3;
    int warp = threadIdx.x >> 5, lane = threadIdx.x & 31;
    int qt = win*128 + qc*32 + warp;
    size_t qoff = (size_t)(b*SEQ + qt)*DM;
    float4 q4 = *reinterpret_cast<const float4*>(g_q + qoff + lane*4);
    float m = -1e30f, l = 0.f;
    float4 acc = make_float4(0.f,0.f,0.f,0.f);
    int kbase = win*128 - 128;
    for (int ch=0; ch<6; ch++) {
        int t0 = kbase + ch*64;
        __syncthreads();
        #pragma unroll
        for (int it=0; it<2; it++) {
            int idx = it*1024 + threadIdx.x;
            int r = idx >> 5, c4 = idx & 31;
            int t = t0 + r;
            float4 kv = make_float4(0.f,0.f,0.f,0.f);
            if (t >= 0 && t < SEQ)
                kv = *reinterpret_cast<const float4*>(g_k + (size_t)(b*SEQ+t)*DM + c4*4);
            *reinterpret_cast<float4*>(&tile[r][c4*4]) = kv;
        }
        __syncthreads();
        for (int j=0; j<64; j++) {
            float4 kv = *reinterpret_cast<const float4*>(&tile[j][lane*4]);
            float s = q4.x*kv.x + q4.y*kv.y + q4.z*kv.z + q4.w*kv.w;
            #pragma unroll
            for (int o=16;o;o>>=1) s += __shfl_xor_sync(~0u,s,o);
            if (lane == (j & 31)) {
                int t = t0 + j;
                scores[warp][j] = (t >= 0 && t < SEQ) ? s*SCALE : -1e38f;
            }
        }
        __syncthreads();
        #pragma unroll
        for (int it=0; it<2; it++) {
            int idx = it*1024 + threadIdx.x;
            int r = idx >> 5, c4 = idx & 31;
            int t = t0 + r;
            float4 vv = make_float4(0.f,0.f,0.f,0.f);
            if (t >= 0 && t < SEQ)
                vv = *reinterpret_cast<const float4*>(g_v + (size_t)(b*SEQ+t)*DM + c4*4);
            *reinterpret_cast<float4*>(&tile[r][c4*4]) = vv;
        }
        __syncthreads();
        float s0 = scores[warp][lane], s1 = scores[warp][lane+32];
        float cm = fmaxf(s0, s1);
        #pragma unroll
        for (int o=16;o;o>>=1) cm = fmaxf(cm, __shfl_xor_sync(~0u,cm,o));
        float mn = fmaxf(m, cm);
        float corr = expf(m - mn);
        l *= corr; acc.x*=corr; acc.y*=corr; acc.z*=corr; acc.w*=corr;
        float p0 = expf(s0 - mn), p1 = expf(s1 - mn);
        l += p0 + p1;                     // per-lane partial sum (2 keys/lane)
        scores[warp][lane] = p0; scores[warp][lane+32] = p1;
        __syncwarp();
        for (int j=0; j<64; j++) {
            float p = scores[warp][j];    // smem broadcast, no MUFU
            float4 vv = *reinterpret_cast<const float4*>(&tile[j][lane*4]);
            acc.x = fmaf(p, vv.x, acc.x);
            acc.y = fmaf(p, vv.y, acc.y);
            acc.z = fmaf(p, vv.z, acc.z);
            acc.w = fmaf(p, vv.w, acc.w);
        }
        m = mn;
    }
    #pragma unroll
    for (int o=16;o;o>>=1) l += __shfl_xor_sync(~0u,l,o);
    float inv = 1.f/l;
    uint2 hv, lv;
    split2h(acc.x*inv, acc.y*inv, hv.x, lv.x);
    split2h(acc.z*inv, acc.w*inv, hv.y, lv.y);
    *reinterpret_cast<uint2*>(g_sh + qoff + lane*4) = hv;
    *reinterpret_cast<uint2*>(g_sl + qoff + lane*4) = lv;
}

// ---------------- k column softmax stats (heads 1..3) -----------------------
__global__ void kstats_kernel() {
    int bh = blockIdx.x;
    int b = bh/3, hh = bh%3 + 1;
    int d = blockIdx.y*32 + threadIdx.x;
    int ty = threadIdx.y;
    int col = hh*DH + d;
    float m = -1e30f, l = 0.f;
    for (int t = ty; t < SEQ; t += 8) {
        float val = g_k[(size_t)(b*SEQ+t)*DM + col];
        if (val > m) { l = l*expf(m - val) + 1.f; m = val; }
        else l += expf(val - m);
    }
    __shared__ float sm[8][32], sl[8][32];
    sm[ty][threadIdx.x] = m; sl[ty][threadIdx.x] = l;
    __syncthreads();
    if (ty == 0) {
        #pragma unroll
        for (int r=1;r<8;r++) {
            float m2 = sm[r][threadIdx.x], l2 = sl[r][threadIdx.x];
            float M = fmaxf(m, m2);
            l = l*expf(m - M) + l2*expf(m2 - M);
            m = M;
        }
        g_kmax[bh*DH + d] = m;
        g_klse[bh*DH + d] = l;
    }
}

// ---------------- ctx partial ------------------------------------------------
__global__ __launch_bounds__(256) void ctx_partial_kernel() {
    __shared__ float kt[32][132];
    __shared__ float vt[32][132];
    __shared__ float smax[DH], sinv[DH];
    int bh = blockIdx.x, ks = blockIdx.y;
    int b = bh/3, hh = bh%3 + 1;
    if (threadIdx.x < DH) {
        smax[threadIdx.x] = g_kmax[bh*DH + threadIdx.x];
        sinv[threadIdx.x] = 1.f/g_klse[bh*DH + threadIdx.x];
    }
    int tx = threadIdx.x & 15, ty = threadIdx.x >> 4;
    float acc[8][8];
    #pragma unroll
    for (int i=0;i<8;i++)
        #pragma unroll
        for (int j=0;j<8;j++) acc[i][j]=0.f;

    for (int t0=0; t0<512; t0+=32) {
        __syncthreads();
        #pragma unroll
        for (int i=0;i<4;i++) {
            int idx = i*256 + threadIdx.x;
            int r = idx >> 5, c4 = idx & 31;
            int t = ks*512 + t0 + r;
            size_t off = (size_t)(b*SEQ+t)*DM + hh*DH + c4*4;
            float4 kv = *reinterpret_cast<const float4*>(g_k + off);
            float4 vv = *reinterpret_cast<const float4*>(g_v + off);
            int d0 = c4*4;
            kt[r][d0+0] = expf(kv.x - smax[d0+0])*sinv[d0+0];
            kt[r][d0+1] = expf(kv.y - smax[d0+1])*sinv[d0+1];
            kt[r][d0+2] = expf(kv.z - smax[d0+2])*sinv[d0+2];
            kt[r][d0+3] = expf(kv.w - smax[d0+3])*sinv[d0+3];
            *reinterpret_cast<float4*>(&vt[r][d0]) = vv;
        }
        __syncthreads();
        #pragma unroll
        for (int kk=0; kk<32; kk++) {
            float a[8], bb[8];
            *reinterpret_cast<float4*>(&a[0])  = *reinterpret_cast<const float4*>(&kt[kk][ty*8]);
            *reinterpret_cast<float4*>(&a[4])  = *reinterpret_cast<const float4*>(&kt[kk][ty*8+4]);
            *reinterpret_cast<float4*>(&bb[0]) = *reinterpret_cast<const float4*>(&vt[kk][tx*8]);
            *reinterpret_cast<float4*>(&bb[4]) = *reinterpret_cast<const float4*>(&vt[kk][tx*8+4]);
            #pragma unroll
            for (int i=0;i<8;i++)
                #pragma unroll
                for (int j=0;j<8;j++)
                    acc[i][j] = fmaf(a[i], bb[j], acc[i][j]);
        }
    }
    float* op = g_ctxp + ((size_t)bh*8 + ks)*DH*DH;
    #pragma unroll
    for (int i=0;i<8;i++)
        #pragma unroll
        for (int j=0;j<8;j+=4) {
            float4 o4 = make_float4(acc[i][j],acc[i][j+1],acc[i][j+2],acc[i][j+3]);
            *reinterpret_cast<float4*>(op + (size_t)(ty*8+i)*DH + tx*8 + j) = o4;
        }
}

__global__ void ctx_reduce_kernel() {
    int idx = blockIdx.x*256 + threadIdx.x;
    if (idx >= BSZ*3*DH*DH) return;
    int bh = idx / (DH*DH);
    int de = idx - bh*DH*DH;
    float s = 0.f;
    #pragma unroll
    for (int ks=0;ks<8;ks++) s += g_ctxp[((size_t)bh*8+ks)*DH*DH + de];
    g_ctx[idx] = s;
}

// ---------------- linear-attn output -> fp16 split ---------------------------
__global__ __launch_bounds__(256) void lin_out_kernel() {
    __shared__ float sctx[64][DH];
    int bh = blockIdx.x;
    int b = bh/3, hh = bh%3 + 1;
    int warp = threadIdx.x >> 5, lane = threadIdx.x & 31;
    const float* ctxp = g_ctx + (size_t)bh*DH*DH;
    float pr[4][4], o[4][4];
    int tbase = blockIdx.y*32 + warp*4;
    #pragma unroll
    for (int tt=0;tt<4;tt++) {
        int t = tbase + tt;
        const float* qp = g_q + (size_t)(b*SEQ+t)*DM + hh*DH;
        float4 q4 = *reinterpret_cast<const float4*>(qp + lane*4);
        float mx = fmaxf(fmaxf(q4.x,q4.y),fmaxf(q4.z,q4.w));
        #pragma unroll
        for (int s=16;s;s>>=1) mx = fmaxf(mx, __shfl_xor_sync(~0u,mx,s));
        float e0=expf(q4.x-mx), e1=expf(q4.y-mx), e2=expf(q4.z-mx), e3=expf(q4.w-mx);
        float sm = e0+e1+e2+e3;
        #pragma unroll
        for (int s=16;s;s>>=1) sm += __shfl_xor_sync(~0u,sm,s);
        float inv = SCALE/sm;
        pr[tt][0]=e0*inv; pr[tt][1]=e1*inv; pr[tt][2]=e2*inv; pr[tt][3]=e3*inv;
        o[tt][0]=0.f; o[tt][1]=0.f; o[tt][2]=0.f; o[tt][3]=0.f;
    }
    for (int ph=0; ph<2; ph++) {
        __syncthreads();
        #pragma unroll
        for (int i=0;i<8;i++) {
            int idx = i*256 + threadIdx.x;
            int r = idx >> 5, c4 = idx & 31;
            *reinterpret_cast<float4*>(&sctx[r][c4*4]) =
                *reinterpret_cast<const float4*>(ctxp + (size_t)(ph*64+r)*DH + c4*4);
        }
        __syncthreads();
        #pragma unroll
        for (int dl=0; dl<16; dl++) {
            int src = ph*16 + dl;
            #pragma unroll
            for (int tt=0;tt<4;tt++) {
                float b0 = __shfl_sync(~0u, pr[tt][0], src);
                float b1 = __shfl_sync(~0u, pr[tt][1], src);
                float b2 = __shfl_sync(~0u, pr[tt][2], src);
                float b3 = __shfl_sync(~0u, pr[tt][3], src);
                float4 c0 = *reinterpret_cast<const float4*>(&sctx[dl*4+0][lane*4]);
                float4 c1 = *reinterpret_cast<const float4*>(&sctx[dl*4+1][lane*4]);
                float4 c2 = *reinterpret_cast<const float4*>(&sctx[dl*4+2][lane*4]);
                float4 c3 = *reinterpret_cast<const float4*>(&sctx[dl*4+3][lane*4]);
                o[tt][0] += b0*c0.x + b1*c1.x + b2*c2.x + b3*c3.x;
                o[tt][1] += b0*c0.y + b1*c1.y + b2*c2.y + b3*c3.y;
                o[tt][2] += b0*c0.z + b1*c1.z + b2*c2.z + b3*c3.z;
                o[tt][3] += b0*c0.w + b1*c1.w + b2*c2.w + b3*c3.w;
            }
        }
    }
    #pragma unroll
    for (int tt=0;tt<4;tt++) {
        int t = tbase + tt;
        size_t off = (size_t)(b*SEQ+t)*DM + hh*DH + lane*4;
        uint2 hv, lv;
        split2h(o[tt][0], o[tt][1], hv.x, lv.x);
        split2h(o[tt][2], o[tt][3], hv.y, lv.y);
        *reinterpret_cast<uint2*>(g_sh + off) = hv;
        *reinterpret_cast<uint2*>(g_sl + off) = lv;
    }
}

// ---------------- final slice ------------------------------------------------
__global__ void slice_kernel(float* __restrict__ out) {
    int idx = blockIdx.x*256 + threadIdx.x;
    const int total = BSZ*NTOK*(DOUT/4);
    if (idx >= total) return;
    int row = idx >> 4;
    int c4  = idx & 15;
    int b = row / NTOK, t = row - b*NTOK;
    reinterpret_cast<float4*>(out)[idx] =
        reinterpret_cast<const float4*>(g_of)[(size_t)(b*SEQ+t)*16 + c4];
}

// ---------------- host ---------------------------------------------------
static inline void tc_gemm(cudaStream_t st, const fp16* Ah, const fp16* Al, const fp16* B,
                           const float* bias, const float* res,
                           float* C, fp16* Chi, fp16* Clo,
                           int N, int K, int act) {
    dim3 grid((N + 127) / 128, BSZ*MTPB);
    tc_gemm_kernel<<<grid, 256, GEMM_SMEM, st>>>(Ah, Al, B, bias, res, C, Chi, Clo, N, K, act);
}

extern "C" void kernel_launch(void* const* d_in, const int* in_sizes, int n_in,
                              void* d_out, int out_size) {
    const float* x    = (const float*)d_in[0];
    const float* W1   = (const float*)d_in[1];
    const float* b1   = (const float*)d_in[2];
    const float* ln1g = (const float*)d_in[3];
    const float* ln1b = (const float*)d_in[4];
    const float* Wq   = (const float*)d_in[5];
    const float* Wk   = (const float*)d_in[6];
    const float* Wv   = (const float*)d_in[7];
    const float* Wo   = (const float*)d_in[8];
    const float* bo   = (const float*)d_in[9];
    const float* ln2g = (const float*)d_in[10];
    const float* ln2b = (const float*)d_in[11];
    const float* Wf1  = (const float*)d_in[12];
    const float* bf1  = (const float*)d_in[13];
    const float* Wf2  = (const float*)d_in[14];
    const float* bf2  = (const float*)d_in[15];
    const float* W2   = (const float*)d_in[16];
    const float* b2   = (const float*)d_in[17];
    float* out = (float*)d_out;

    static int init_done = 0;
    static cudaStream_t st1, st2;
    static cudaEvent_t evStart, evT1, evQKV, evPad, evLin;
    if (!init_done) {
        cudaFuncSetAttribute(tc_gemm_kernel, cudaFuncAttributeMaxDynamicSharedMemorySize, GEMM_SMEM);
        cudaStreamCreateWithFlags(&st1, cudaStreamNonBlocking);
        cudaStreamCreateWithFlags(&st2, cudaStreamNonBlocking);
        cudaEventCreateWithFlags(&evStart, cudaEventDisableTiming);
        cudaEventCreateWithFlags(&evT1,    cudaEventDisableTiming);
        cudaEventCreateWithFlags(&evQKV,   cudaEventDisableTiming);
        cudaEventCreateWithFlags(&evPad,   cudaEventDisableTiming);
        cudaEventCreateWithFlags(&evLin,   cudaEventDisableTiming);
        init_done = 1;
    }

    float *h,*q,*k,*v,*of;
    fp16 *sh,*sl,*s2h,*s2l;
    fp16 *w1h,*wqh,*wkh,*wvh,*woh,*wf1h,*wf2h,*w2h;
    cudaGetSymbolAddress((void**)&h,    g_h);
    cudaGetSymbolAddress((void**)&q,    g_q);
    cudaGetSymbolAddress((void**)&k,    g_k);
    cudaGetSymbolAddress((void**)&v,    g_v);
    cudaGetSymbolAddress((void**)&of,   g_of);
    cudaGetSymbolAddress((void**)&sh,   g_sh);
    cudaGetSymbolAddress((void**)&sl,   g_sl);
    cudaGetSymbolAddress((void**)&s2h,  g_s2h);
    cudaGetSymbolAddress((void**)&s2l,  g_s2l);
    cudaGetSymbolAddress((void**)&w1h,  g_w1h);
    cudaGetSymbolAddress((void**)&wqh,  g_wqh);
    cudaGetSymbolAddress((void**)&wkh,  g_wkh);
    cudaGetSymbolAddress((void**)&wvh,  g_wvh);
    cudaGetSymbolAddress((void**)&woh,  g_woh);
    cudaGetSymbolAddress((void**)&wf1h, g_wf1h);
    cudaGetSymbolAddress((void**)&wf2h, g_wf2h);
    cudaGetSymbolAddress((void**)&w2h,  g_w2h);

    dim3 tb(32, 8);

    // fork: pad-row chain (st2) and weight transposes (st1) off the main stream
    cudaEventRecord(evStart, 0);
    cudaStreamWaitEvent(st2, evStart, 0);
    pad_ln_kernel<<<1, 512, 0, st2>>>(b1, ln1g, ln1b);
    pad_kv_kernel<<<4, 256, 0, st2>>>(Wk, Wv);
    padfill_kernel<<<(BSZ*(SEQ-NTOK)*(DM/4) + 255)/256, 256, 0, st2>>>();
    cudaEventRecord(evPad, st2);

    cudaStreamWaitEvent(st1, evStart, 0);
    transpose_h_kernel<<<dim3(DM/32,  DM/32),  tb, 0, st1>>>(Wq,  wqh,  DM,  DM);
    transpose_h_kernel<<<dim3(DM/32,  DM/32),  tb, 0, st1>>>(Wk,  wkh,  DM,  DM);
    transpose_h_kernel<<<dim3(DM/32,  DM/32),  tb, 0, st1>>>(Wv,  wvh,  DM,  DM);
    transpose_h_kernel<<<dim3(DM/32,  DM/32),  tb, 0, st1>>>(Wo,  woh,  DM,  DM);
    transpose_h_kernel<<<dim3(DFF/32, DM/32),  tb, 0, st1>>>(Wf1, wf1h, DM,  DFF);
    transpose_h_kernel<<<dim3(DM/32,  DFF/32), tb, 0, st1>>>(Wf2, wf2h, DFF, DM);
    transpose_h_kernel<<<dim3(DOUT/32,DM/32),  tb, 0, st1>>>(W2,  w2h,  DM,  DOUT);
    cudaEventRecord(evT1, st1);

    // main stream
    transpose_h_kernel<<<dim3(DM/32, DIN/32), tb>>>(W1, w1h, DIN, DM);
    pad_split_kernel<<<(BSZ*NTOK*(DIN/4) + 255)/256, 256>>>(x);
    tc_gemm(0, sh, sl, w1h, b1, nullptr, h, nullptr, nullptr, DM, DIN, 1);
    ln_kernel<<<BSZ*NTOK/8, 256>>>(h, ln1g, ln1b);
    cudaStreamWaitEvent(0, evT1, 0);
    tc_gemm(0, sh, sl, wqh, nullptr, nullptr, q, nullptr, nullptr, DM, DM, 0);
    tc_gemm(0, sh, sl, wkh, nullptr, nullptr, k, nullptr, nullptr, DM, DM, 0);
    tc_gemm(0, sh, sl, wvh, nullptr, nullptr, v, nullptr, nullptr, DM, DM, 0);
    cudaEventRecord(evQKV, 0);

    // linear-attn chain on st1, local attention on main stream (overlapped)
    cudaStreamWaitEvent(st1, evQKV, 0);
    cudaStreamWaitEvent(st1, evPad, 0);
    kstats_kernel<<<dim3(BSZ*3,4), dim3(32,8), 0, st1>>>();
    ctx_partial_kernel<<<dim3(BSZ*3,8), 256, 0, st1>>>();
    ctx_reduce_kernel<<<(BSZ*3*DH*DH + 255)/256, 256, 0, st1>>>();
    lin_out_kernel<<<dim3(BSZ*3, 94), 256, 0, st1>>>();
    cudaEventRecord(evLin, st1);

    cudaStreamWaitEvent(0, evPad, 0);
    local_attn_kernel<<<BSZ*94, 1024>>>();
    cudaStreamWaitEvent(0, evLin, 0);

    // tail on main stream
    tc_gemm(0, sh, sl, woh, bo, h, h, nullptr, nullptr, DM, DM, 0);
    ln_kernel<<<BSZ*NTOK/8, 256>>>(h, ln2g, ln2b);
    tc_gemm(0, sh, sl, wf1h, bf1, nullptr, nullptr, s2h, s2l, DFF, DM, 2);
    tc_gemm(0, s2h, s2l, wf2h, bf2, h, nullptr, sh, sl, DM, DFF, 0);
    tc_gemm(0, sh, sl, w2h, b2, nullptr, of, nullptr, nullptr, DOUT, DM, 0);
    slice_kernel<<<(BSZ*NTOK*(DOUT/4) + 255)/256, 256>>>(out);
}

// round 8
// speedup vs baseline: 4.2491x; 1.2544x over previous
#include <cuda_runtime.h>
#include <cuda_fp16.h>
#include <math.h>
#include <stdint.h>

#define BSZ   8
#define SEQ   4096
#define NTOK  3000
#define DIN   128
#define DM    512
#define DFF   2048
#define DOUT  64
#define DH    128
#define MTOT  (BSZ*SEQ)
#define MTPB  24                     // M-tiles per batch: ceil(3000/128)
#define SCALE 0.08838834764831845f   // 1/sqrt(128)
#define GEMM_SMEM (3*16384)          // 3 stages x 2 arrays x 128 x 64B (swizzled)

typedef __half fp16;

// ---------------- scratch (static device globals: no allocation) -------------
__device__ float g_h[MTOT*DM];
__device__ float g_q[MTOT*DM];
__device__ float g_k[MTOT*DM];
__device__ float g_v[MTOT*DM];
__device__ float g_of[MTOT*DOUT];
__device__ float g_kmax[BSZ*3*DH];
__device__ float g_klse[BSZ*3*DH];
__device__ float g_ctxp[BSZ*3*8*DH*DH];
__device__ float g_ctx[BSZ*3*DH*DH];
__device__ float g_lnpad[DM];
__device__ float g_kpad[DM];
__device__ float g_vpad[DM];
// fp16 activation buffers
__device__ fp16 g_sh[MTOT*DM];
__device__ fp16 g_s2h[MTOT*DFF];
// transposed weights [N][K], fp16
__device__ fp16 g_w1h[DM*DIN];
__device__ fp16 g_wqh[DM*DM];
__device__ fp16 g_wkh[DM*DM];
__device__ fp16 g_wvh[DM*DM];
__device__ fp16 g_woh[DM*DM];
__device__ fp16 g_wf1h[DFF*DM];
__device__ fp16 g_wf2h[DM*DFF];
__device__ fp16 g_w2h[DOUT*DM];

// ---------------- helpers ----------------
__device__ __forceinline__ uint32_t smem_u32(const void* p) {
    uint32_t a;
    asm("{ .reg .u64 t; cvta.to.shared.u64 t, %1; cvt.u32.u64 %0, t; }" : "=r"(a) : "l"(p));
    return a;
}
__device__ __forceinline__ uint32_t pack2h(float x, float y) {
    __half2 h = __floats2half2_rn(x, y);
    return *reinterpret_cast<uint32_t*>(&h);
}

#define LDSM_X4(r0,r1,r2,r3,addr) \
    asm volatile("ldmatrix.sync.aligned.m8n8.x4.shared.b16 {%0,%1,%2,%3}, [%4];" \
        : "=r"(r0),"=r"(r1),"=r"(r2),"=r"(r3) : "r"(addr))
#define MMA16816(d, a0,a1,a2,a3, b0,b1) \
    asm volatile("mma.sync.aligned.m16n8k16.row.col.f32.f16.f16.f32 " \
        "{%0,%1,%2,%3},{%4,%5,%6,%7},{%8,%9},{%0,%1,%2,%3};" \
        : "+f"((d)[0]),"+f"((d)[1]),"+f"((d)[2]),"+f"((d)[3]) \
        : "r"(a0),"r"(a1),"r"(a2),"r"(a3),"r"(b0),"r"(b1))
#define CP_ASYNC16(dst, src, sz) \
    asm volatile("cp.async.cg.shared.global [%0], [%1], 16, %2;" :: "r"(dst), "l"(src), "r"(sz))
#define CP_COMMIT()  asm volatile("cp.async.commit_group;" ::: "memory")
#define CP_WAIT0()   asm volatile("cp.async.wait_group 0;" ::: "memory")
#define CP_WAIT1()   asm volatile("cp.async.wait_group 1;" ::: "memory")

// ---------------- weight transpose + fp16: T[n][k] = h(W[k][n]) --------------
__global__ void transpose_h_kernel(const float* __restrict__ W,
                                   fp16* __restrict__ Th, int K, int N) {
    __shared__ float t[32][33];
    int bx = blockIdx.x * 32, by = blockIdx.y * 32;
    int x = bx + threadIdx.x;
    #pragma unroll
    for (int i = 0; i < 32; i += 8) {
        int y = by + threadIdx.y + i;
        if (x < N && y < K) t[threadIdx.y + i][threadIdx.x] = W[(size_t)y * N + x];
    }
    __syncthreads();
    int xk = by + threadIdx.x;
    #pragma unroll
    for (int i = 0; i < 32; i += 8) {
        int yn = bx + threadIdx.y + i;
        if (xk < K && yn < N)
            Th[(size_t)yn * K + xk] = __float2half_rn(t[threadIdx.x][threadIdx.y + i]);
    }
}

// ---------------- x (real rows only) -> g_sh fp16 ----------------------------
__global__ void pad_split_kernel(const float* __restrict__ x) {
    int idx = blockIdx.x*256 + threadIdx.x;
    const int total = BSZ*NTOK*(DIN/4);
    if (idx >= total) return;
    int rr = idx >> 5;
    int c4 = idx & 31;
    int b = rr / NTOK, t = rr - b*NTOK;
    float4 val = reinterpret_cast<const float4*>(x)[(size_t)rr*32 + c4];
    uint2 hv;
    hv.x = pack2h(val.x, val.y);
    hv.y = pack2h(val.z, val.w);
    *reinterpret_cast<uint2*>(g_sh + (size_t)(b*SEQ + t)*DIN + c4*4) = hv;
}

// ---------------- pad-row LN: lnpad = LN(tanh(b1)) ---------------------------
__global__ void pad_ln_kernel(const float* __restrict__ b1, const float* __restrict__ gam,
                              const float* __restrict__ bet) {
    __shared__ float ss[16], ss2[16], stat[2];
    int t = threadIdx.x;
    float h = tanhf(b1[t]);
    float s = h, s2 = h*h;
    #pragma unroll
    for (int o=16;o;o>>=1) { s += __shfl_xor_sync(~0u,s,o); s2 += __shfl_xor_sync(~0u,s2,o); }
    if ((t & 31) == 0) { ss[t>>5] = s; ss2[t>>5] = s2; }
    __syncthreads();
    if (t == 0) {
        float S=0.f, S2=0.f;
        #pragma unroll
        for (int i=0;i<16;i++) { S += ss[i]; S2 += ss2[i]; }
        float mu = S*(1.f/512.f);
        float var = S2*(1.f/512.f) - mu*mu;
        stat[0] = mu; stat[1] = rsqrtf(var + 1e-5f);
    }
    __syncthreads();
    g_lnpad[t] = (h - stat[0])*stat[1]*gam[t] + bet[t];
}

// ---------------- pad-row k/v ------------------------------------------------
__global__ void pad_kv_kernel(const float* __restrict__ Wk, const float* __restrict__ Wv) {
    int d = blockIdx.x*256 + threadIdx.x;
    if (d >= 2*DM) return;
    const float* W = (d < DM) ? Wk : Wv;
    int dd = d & (DM-1);
    float s = 0.f;
    for (int kk = 0; kk < DM; kk++) s += g_lnpad[kk] * W[(size_t)kk*DM + dd];
    if (d < DM) g_kpad[dd] = s; else g_vpad[dd] = s;
}

// ---------------- broadcast pad k/v rows -------------------------------------
__global__ void padfill_kernel() {
    int idx = blockIdx.x*256 + threadIdx.x;
    const int per = (SEQ-NTOK)*(DM/4);
    if (idx >= BSZ*per) return;
    int b = idx / per, r = idx - b*per;
    int t = NTOK + r/(DM/4), c4 = r % (DM/4);
    size_t off = (size_t)(b*SEQ + t)*DM + c4*4;
    *reinterpret_cast<float4*>(g_k + off) = *reinterpret_cast<const float4*>(g_kpad + c4*4);
    *reinterpret_cast<float4*>(g_v + off) = *reinterpret_cast<const float4*>(g_vpad + c4*4);
}

// ---------------- fp16 single-product tensor-core GEMM (real rows) -----------
// C = act(A @ B^T + bias) + res. A fp16 [rows][K], B fp16 [N][K].
__global__ __launch_bounds__(256, 2) void tc_gemm_kernel(
    const fp16* __restrict__ A, const fp16* __restrict__ B,
    const float* __restrict__ bias, const float* __restrict__ res,
    float* __restrict__ C, fp16* __restrict__ Ch,
    int N, int K, int act)
{
    extern __shared__ __align__(1024) char smc[];
    uint32_t sbase = smem_u32(smc);
    int tid = threadIdx.x;
    int mtile = blockIdx.y;
    int bb = mtile / MTPB, t0 = (mtile - bb*MTPB) << 7;
    int bm = bb*SEQ + t0;
    int alim = NTOK - t0;
    int rowlim = bm + alim;
    int bn = blockIdx.x << 7;
    int lane = tid & 31, w = tid >> 5;
    int wm = w & 1, wn = w >> 1;
    int grp = lane >> 2, qp = lane & 3;

    uint32_t swz = (lane >> 1) & 3;
    uint32_t a_base = (uint32_t)(wm*64 + (lane & 15))*64 + (((uint32_t)(lane >> 4) ^ swz) << 4);
    uint32_t b_base = (uint32_t)(wn*32 + ((lane >> 4) & 1)*8 + (lane & 7))*64
                    + ((((uint32_t)(lane >> 3) & 1) ^ swz) << 4);

    float acc[4][4][4];
    #pragma unroll
    for (int i=0;i<4;i++)
        #pragma unroll
        for (int j=0;j<4;j++)
            #pragma unroll
            for (int r=0;r<4;r++) acc[i][j][r] = 0.f;

    const int NC = K >> 5;

    #define STAGE_LOAD(c_, buf_) do { \
        int k0 = (c_) << 5; \
        uint32_t sb = sbase + (uint32_t)(buf_)*16384u; \
        _Pragma("unroll") \
        for (int i_ = 0; i_ < 4; i_++) { \
            const int arr_ = i_ >> 1; \
            int j_ = ((i_ & 1) << 8) + tid; \
            int r_ = j_ >> 2, cc_ = j_ & 3; \
            uint32_t dst_ = sb + arr_*8192u + (uint32_t)r_*64u \
                          + ((uint32_t)(cc_ ^ ((r_ >> 1) & 3)) << 4); \
            const fp16* g_; int sz_ = 16; \
            if (arr_ == 0) { \
                if (r_ < alim) g_ = A + (size_t)(bm + r_)*K + k0 + cc_*8; \
                else { g_ = A; sz_ = 0; } \
            } else { \
                int rowv_ = bn + r_; \
                if (rowv_ < N) g_ = B + (size_t)rowv_*K + k0 + cc_*8; \
                else { g_ = B; sz_ = 0; } \
            } \
            CP_ASYNC16(dst_, g_, sz_); \
        } \
        CP_COMMIT(); \
    } while (0)

    STAGE_LOAD(0, 0);
    if (NC > 1) STAGE_LOAD(1, 1);

    int buf = 0, bufn = 2;
    for (int c = 0; c < NC; c++) {
        if (c + 1 < NC) CP_WAIT1(); else CP_WAIT0();
        __syncthreads();
        if (c + 2 < NC) {
            STAGE_LOAD(c + 2, bufn);
            bufn = (bufn == 2) ? 0 : bufn + 1;
        }
        uint32_t sA = sbase + (uint32_t)buf*16384u;
        uint32_t sB = sA + 8192u;
        buf = (buf == 2) ? 0 : buf + 1;

        #pragma unroll
        for (int ks = 0; ks < 2; ks++) {
            uint32_t kx = ks ? 32u : 0u;
            uint32_t bh[4][2], a[4][4];
            #pragma unroll
            for (int p = 0; p < 2; p++)
                LDSM_X4(bh[2*p][0], bh[2*p][1], bh[2*p+1][0], bh[2*p+1][1],
                        sB + ((b_base + p*1024u) ^ kx));
            #pragma unroll
            for (int mt = 0; mt < 4; mt++)
                LDSM_X4(a[mt][0], a[mt][1], a[mt][2], a[mt][3],
                        sA + ((a_base + mt*1024u) ^ kx));
            #pragma unroll
            for (int mt = 0; mt < 4; mt++)
                #pragma unroll
                for (int nt = 0; nt < 4; nt++)
                    MMA16816(acc[mt][nt], a[mt][0],a[mt][1],a[mt][2],a[mt][3], bh[nt][0],bh[nt][1]);
        }
    }
    #undef STAGE_LOAD

    // ---- epilogue (valid rows only) ----
    #pragma unroll
    for (int mt = 0; mt < 4; mt++) {
        #pragma unroll
        for (int nt = 0; nt < 4; nt++) {
            int c0 = bn + wn*32 + nt*8 + qp*2;
            if (c0 >= N) continue;
            int rbase = bm + wm*64 + mt*16 + grp;
            float bs0 = 0.f, bs1 = 0.f;
            if (bias) { bs0 = bias[c0]; bs1 = bias[c0 + 1]; }
            #pragma unroll
            for (int half = 0; half < 2; half++) {
                int r = rbase + half*8;
                if (r >= rowlim) continue;
                float v0 = acc[mt][nt][half*2 + 0] + bs0;
                float v1 = acc[mt][nt][half*2 + 1] + bs1;
                if (act == 1) { v0 = tanhf(v0); v1 = tanhf(v1); }
                else if (act == 2) {
                    v0 = 0.5f*v0*(1.f + erff(v0*0.7071067811865476f));
                    v1 = 0.5f*v1*(1.f + erff(v1*0.7071067811865476f));
                }
                if (res) {
                    v0 += res[(size_t)r*N + c0];
                    v1 += res[(size_t)r*N + c0 + 1];
                }
                if (Ch) {
                    *reinterpret_cast<uint32_t*>(Ch + (size_t)r*N + c0) = pack2h(v0, v1);
                } else {
                    float2 o; o.x = v0; o.y = v1;
                    *reinterpret_cast<float2*>(C + (size_t)r*N + c0) = o;
                }
            }
        }
    }
}

// ---------------- LayerNorm (real rows) -> fp16 ------------------------------
__global__ void ln_kernel(const float* __restrict__ in, const float* __restrict__ gam,
                          const float* __restrict__ bet) {
    int gw = (blockIdx.x*blockDim.x + threadIdx.x) >> 5;
    int lane = threadIdx.x & 31;
    if (gw >= BSZ*NTOK) return;
    int b = gw / NTOK, t = gw - b*NTOK;
    size_t row = (size_t)(b*SEQ + t);
    const float4* rp = reinterpret_cast<const float4*>(in + row*DM);
    float4 v[4];
    float s=0.f, s2=0.f;
    #pragma unroll
    for (int i=0;i<4;i++) {
        v[i] = rp[lane + 32*i];
        s  += v[i].x+v[i].y+v[i].z+v[i].w;
        s2 += v[i].x*v[i].x + v[i].y*v[i].y + v[i].z*v[i].z + v[i].w*v[i].w;
    }
    #pragma unroll
    for (int o=16;o;o>>=1) { s += __shfl_xor_sync(~0u,s,o); s2 += __shfl_xor_sync(~0u,s2,o); }
    float mu  = s*(1.f/512.f);
    float var = s2*(1.f/512.f) - mu*mu;
    float r = rsqrtf(var + 1e-5f);
    #pragma unroll
    for (int i=0;i<4;i++) {
        int c = (lane + 32*i)*4;
        float4 g4 = *reinterpret_cast<const float4*>(gam + c);
        float4 b4 = *reinterpret_cast<const float4*>(bet + c);
        uint2 hv;
        hv.x = pack2h((v[i].x-mu)*r*g4.x + b4.x, (v[i].y-mu)*r*g4.y + b4.y);
        hv.y = pack2h((v[i].z-mu)*r*g4.z + b4.z, (v[i].w-mu)*r*g4.w + b4.w);
        *reinterpret_cast<uint2*>(g_sh + row*DM + c) = hv;
    }
}

// ---------------- local attention, head 0 (dedup exp; real queries) ---------
__global__ __launch_bounds__(1024) void local_attn_kernel() {
    __shared__ float tile[64][DH];
    __shared__ float scores[32][64];
    int b   = blockIdx.x / 94;
    int blk = blockIdx.x - b*94;
    int win = blk >> 2;
    int qc  = blk & 3;
    int warp = threadIdx.x >> 5, lane = threadIdx.x & 31;
    int qt = win*128 + qc*32 + warp;
    size_t qoff = (size_t)(b*SEQ + qt)*DM;
    float4 q4 = *reinterpret_cast<const float4*>(g_q + qoff + lane*4);
    float m = -1e30f, l = 0.f;
    float4 acc = make_float4(0.f,0.f,0.f,0.f);
    int kbase = win*128 - 128;
    for (int ch=0; ch<6; ch++) {
        int t0 = kbase + ch*64;
        __syncthreads();
        #pragma unroll
        for (int it=0; it<2; it++) {
            int idx = it*1024 + threadIdx.x;
            int r = idx >> 5, c4 = idx & 31;
            int t = t0 + r;
            float4 kv = make_float4(0.f,0.f,0.f,0.f);
            if (t >= 0 && t < SEQ)
                kv = *reinterpret_cast<const float4*>(g_k + (size_t)(b*SEQ+t)*DM + c4*4);
            *reinterpret_cast<float4*>(&tile[r][c4*4]) = kv;
        }
        __syncthreads();
        for (int j=0; j<64; j++) {
            float4 kv = *reinterpret_cast<const float4*>(&tile[j][lane*4]);
            float s = q4.x*kv.x + q4.y*kv.y + q4.z*kv.z + q4.w*kv.w;
            #pragma unroll
            for (int o=16;o;o>>=1) s += __shfl_xor_sync(~0u,s,o);
            if (lane == (j & 31)) {
                int t = t0 + j;
                scores[warp][j] = (t >= 0 && t < SEQ) ? s*SCALE : -1e38f;
            }
        }
        __syncthreads();
        #pragma unroll
        for (int it=0; it<2; it++) {
            int idx = it*1024 + threadIdx.x;
            int r = idx >> 5, c4 = idx & 31;
            int t = t0 + r;
            float4 vv = make_float4(0.f,0.f,0.f,0.f);
            if (t >= 0 && t < SEQ)
                vv = *reinterpret_cast<const float4*>(g_v + (size_t)(b*SEQ+t)*DM + c4*4);
            *reinterpret_cast<float4*>(&tile[r][c4*4]) = vv;
        }
        __syncthreads();
        float s0 = scores[warp][lane], s1 = scores[warp][lane+32];
        float cm = fmaxf(s0, s1);
        #pragma unroll
        for (int o=16;o;o>>=1) cm = fmaxf(cm, __shfl_xor_sync(~0u,cm,o));
        float mn = fmaxf(m, cm);
        float corr = expf(m - mn);
        l *= corr; acc.x*=corr; acc.y*=corr; acc.z*=corr; acc.w*=corr;
        float p0 = expf(s0 - mn), p1 = expf(s1 - mn);
        l += p0 + p1;
        scores[warp][lane] = p0; scores[warp][lane+32] = p1;
        __syncwarp();
        for (int j=0; j<64; j++) {
            float p = scores[warp][j];
            float4 vv = *reinterpret_cast<const float4*>(&tile[j][lane*4]);
            acc.x = fmaf(p, vv.x, acc.x);
            acc.y = fmaf(p, vv.y, acc.y);
            acc.z = fmaf(p, vv.z, acc.z);
            acc.w = fmaf(p, vv.w, acc.w);
        }
        m = mn;
    }
    #pragma unroll
    for (int o=16;o;o>>=1) l += __shfl_xor_sync(~0u,l,o);
    float inv = 1.f/l;
    uint2 hv;
    hv.x = pack2h(acc.x*inv, acc.y*inv);
    hv.y = pack2h(acc.z*inv, acc.w*inv);
    *reinterpret_cast<uint2*>(g_sh + qoff + lane*4) = hv;
}

// ---------------- k column softmax stats (heads 1..3) -----------------------
__global__ void kstats_kernel() {
    int bh = blockIdx.x;
    int b = bh/3, hh = bh%3 + 1;
    int d = blockIdx.y*32 + threadIdx.x;
    int ty = threadIdx.y;
    int col = hh*DH + d;
    float m = -1e30f, l = 0.f;
    for (int t = ty; t < SEQ; t += 8) {
        float val = g_k[(size_t)(b*SEQ+t)*DM + col];
        if (val > m) { l = l*expf(m - val) + 1.f; m = val; }
        else l += expf(val - m);
    }
    __shared__ float sm[8][32], sl[8][32];
    sm[ty][threadIdx.x] = m; sl[ty][threadIdx.x] = l;
    __syncthreads();
    if (ty == 0) {
        #pragma unroll
        for (int r=1;r<8;r++) {
            float m2 = sm[r][threadIdx.x], l2 = sl[r][threadIdx.x];
            float M = fmaxf(m, m2);
            l = l*expf(m - M) + l2*expf(m2 - M);
            m = M;
        }
        g_kmax[bh*DH + d] = m;
        g_klse[bh*DH + d] = l;
    }
}

// ---------------- ctx partial ------------------------------------------------
__global__ __launch_bounds__(256) void ctx_partial_kernel() {
    __shared__ float kt[32][132];
    __shared__ float vt[32][132];
    __shared__ float smax[DH], sinv[DH];
    int bh = blockIdx.x, ks = blockIdx.y;
    int b = bh/3, hh = bh%3 + 1;
    if (threadIdx.x < DH) {
        smax[threadIdx.x] = g_kmax[bh*DH + threadIdx.x];
        sinv[threadIdx.x] = 1.f/g_klse[bh*DH + threadIdx.x];
    }
    int tx = threadIdx.x & 15, ty = threadIdx.x >> 4;
    float acc[8][8];
    #pragma unroll
    for (int i=0;i<8;i++)
        #pragma unroll
        for (int j=0;j<8;j++) acc[i][j]=0.f;

    for (int t0=0; t0<512; t0+=32) {
        __syncthreads();
        #pragma unroll
        for (int i=0;i<4;i++) {
            int idx = i*256 + threadIdx.x;
            int r = idx >> 5, c4 = idx & 31;
            int t = ks*512 + t0 + r;
            size_t off = (size_t)(b*SEQ+t)*DM + hh*DH + c4*4;
            float4 kv = *reinterpret_cast<const float4*>(g_k + off);
            float4 vv = *reinterpret_cast<const float4*>(g_v + off);
            int d0 = c4*4;
            kt[r][d0+0] = expf(kv.x - smax[d0+0])*sinv[d0+0];
            kt[r][d0+1] = expf(kv.y - smax[d0+1])*sinv[d0+1];
            kt[r][d0+2] = expf(kv.z - smax[d0+2])*sinv[d0+2];
            kt[r][d0+3] = expf(kv.w - smax[d0+3])*sinv[d0+3];
            *reinterpret_cast<float4*>(&vt[r][d0]) = vv;
        }
        __syncthreads();
        #pragma unroll
        for (int kk=0; kk<32; kk++) {
            float a[8], bb[8];
            *reinterpret_cast<float4*>(&a[0])  = *reinterpret_cast<const float4*>(&kt[kk][ty*8]);
            *reinterpret_cast<float4*>(&a[4])  = *reinterpret_cast<const float4*>(&kt[kk][ty*8+4]);
            *reinterpret_cast<float4*>(&bb[0]) = *reinterpret_cast<const float4*>(&vt[kk][tx*8]);
            *reinterpret_cast<float4*>(&bb[4]) = *reinterpret_cast<const float4*>(&vt[kk][tx*8+4]);
            #pragma unroll
            for (int i=0;i<8;i++)
                #pragma unroll
                for (int j=0;j<8;j++)
                    acc[i][j] = fmaf(a[i], bb[j], acc[i][j]);
        }
    }
    float* op = g_ctxp + ((size_t)bh*8 + ks)*DH*DH;
    #pragma unroll
    for (int i=0;i<8;i++)
        #pragma unroll
        for (int j=0;j<8;j+=4) {
            float4 o4 = make_float4(acc[i][j],acc[i][j+1],acc[i][j+2],acc[i][j+3]);
            *reinterpret_cast<float4*>(op + (size_t)(ty*8+i)*DH + tx*8 + j) = o4;
        }
}

__global__ void ctx_reduce_kernel() {
    int idx = blockIdx.x*256 + threadIdx.x;
    if (idx >= BSZ*3*DH*DH) return;
    int bh = idx / (DH*DH);
    int de = idx - bh*DH*DH;
    float s = 0.f;
    #pragma unroll
    for (int ks=0;ks<8;ks++) s += g_ctxp[((size_t)bh*8+ks)*DH*DH + de];
    g_ctx[idx] = s;
}

// ---------------- linear-attn output -> fp16 ---------------------------------
__global__ __launch_bounds__(256) void lin_out_kernel() {
    __shared__ float sctx[64][DH];
    int bh = blockIdx.x;
    int b = bh/3, hh = bh%3 + 1;
    int warp = threadIdx.x >> 5, lane = threadIdx.x & 31;
    const float* ctxp = g_ctx + (size_t)bh*DH*DH;
    float pr[4][4], o[4][4];
    int tbase = blockIdx.y*32 + warp*4;
    #pragma unroll
    for (int tt=0;tt<4;tt++) {
        int t = tbase + tt;
        const float* qp = g_q + (size_t)(b*SEQ+t)*DM + hh*DH;
        float4 q4 = *reinterpret_cast<const float4*>(qp + lane*4);
        float mx = fmaxf(fmaxf(q4.x,q4.y),fmaxf(q4.z,q4.w));
        #pragma unroll
        for (int s=16;s;s>>=1) mx = fmaxf(mx, __shfl_xor_sync(~0u,mx,s));
        float e0=expf(q4.x-mx), e1=expf(q4.y-mx), e2=expf(q4.z-mx), e3=expf(q4.w-mx);
        float sm = e0+e1+e2+e3;
        #pragma unroll
        for (int s=16;s;s>>=1) sm += __shfl_xor_sync(~0u,sm,s);
        float inv = SCALE/sm;
        pr[tt][0]=e0*inv; pr[tt][1]=e1*inv; pr[tt][2]=e2*inv; pr[tt][3]=e3*inv;
        o[tt][0]=0.f; o[tt][1]=0.f; o[tt][2]=0.f; o[tt][3]=0.f;
    }
    for (int ph=0; ph<2; ph++) {
        __syncthreads();
        #pragma unroll
        for (int i=0;i<8;i++) {
            int idx = i*256 + threadIdx.x;
            int r = idx >> 5, c4 = idx & 31;
            *reinterpret_cast<float4*>(&sctx[r][c4*4]) =
                *reinterpret_cast<const float4*>(ctxp + (size_t)(ph*64+r)*DH + c4*4);
        }
        __syncthreads();
        #pragma unroll
        for (int dl=0; dl<16; dl++) {
            int src = ph*16 + dl;
            #pragma unroll
            for (int tt=0;tt<4;tt++) {
                float b0 = __shfl_sync(~0u, pr[tt][0], src);
                float b1 = __shfl_sync(~0u, pr[tt][1], src);
                float b2 = __shfl_sync(~0u, pr[tt][2], src);
                float b3 = __shfl_sync(~0u, pr[tt][3], src);
                float4 c0 = *reinterpret_cast<const float4*>(&sctx[dl*4+0][lane*4]);
                float4 c1 = *reinterpret_cast<const float4*>(&sctx[dl*4+1][lane*4]);
                float4 c2 = *reinterpret_cast<const float4*>(&sctx[dl*4+2][lane*4]);
                float4 c3 = *reinterpret_cast<const float4*>(&sctx[dl*4+3][lane*4]);
                o[tt][0] += b0*c0.x + b1*c1.x + b2*c2.x + b3*c3.x;
                o[tt][1] += b0*c0.y + b1*c1.y + b2*c2.y + b3*c3.y;
                o[tt][2] += b0*c0.z + b1*c1.z + b2*c2.z + b3*c3.z;
                o[tt][3] += b0*c0.w + b1*c1.w + b2*c2.w + b3*c3.w;
            }
        }
    }
    #pragma unroll
    for (int tt=0;tt<4;tt++) {
        int t = tbase + tt;
        uint2 hv;
        hv.x = pack2h(o[tt][0], o[tt][1]);
        hv.y = pack2h(o[tt][2], o[tt][3]);
        *reinterpret_cast<uint2*>(g_sh + (size_t)(b*SEQ+t)*DM + hh*DH + lane*4) = hv;
    }
}

// ---------------- final slice ------------------------------------------------
__global__ void slice_kernel(float* __restrict__ out) {
    int idx = blockIdx.x*256 + threadIdx.x;
    const int total = BSZ*NTOK*(DOUT/4);
    if (idx >= total) return;
    int row = idx >> 4;
    int c4  = idx & 15;
    int b = row / NTOK, t = row - b*NTOK;
    reinterpret_cast<float4*>(out)[idx] =
        reinterpret_cast<const float4*>(g_of)[(size_t)(b*SEQ+t)*16 + c4];
}

// ---------------- host ---------------------------------------------------
static inline void tc_gemm(cudaStream_t st, const fp16* A, const fp16* B,
                           const float* bias, const float* res,
                           float* C, fp16* Ch, int N, int K, int act) {
    dim3 grid((N + 127) / 128, BSZ*MTPB);
    tc_gemm_kernel<<<grid, 256, GEMM_SMEM, st>>>(A, B, bias, res, C, Ch, N, K, act);
}

extern "C" void kernel_launch(void* const* d_in, const int* in_sizes, int n_in,
                              void* d_out, int out_size) {
    const float* x    = (const float*)d_in[0];
    const float* W1   = (const float*)d_in[1];
    const float* b1   = (const float*)d_in[2];
    const float* ln1g = (const float*)d_in[3];
    const float* ln1b = (const float*)d_in[4];
    const float* Wq   = (const float*)d_in[5];
    const float* Wk   = (const float*)d_in[6];
    const float* Wv   = (const float*)d_in[7];
    const float* Wo   = (const float*)d_in[8];
    const float* bo   = (const float*)d_in[9];
    const float* ln2g = (const float*)d_in[10];
    const float* ln2b = (const float*)d_in[11];
    const float* Wf1  = (const float*)d_in[12];
    const float* bf1  = (const float*)d_in[13];
    const float* Wf2  = (const float*)d_in[14];
    const float* bf2  = (const float*)d_in[15];
    const float* W2   = (const float*)d_in[16];
    const float* b2   = (const float*)d_in[17];
    float* out = (float*)d_out;

    static int init_done = 0;
    static cudaStream_t st1, st2;
    static cudaEvent_t evStart, evT1, evQKV, evPad, evLin;
    if (!init_done) {
        cudaFuncSetAttribute(tc_gemm_kernel, cudaFuncAttributeMaxDynamicSharedMemorySize, GEMM_SMEM);
        cudaStreamCreateWithFlags(&st1, cudaStreamNonBlocking);
        cudaStreamCreateWithFlags(&st2, cudaStreamNonBlocking);
        cudaEventCreateWithFlags(&evStart, cudaEventDisableTiming);
        cudaEventCreateWithFlags(&evT1,    cudaEventDisableTiming);
        cudaEventCreateWithFlags(&evQKV,   cudaEventDisableTiming);
        cudaEventCreateWithFlags(&evPad,   cudaEventDisableTiming);
        cudaEventCreateWithFlags(&evLin,   cudaEventDisableTiming);
        init_done = 1;
    }

    float *h,*q,*k,*v,*of;
    fp16 *sh,*s2h;
    fp16 *w1h,*wqh,*wkh,*wvh,*woh,*wf1h,*wf2h,*w2h;
    cudaGetSymbolAddress((void**)&h,    g_h);
    cudaGetSymbolAddress((void**)&q,    g_q);
    cudaGetSymbolAddress((void**)&k,    g_k);
    cudaGetSymbolAddress((void**)&v,    g_v);
    cudaGetSymbolAddress((void**)&of,   g_of);
    cudaGetSymbolAddress((void**)&sh,   g_sh);
    cudaGetSymbolAddress((void**)&s2h,  g_s2h);
    cudaGetSymbolAddress((void**)&w1h,  g_w1h);
    cudaGetSymbolAddress((void**)&wqh,  g_wqh);
    cudaGetSymbolAddress((void**)&wkh,  g_wkh);
    cudaGetSymbolAddress((void**)&wvh,  g_wvh);
    cudaGetSymbolAddress((void**)&woh,  g_woh);
    cudaGetSymbolAddress((void**)&wf1h, g_wf1h);
    cudaGetSymbolAddress((void**)&wf2h, g_wf2h);
    cudaGetSymbolAddress((void**)&w2h,  g_w2h);

    dim3 tb(32, 8);

    // fork: pad-row chain (st2) and weight transposes (st1)
    cudaEventRecord(evStart, 0);
    cudaStreamWaitEvent(st2, evStart, 0);
    pad_ln_kernel<<<1, 512, 0, st2>>>(b1, ln1g, ln1b);
    pad_kv_kernel<<<4, 256, 0, st2>>>(Wk, Wv);
    padfill_kernel<<<(BSZ*(SEQ-NTOK)*(DM/4) + 255)/256, 256, 0, st2>>>();
    cudaEventRecord(evPad, st2);

    cudaStreamWaitEvent(st1, evStart, 0);
    transpose_h_kernel<<<dim3(DM/32,  DM/32),  tb, 0, st1>>>(Wq,  wqh,  DM,  DM);
    transpose_h_kernel<<<dim3(DM/32,  DM/32),  tb, 0, st1>>>(Wk,  wkh,  DM,  DM);
    transpose_h_kernel<<<dim3(DM/32,  DM/32),  tb, 0, st1>>>(Wv,  wvh,  DM,  DM);
    transpose_h_kernel<<<dim3(DM/32,  DM/32),  tb, 0, st1>>>(Wo,  woh,  DM,  DM);
    transpose_h_kernel<<<dim3(DFF/32, DM/32),  tb, 0, st1>>>(Wf1, wf1h, DM,  DFF);
    transpose_h_kernel<<<dim3(DM/32,  DFF/32), tb, 0, st1>>>(Wf2, wf2h, DFF, DM);
    transpose_h_kernel<<<dim3(DOUT/32,DM/32),  tb, 0, st1>>>(W2,  w2h,  DM,  DOUT);
    cudaEventRecord(evT1, st1);

    // main stream
    transpose_h_kernel<<<dim3(DM/32, DIN/32), tb>>>(W1, w1h, DIN, DM);
    pad_split_kernel<<<(BSZ*NTOK*(DIN/4) + 255)/256, 256>>>(x);
    tc_gemm(0, sh, w1h, b1, nullptr, h, nullptr, DM, DIN, 1);
    ln_kernel<<<BSZ*NTOK/8, 256>>>(h, ln1g, ln1b);
    cudaStreamWaitEvent(0, evT1, 0);
    tc_gemm(0, sh, wqh, nullptr, nullptr, q, nullptr, DM, DM, 0);
    tc_gemm(0, sh, wkh, nullptr, nullptr, k, nullptr, DM, DM, 0);
    tc_gemm(0, sh, wvh, nullptr, nullptr, v, nullptr, DM, DM, 0);
    cudaEventRecord(evQKV, 0);

    // linear-attn chain on st1, local attention on main stream
    cudaStreamWaitEvent(st1, evQKV, 0);
    cudaStreamWaitEvent(st1, evPad, 0);
    kstats_kernel<<<dim3(BSZ*3,4), dim3(32,8), 0, st1>>>();
    ctx_partial_kernel<<<dim3(BSZ*3,8), 256, 0, st1>>>();
    ctx_reduce_kernel<<<(BSZ*3*DH*DH + 255)/256, 256, 0, st1>>>();
    lin_out_kernel<<<dim3(BSZ*3, 94), 256, 0, st1>>>();
    cudaEventRecord(evLin, st1);

    cudaStreamWaitEvent(0, evPad, 0);
    local_attn_kernel<<<BSZ*94, 1024>>>();
    cudaStreamWaitEvent(0, evLin, 0);

    // tail on main stream
    tc_gemm(0, sh, woh, bo, h, h, nullptr, DM, DM, 0);
    ln_kernel<<<BSZ*NTOK/8, 256>>>(h, ln2g, ln2b);
    tc_gemm(0, sh, wf1h, bf1, nullptr, nullptr, s2h, DFF, DM, 2);
    tc_gemm(0, s2h, wf2h, bf2, h, nullptr, sh, DM, DFF, 0);
    tc_gemm(0, sh, w2h, b2, nullptr, of, nullptr, DOUT, DM, 0);
    slice_kernel<<<(BSZ*NTOK*(DOUT/4) + 255)/256, 256>>>(out);
}

// round 9
// speedup vs baseline: 4.7275x; 1.1126x over previous
#include <cuda_runtime.h>
#include <cuda_fp16.h>
#include <math.h>
#include <stdint.h>

#define BSZ   8
#define SEQ   4096
#define NTOK  3000
#define DIN   128
#define DM    512
#define DFF   2048
#define DOUT  64
#define DH    128
#define MTOT  (BSZ*SEQ)
#define MTPB  24                     // M-tiles per batch: ceil(3000/128)
#define SCALE 0.08838834764831845f   // 1/sqrt(128)
#define GEMM_SMEM (3*16384)          // 3 stages x 2 arrays x 128 x 64B (swizzled)
#define EXPF(x) __expf(x)

typedef __half fp16;

// ---------------- scratch (static device globals: no allocation) -------------
__device__ float g_h[MTOT*DM];
__device__ float g_q[MTOT*DM];
__device__ float g_k[MTOT*DM];
__device__ float g_v[MTOT*DM];
__device__ float g_kmax[BSZ*3*DH];
__device__ float g_lsep[BSZ*3*8*DH];
__device__ float g_ctxp[BSZ*3*8*DH*DH];
__device__ float g_ctx[BSZ*3*DH*DH];
__device__ float g_lnpad[DM];
__device__ float g_kpad[DM];
__device__ float g_vpad[DM];
// fp16 activation buffers
__device__ fp16 g_sh[MTOT*DM];
__device__ fp16 g_s2h[MTOT*DFF];
// transposed weights [N][K], fp16
__device__ fp16 g_w1h[DM*DIN];
__device__ fp16 g_wqh[DM*DM];
__device__ fp16 g_wkh[DM*DM];
__device__ fp16 g_wvh[DM*DM];
__device__ fp16 g_woh[DM*DM];
__device__ fp16 g_wf1h[DFF*DM];
__device__ fp16 g_wf2h[DM*DFF];
__device__ fp16 g_w2h[DOUT*DM];

// ---------------- helpers ----------------
__device__ __forceinline__ uint32_t smem_u32(const void* p) {
    uint32_t a;
    asm("{ .reg .u64 t; cvta.to.shared.u64 t, %1; cvt.u32.u64 %0, t; }" : "=r"(a) : "l"(p));
    return a;
}
__device__ __forceinline__ uint32_t pack2h(float x, float y) {
    __half2 h = __floats2half2_rn(x, y);
    return *reinterpret_cast<uint32_t*>(&h);
}

#define LDSM_X4(r0,r1,r2,r3,addr) \
    asm volatile("ldmatrix.sync.aligned.m8n8.x4.shared.b16 {%0,%1,%2,%3}, [%4];" \
        : "=r"(r0),"=r"(r1),"=r"(r2),"=r"(r3) : "r"(addr))
#define MMA16816(d, a0,a1,a2,a3, b0,b1) \
    asm volatile("mma.sync.aligned.m16n8k16.row.col.f32.f16.f16.f32 " \
        "{%0,%1,%2,%3},{%4,%5,%6,%7},{%8,%9},{%0,%1,%2,%3};" \
        : "+f"((d)[0]),"+f"((d)[1]),"+f"((d)[2]),"+f"((d)[3]) \
        : "r"(a0),"r"(a1),"r"(a2),"r"(a3),"r"(b0),"r"(b1))
#define CP_ASYNC16(dst, src, sz) \
    asm volatile("cp.async.cg.shared.global [%0], [%1], 16, %2;" :: "r"(dst), "l"(src), "r"(sz))
#define CP_COMMIT()  asm volatile("cp.async.commit_group;" ::: "memory")
#define CP_WAIT0()   asm volatile("cp.async.wait_group 0;" ::: "memory")
#define CP_WAIT1()   asm volatile("cp.async.wait_group 1;" ::: "memory")

// ---------------- weight transpose + fp16: T[n][k] = h(W[k][n]) --------------
__global__ void transpose_h_kernel(const float* __restrict__ W,
                                   fp16* __restrict__ Th, int K, int N) {
    __shared__ float t[32][33];
    int bx = blockIdx.x * 32, by = blockIdx.y * 32;
    int x = bx + threadIdx.x;
    #pragma unroll
    for (int i = 0; i < 32; i += 8) {
        int y = by + threadIdx.y + i;
        if (x < N && y < K) t[threadIdx.y + i][threadIdx.x] = W[(size_t)y * N + x];
    }
    __syncthreads();
    int xk = by + threadIdx.x;
    #pragma unroll
    for (int i = 0; i < 32; i += 8) {
        int yn = bx + threadIdx.y + i;
        if (xk < K && yn < N)
            Th[(size_t)yn * K + xk] = __float2half_rn(t[threadIdx.x][threadIdx.y + i]);
    }
}

// ---------------- x (real rows only) -> g_sh fp16 ----------------------------
__global__ void pad_split_kernel(const float* __restrict__ x) {
    int idx = blockIdx.x*256 + threadIdx.x;
    const int total = BSZ*NTOK*(DIN/4);
    if (idx >= total) return;
    int rr = idx >> 5;
    int c4 = idx & 31;
    int b = rr / NTOK, t = rr - b*NTOK;
    float4 val = reinterpret_cast<const float4*>(x)[(size_t)rr*32 + c4];
    uint2 hv;
    hv.x = pack2h(val.x, val.y);
    hv.y = pack2h(val.z, val.w);
    *reinterpret_cast<uint2*>(g_sh + (size_t)(b*SEQ + t)*DIN + c4*4) = hv;
}

// ---------------- pad-row LN: lnpad = LN(tanh(b1)) ---------------------------
__global__ void pad_ln_kernel(const float* __restrict__ b1, const float* __restrict__ gam,
                              const float* __restrict__ bet) {
    __shared__ float ss[16], ss2[16], stat[2];
    int t = threadIdx.x;
    float h = tanhf(b1[t]);
    float s = h, s2 = h*h;
    #pragma unroll
    for (int o=16;o;o>>=1) { s += __shfl_xor_sync(~0u,s,o); s2 += __shfl_xor_sync(~0u,s2,o); }
    if ((t & 31) == 0) { ss[t>>5] = s; ss2[t>>5] = s2; }
    __syncthreads();
    if (t == 0) {
        float S=0.f, S2=0.f;
        #pragma unroll
        for (int i=0;i<16;i++) { S += ss[i]; S2 += ss2[i]; }
        float mu = S*(1.f/512.f);
        float var = S2*(1.f/512.f) - mu*mu;
        stat[0] = mu; stat[1] = rsqrtf(var + 1e-5f);
    }
    __syncthreads();
    g_lnpad[t] = (h - stat[0])*stat[1]*gam[t] + bet[t];
}

// ---------------- pad-row k/v ------------------------------------------------
__global__ void pad_kv_kernel(const float* __restrict__ Wk, const float* __restrict__ Wv) {
    int d = blockIdx.x*256 + threadIdx.x;
    if (d >= 2*DM) return;
    const float* W = (d < DM) ? Wk : Wv;
    int dd = d & (DM-1);
    float s = 0.f;
    for (int kk = 0; kk < DM; kk++) s += g_lnpad[kk] * W[(size_t)kk*DM + dd];
    if (d < DM) g_kpad[dd] = s; else g_vpad[dd] = s;
}

// ---------------- broadcast pad k/v rows -------------------------------------
__global__ void padfill_kernel() {
    int idx = blockIdx.x*256 + threadIdx.x;
    const int per = (SEQ-NTOK)*(DM/4);
    if (idx >= BSZ*per) return;
    int b = idx / per, r = idx - b*per;
    int t = NTOK + r/(DM/4), c4 = r % (DM/4);
    size_t off = (size_t)(b*SEQ + t)*DM + c4*4;
    *reinterpret_cast<float4*>(g_k + off) = *reinterpret_cast<const float4*>(g_kpad + c4*4);
    *reinterpret_cast<float4*>(g_v + off) = *reinterpret_cast<const float4*>(g_vpad + c4*4);
}

// ---------------- fp16 single-product tensor-core GEMM (real rows) -----------
// C = act(A @ B^T + bias) + res. omul: output row = b*omul + t (SEQ or NTOK).
__global__ __launch_bounds__(256, 2) void tc_gemm_kernel(
    const fp16* __restrict__ A, const fp16* __restrict__ B,
    const float* __restrict__ bias, const float* __restrict__ res,
    float* __restrict__ C, fp16* __restrict__ Ch,
    int N, int K, int act, int omul)
{
    extern __shared__ __align__(1024) char smc[];
    uint32_t sbase = smem_u32(smc);
    int tid = threadIdx.x;
    int mtile = blockIdx.y;
    int bb = mtile / MTPB, t0 = (mtile - bb*MTPB) << 7;
    int bm = bb*SEQ + t0;
    int alim = NTOK - t0;
    int rowlim = bm + alim;
    int odelta = bb*(omul - SEQ);   // out row = r + odelta
    int bn = blockIdx.x << 7;
    int lane = tid & 31, w = tid >> 5;
    int wm = w & 1, wn = w >> 1;
    int grp = lane >> 2, qp = lane & 3;

    uint32_t swz = (lane >> 1) & 3;
    uint32_t a_base = (uint32_t)(wm*64 + (lane & 15))*64 + (((uint32_t)(lane >> 4) ^ swz) << 4);
    uint32_t b_base = (uint32_t)(wn*32 + ((lane >> 4) & 1)*8 + (lane & 7))*64
                    + ((((uint32_t)(lane >> 3) & 1) ^ swz) << 4);

    float acc[4][4][4];
    #pragma unroll
    for (int i=0;i<4;i++)
        #pragma unroll
        for (int j=0;j<4;j++)
            #pragma unroll
            for (int r=0;r<4;r++) acc[i][j][r] = 0.f;

    const int NC = K >> 5;

    #define STAGE_LOAD(c_, buf_) do { \
        int k0 = (c_) << 5; \
        uint32_t sb = sbase + (uint32_t)(buf_)*16384u; \
        _Pragma("unroll") \
        for (int i_ = 0; i_ < 4; i_++) { \
            const int arr_ = i_ >> 1; \
            int j_ = ((i_ & 1) << 8) + tid; \
            int r_ = j_ >> 2, cc_ = j_ & 3; \
            uint32_t dst_ = sb + arr_*8192u + (uint32_t)r_*64u \
                          + ((uint32_t)(cc_ ^ ((r_ >> 1) & 3)) << 4); \
            const fp16* g_; int sz_ = 16; \
            if (arr_ == 0) { \
                if (r_ < alim) g_ = A + (size_t)(bm + r_)*K + k0 + cc_*8; \
                else { g_ = A; sz_ = 0; } \
            } else { \
                int rowv_ = bn + r_; \
                if (rowv_ < N) g_ = B + (size_t)rowv_*K + k0 + cc_*8; \
                else { g_ = B; sz_ = 0; } \
            } \
            CP_ASYNC16(dst_, g_, sz_); \
        } \
        CP_COMMIT(); \
    } while (0)

    STAGE_LOAD(0, 0);
    if (NC > 1) STAGE_LOAD(1, 1);

    int buf = 0, bufn = 2;
    for (int c = 0; c < NC; c++) {
        if (c + 1 < NC) CP_WAIT1(); else CP_WAIT0();
        __syncthreads();
        if (c + 2 < NC) {
            STAGE_LOAD(c + 2, bufn);
            bufn = (bufn == 2) ? 0 : bufn + 1;
        }
        uint32_t sA = sbase + (uint32_t)buf*16384u;
        uint32_t sB = sA + 8192u;
        buf = (buf == 2) ? 0 : buf + 1;

        #pragma unroll
        for (int ks = 0; ks < 2; ks++) {
            uint32_t kx = ks ? 32u : 0u;
            uint32_t bh[4][2], a[4][4];
            #pragma unroll
            for (int p = 0; p < 2; p++)
                LDSM_X4(bh[2*p][0], bh[2*p][1], bh[2*p+1][0], bh[2*p+1][1],
                        sB + ((b_base + p*1024u) ^ kx));
            #pragma unroll
            for (int mt = 0; mt < 4; mt++)
                LDSM_X4(a[mt][0], a[mt][1], a[mt][2], a[mt][3],
                        sA + ((a_base + mt*1024u) ^ kx));
            #pragma unroll
            for (int mt = 0; mt < 4; mt++)
                #pragma unroll
                for (int nt = 0; nt < 4; nt++)
                    MMA16816(acc[mt][nt], a[mt][0],a[mt][1],a[mt][2],a[mt][3], bh[nt][0],bh[nt][1]);
        }
    }
    #undef STAGE_LOAD

    // ---- epilogue (valid rows only) ----
    #pragma unroll
    for (int mt = 0; mt < 4; mt++) {
        #pragma unroll
        for (int nt = 0; nt < 4; nt++) {
            int c0 = bn + wn*32 + nt*8 + qp*2;
            if (c0 >= N) continue;
            int rbase = bm + wm*64 + mt*16 + grp;
            float bs0 = 0.f, bs1 = 0.f;
            if (bias) { bs0 = bias[c0]; bs1 = bias[c0 + 1]; }
            #pragma unroll
            for (int half = 0; half < 2; half++) {
                int r = rbase + half*8;
                if (r >= rowlim) continue;
                float v0 = acc[mt][nt][half*2 + 0] + bs0;
                float v1 = acc[mt][nt][half*2 + 1] + bs1;
                if (act == 1) { v0 = tanhf(v0); v1 = tanhf(v1); }
                else if (act == 2) {
                    v0 = 0.5f*v0*(1.f + erff(v0*0.7071067811865476f));
                    v1 = 0.5f*v1*(1.f + erff(v1*0.7071067811865476f));
                }
                if (res) {
                    v0 += res[(size_t)r*N + c0];
                    v1 += res[(size_t)r*N + c0 + 1];
                }
                size_t orow = (size_t)(r + odelta);
                if (Ch) {
                    *reinterpret_cast<uint32_t*>(Ch + orow*N + c0) = pack2h(v0, v1);
                } else {
                    float2 o; o.x = v0; o.y = v1;
                    *reinterpret_cast<float2*>(C + orow*N + c0) = o;
                }
            }
        }
    }
}

// ---------------- LayerNorm (real rows) -> fp16 ------------------------------
__global__ void ln_kernel(const float* __restrict__ in, const float* __restrict__ gam,
                          const float* __restrict__ bet) {
    int gw = (blockIdx.x*blockDim.x + threadIdx.x) >> 5;
    int lane = threadIdx.x & 31;
    if (gw >= BSZ*NTOK) return;
    int b = gw / NTOK, t = gw - b*NTOK;
    size_t row = (size_t)(b*SEQ + t);
    const float4* rp = reinterpret_cast<const float4*>(in + row*DM);
    float4 v[4];
    float s=0.f, s2=0.f;
    #pragma unroll
    for (int i=0;i<4;i++) {
        v[i] = rp[lane + 32*i];
        s  += v[i].x+v[i].y+v[i].z+v[i].w;
        s2 += v[i].x*v[i].x + v[i].y*v[i].y + v[i].z*v[i].z + v[i].w*v[i].w;
    }
    #pragma unroll
    for (int o=16;o;o>>=1) { s += __shfl_xor_sync(~0u,s,o); s2 += __shfl_xor_sync(~0u,s2,o); }
    float mu  = s*(1.f/512.f);
    float var = s2*(1.f/512.f) - mu*mu;
    float r = rsqrtf(var + 1e-5f);
    #pragma unroll
    for (int i=0;i<4;i++) {
        int c = (lane + 32*i)*4;
        float4 g4 = *reinterpret_cast<const float4*>(gam + c);
        float4 b4 = *reinterpret_cast<const float4*>(bet + c);
        uint2 hv;
        hv.x = pack2h((v[i].x-mu)*r*g4.x + b4.x, (v[i].y-mu)*r*g4.y + b4.y);
        hv.y = pack2h((v[i].z-mu)*r*g4.z + b4.z, (v[i].w-mu)*r*g4.w + b4.w);
        *reinterpret_cast<uint2*>(g_sh + row*DM + c) = hv;
    }
}

// ---------------- local attention, head 0 (real queries) ---------------------
__global__ __launch_bounds__(1024) void local_attn_kernel() {
    __shared__ float tile[64][DH];
    __shared__ float scores[32][64];
    int b   = blockIdx.x / 94;
    int blk = blockIdx.x - b*94;
    int win = blk >> 2;
    int qc  = blk & 3;
    int warp = threadIdx.x >> 5, lane = threadIdx.x & 31;
    int qt = win*128 + qc*32 + warp;
    size_t qoff = (size_t)(b*SEQ + qt)*DM;
    float4 q4 = *reinterpret_cast<const float4*>(g_q + qoff + lane*4);
    float m = -1e30f, l = 0.f;
    float4 acc = make_float4(0.f,0.f,0.f,0.f);
    int kbase = win*128 - 128;
    for (int ch=0; ch<6; ch++) {
        int t0 = kbase + ch*64;
        __syncthreads();
        #pragma unroll
        for (int it=0; it<2; it++) {
            int idx = it*1024 + threadIdx.x;
            int r = idx >> 5, c4 = idx & 31;
            int t = t0 + r;
            float4 kv = make_float4(0.f,0.f,0.f,0.f);
            if (t >= 0 && t < SEQ)
                kv = *reinterpret_cast<const float4*>(g_k + (size_t)(b*SEQ+t)*DM + c4*4);
            *reinterpret_cast<float4*>(&tile[r][c4*4]) = kv;
        }
        __syncthreads();
        for (int j=0; j<64; j++) {
            float4 kv = *reinterpret_cast<const float4*>(&tile[j][lane*4]);
            float s = q4.x*kv.x + q4.y*kv.y + q4.z*kv.z + q4.w*kv.w;
            #pragma unroll
            for (int o=16;o;o>>=1) s += __shfl_xor_sync(~0u,s,o);
            if (lane == (j & 31)) {
                int t = t0 + j;
                scores[warp][j] = (t >= 0 && t < SEQ) ? s*SCALE : -1e38f;
            }
        }
        __syncthreads();
        #pragma unroll
        for (int it=0; it<2; it++) {
            int idx = it*1024 + threadIdx.x;
            int r = idx >> 5, c4 = idx & 31;
            int t = t0 + r;
            float4 vv = make_float4(0.f,0.f,0.f,0.f);
            if (t >= 0 && t < SEQ)
                vv = *reinterpret_cast<const float4*>(g_v + (size_t)(b*SEQ+t)*DM + c4*4);
            *reinterpret_cast<float4*>(&tile[r][c4*4]) = vv;
        }
        __syncthreads();
        float s0 = scores[warp][lane], s1 = scores[warp][lane+32];
        float cm = fmaxf(s0, s1);
        #pragma unroll
        for (int o=16;o;o>>=1) cm = fmaxf(cm, __shfl_xor_sync(~0u,cm,o));
        float mn = fmaxf(m, cm);
        float corr = EXPF(m - mn);
        l *= corr; acc.x*=corr; acc.y*=corr; acc.z*=corr; acc.w*=corr;
        float p0 = EXPF(s0 - mn), p1 = EXPF(s1 - mn);
        l += p0 + p1;
        scores[warp][lane] = p0; scores[warp][lane+32] = p1;
        __syncwarp();
        for (int j=0; j<64; j++) {
            float p = scores[warp][j];
            float4 vv = *reinterpret_cast<const float4*>(&tile[j][lane*4]);
            acc.x = fmaf(p, vv.x, acc.x);
            acc.y = fmaf(p, vv.y, acc.y);
            acc.z = fmaf(p, vv.z, acc.z);
            acc.w = fmaf(p, vv.w, acc.w);
        }
        m = mn;
    }
    #pragma unroll
    for (int o=16;o;o>>=1) l += __shfl_xor_sync(~0u,l,o);
    float inv = 1.f/l;
    uint2 hv;
    hv.x = pack2h(acc.x*inv, acc.y*inv);
    hv.y = pack2h(acc.z*inv, acc.w*inv);
    *reinterpret_cast<uint2*>(g_sh + qoff + lane*4) = hv;
}

// ---------------- k column max (heads 1..3) — no exp -------------------------
__global__ void kmax_kernel() {
    int bh = blockIdx.x;
    int b = bh/3, hh = bh%3 + 1;
    int d = blockIdx.y*32 + threadIdx.x;
    int ty = threadIdx.y;
    int col = hh*DH + d;
    float m = -1e30f;
    for (int t = ty; t < SEQ; t += 8)
        m = fmaxf(m, g_k[(size_t)(b*SEQ+t)*DM + col]);
    __shared__ float sm[8][32];
    sm[ty][threadIdx.x] = m;
    __syncthreads();
    if (ty == 0) {
        #pragma unroll
        for (int r=1;r<8;r++) m = fmaxf(m, sm[r][threadIdx.x]);
        g_kmax[bh*DH + d] = m;
    }
}

// ---------------- ctx partial: unnormalized e@v + lse partials ---------------
__global__ __launch_bounds__(256) void ctx_partial_kernel() {
    __shared__ float kt[32][132];
    __shared__ float vt[32][132];
    __shared__ float smax[DH];
    int bh = blockIdx.x, ks = blockIdx.y;
    int b = bh/3, hh = bh%3 + 1;
    if (threadIdx.x < DH)
        smax[threadIdx.x] = g_kmax[bh*DH + threadIdx.x];
    int tx = threadIdx.x & 15, ty = threadIdx.x >> 4;
    int lr0 = threadIdx.x >> 5, lc4 = threadIdx.x & 31;   // load indices
    float acc[8][8];
    float4 lacc = make_float4(0.f,0.f,0.f,0.f);           // lse partial for d=lc4*4..+3
    #pragma unroll
    for (int i=0;i<8;i++)
        #pragma unroll
        for (int j=0;j<8;j++) acc[i][j]=0.f;

    for (int t0=0; t0<512; t0+=32) {
        __syncthreads();
        #pragma unroll
        for (int i=0;i<4;i++) {
            int r = lr0 + 8*i;
            int t = ks*512 + t0 + r;
            size_t off = (size_t)(b*SEQ+t)*DM + hh*DH + lc4*4;
            float4 kv = *reinterpret_cast<const float4*>(g_k + off);
            float4 vv = *reinterpret_cast<const float4*>(g_v + off);
            int d0 = lc4*4;
            float e0 = EXPF(kv.x - smax[d0+0]);
            float e1 = EXPF(kv.y - smax[d0+1]);
            float e2 = EXPF(kv.z - smax[d0+2]);
            float e3 = EXPF(kv.w - smax[d0+3]);
            kt[r][d0+0] = e0; kt[r][d0+1] = e1; kt[r][d0+2] = e2; kt[r][d0+3] = e3;
            lacc.x += e0; lacc.y += e1; lacc.z += e2; lacc.w += e3;
            *reinterpret_cast<float4*>(&vt[r][d0]) = vv;
        }
        __syncthreads();
        #pragma unroll
        for (int kk=0; kk<32; kk++) {
            float a[8], bb[8];
            *reinterpret_cast<float4*>(&a[0])  = *reinterpret_cast<const float4*>(&kt[kk][ty*8]);
            *reinterpret_cast<float4*>(&a[4])  = *reinterpret_cast<const float4*>(&kt[kk][ty*8+4]);
            *reinterpret_cast<float4*>(&bb[0]) = *reinterpret_cast<const float4*>(&vt[kk][tx*8]);
            *reinterpret_cast<float4*>(&bb[4]) = *reinterpret_cast<const float4*>(&vt[kk][tx*8+4]);
            #pragma unroll
            for (int i=0;i<8;i++)
                #pragma unroll
                for (int j=0;j<8;j++)
                    acc[i][j] = fmaf(a[i], bb[j], acc[i][j]);
        }
    }
    // lse partial reduce: 8 row-groups per d
    __syncthreads();
    *reinterpret_cast<float4*>(&kt[lr0][lc4*4]) = lacc;
    __syncthreads();
    if (threadIdx.x < DH) {
        float s = 0.f;
        #pragma unroll
        for (int j=0;j<8;j++) s += kt[j][threadIdx.x];
        g_lsep[(bh*8 + ks)*DH + threadIdx.x] = s;
    }
    float* op = g_ctxp + ((size_t)bh*8 + ks)*DH*DH;
    #pragma unroll
    for (int i=0;i<8;i++)
        #pragma unroll
        for (int j=0;j<8;j+=4) {
            float4 o4 = make_float4(acc[i][j],acc[i][j+1],acc[i][j+2],acc[i][j+3]);
            *reinterpret_cast<float4*>(op + (size_t)(ty*8+i)*DH + tx*8 + j) = o4;
        }
}

// ---------------- ctx reduce + normalize by lse ------------------------------
__global__ void ctx_reduce_kernel() {
    int idx = blockIdx.x*256 + threadIdx.x;
    if (idx >= BSZ*3*DH*DH) return;
    int bh = idx / (DH*DH);
    int de = idx - bh*DH*DH;
    int d = de >> 7;                 // row index (DH=128)
    float s = 0.f, ls = 0.f;
    #pragma unroll
    for (int ks=0;ks<8;ks++) {
        s  += g_ctxp[((size_t)bh*8+ks)*DH*DH + de];
        ls += g_lsep[(bh*8+ks)*DH + d];
    }
    g_ctx[idx] = s / ls;
}

// ---------------- linear-attn output -> fp16 ---------------------------------
__global__ __launch_bounds__(256) void lin_out_kernel() {
    __shared__ float sctx[64][DH];
    int bh = blockIdx.x;
    int b = bh/3, hh = bh%3 + 1;
    int warp = threadIdx.x >> 5, lane = threadIdx.x & 31;
    const float* ctxp = g_ctx + (size_t)bh*DH*DH;
    float pr[4][4], o[4][4];
    int tbase = blockIdx.y*32 + warp*4;
    #pragma unroll
    for (int tt=0;tt<4;tt++) {
        int t = tbase + tt;
        const float* qp = g_q + (size_t)(b*SEQ+t)*DM + hh*DH;
        float4 q4 = *reinterpret_cast<const float4*>(qp + lane*4);
        float mx = fmaxf(fmaxf(q4.x,q4.y),fmaxf(q4.z,q4.w));
        #pragma unroll
        for (int s=16;s;s>>=1) mx = fmaxf(mx, __shfl_xor_sync(~0u,mx,s));
        float e0=EXPF(q4.x-mx), e1=EXPF(q4.y-mx), e2=EXPF(q4.z-mx), e3=EXPF(q4.w-mx);
        float sm = e0+e1+e2+e3;
        #pragma unroll
        for (int s=16;s;s>>=1) sm += __shfl_xor_sync(~0u,sm,s);
        float inv = SCALE/sm;
        pr[tt][0]=e0*inv; pr[tt][1]=e1*inv; pr[tt][2]=e2*inv; pr[tt][3]=e3*inv;
        o[tt][0]=0.f; o[tt][1]=0.f; o[tt][2]=0.f; o[tt][3]=0.f;
    }
    for (int ph=0; ph<2; ph++) {
        __syncthreads();
        #pragma unroll
        for (int i=0;i<8;i++) {
            int idx = i*256 + threadIdx.x;
            int r = idx >> 5, c4 = idx & 31;
            *reinterpret_cast<float4*>(&sctx[r][c4*4]) =
                *reinterpret_cast<const float4*>(ctxp + (size_t)(ph*64+r)*DH + c4*4);
        }
        __syncthreads();
        #pragma unroll
        for (int dl=0; dl<16; dl++) {
            int src = ph*16 + dl;
            #pragma unroll
            for (int tt=0;tt<4;tt++) {
                float b0 = __shfl_sync(~0u, pr[tt][0], src);
                float b1 = __shfl_sync(~0u, pr[tt][1], src);
                float b2 = __shfl_sync(~0u, pr[tt][2], src);
                float b3 = __shfl_sync(~0u, pr[tt][3], src);
                float4 c0 = *reinterpret_cast<const float4*>(&sctx[dl*4+0][lane*4]);
                float4 c1 = *reinterpret_cast<const float4*>(&sctx[dl*4+1][lane*4]);
                float4 c2 = *reinterpret_cast<const float4*>(&sctx[dl*4+2][lane*4]);
                float4 c3 = *reinterpret_cast<const float4*>(&sctx[dl*4+3][lane*4]);
                o[tt][0] += b0*c0.x + b1*c1.x + b2*c2.x + b3*c3.x;
                o[tt][1] += b0*c0.y + b1*c1.y + b2*c2.y + b3*c3.y;
                o[tt][2] += b0*c0.z + b1*c1.z + b2*c2.z + b3*c3.z;
                o[tt][3] += b0*c0.w + b1*c1.w + b2*c2.w + b3*c3.w;
            }
        }
    }
    #pragma unroll
    for (int tt=0;tt<4;tt++) {
        int t = tbase + tt;
        uint2 hv;
        hv.x = pack2h(o[tt][0], o[tt][1]);
        hv.y = pack2h(o[tt][2], o[tt][3]);
        *reinterpret_cast<uint2*>(g_sh + (size_t)(b*SEQ+t)*DM + hh*DH + lane*4) = hv;
    }
}

// ---------------- host ---------------------------------------------------
static inline void tc_gemm(cudaStream_t st, const fp16* A, const fp16* B,
                           const float* bias, const float* res,
                           float* C, fp16* Ch, int N, int K, int act, int omul = SEQ) {
    dim3 grid((N + 127) / 128, BSZ*MTPB);
    tc_gemm_kernel<<<grid, 256, GEMM_SMEM, st>>>(A, B, bias, res, C, Ch, N, K, act, omul);
}

extern "C" void kernel_launch(void* const* d_in, const int* in_sizes, int n_in,
                              void* d_out, int out_size) {
    const float* x    = (const float*)d_in[0];
    const float* W1   = (const float*)d_in[1];
    const float* b1   = (const float*)d_in[2];
    const float* ln1g = (const float*)d_in[3];
    const float* ln1b = (const float*)d_in[4];
    const float* Wq   = (const float*)d_in[5];
    const float* Wk   = (const float*)d_in[6];
    const float* Wv   = (const float*)d_in[7];
    const float* Wo   = (const float*)d_in[8];
    const float* bo   = (const float*)d_in[9];
    const float* ln2g = (const float*)d_in[10];
    const float* ln2b = (const float*)d_in[11];
    const float* Wf1  = (const float*)d_in[12];
    const float* bf1  = (const float*)d_in[13];
    const float* Wf2  = (const float*)d_in[14];
    const float* bf2  = (const float*)d_in[15];
    const float* W2   = (const float*)d_in[16];
    const float* b2   = (const float*)d_in[17];
    float* out = (float*)d_out;

    static int init_done = 0;
    static cudaStream_t st1, st2;
    static cudaEvent_t evStart, evT1, evQKV, evPad, evLin;
    if (!init_done) {
        cudaFuncSetAttribute(tc_gemm_kernel, cudaFuncAttributeMaxDynamicSharedMemorySize, GEMM_SMEM);
        cudaStreamCreateWithFlags(&st1, cudaStreamNonBlocking);
        cudaStreamCreateWithFlags(&st2, cudaStreamNonBlocking);
        cudaEventCreateWithFlags(&evStart, cudaEventDisableTiming);
        cudaEventCreateWithFlags(&evT1,    cudaEventDisableTiming);
        cudaEventCreateWithFlags(&evQKV,   cudaEventDisableTiming);
        cudaEventCreateWithFlags(&evPad,   cudaEventDisableTiming);
        cudaEventCreateWithFlags(&evLin,   cudaEventDisableTiming);
        init_done = 1;
    }

    float *h,*q,*k,*v;
    fp16 *sh,*s2h;
    fp16 *w1h,*wqh,*wkh,*wvh,*woh,*wf1h,*wf2h,*w2h;
    cudaGetSymbolAddress((void**)&h,    g_h);
    cudaGetSymbolAddress((void**)&q,    g_q);
    cudaGetSymbolAddress((void**)&k,    g_k);
    cudaGetSymbolAddress((void**)&v,    g_v);
    cudaGetSymbolAddress((void**)&sh,   g_sh);
    cudaGetSymbolAddress((void**)&s2h,  g_s2h);
    cudaGetSymbolAddress((void**)&w1h,  g_w1h);
    cudaGetSymbolAddress((void**)&wqh,  g_wqh);
    cudaGetSymbolAddress((void**)&wkh,  g_wkh);
    cudaGetSymbolAddress((void**)&wvh,  g_wvh);
    cudaGetSymbolAddress((void**)&woh,  g_woh);
    cudaGetSymbolAddress((void**)&wf1h, g_wf1h);
    cudaGetSymbolAddress((void**)&wf2h, g_wf2h);
    cudaGetSymbolAddress((void**)&w2h,  g_w2h);

    dim3 tb(32, 8);

    // fork: pad-row chain (st2) and weight transposes (st1)
    cudaEventRecord(evStart, 0);
    cudaStreamWaitEvent(st2, evStart, 0);
    pad_ln_kernel<<<1, 512, 0, st2>>>(b1, ln1g, ln1b);
    pad_kv_kernel<<<4, 256, 0, st2>>>(Wk, Wv);
    padfill_kernel<<<(BSZ*(SEQ-NTOK)*(DM/4) + 255)/256, 256, 0, st2>>>();
    cudaEventRecord(evPad, st2);

    cudaStreamWaitEvent(st1, evStart, 0);
    transpose_h_kernel<<<dim3(DM/32,  DM/32),  tb, 0, st1>>>(Wq,  wqh,  DM,  DM);
    transpose_h_kernel<<<dim3(DM/32,  DM/32),  tb, 0, st1>>>(Wk,  wkh,  DM,  DM);
    transpose_h_kernel<<<dim3(DM/32,  DM/32),  tb, 0, st1>>>(Wv,  wvh,  DM,  DM);
    transpose_h_kernel<<<dim3(DM/32,  DM/32),  tb, 0, st1>>>(Wo,  woh,  DM,  DM);
    transpose_h_kernel<<<dim3(DFF/32, DM/32),  tb, 0, st1>>>(Wf1, wf1h, DM,  DFF);
    transpose_h_kernel<<<dim3(DM/32,  DFF/32), tb, 0, st1>>>(Wf2, wf2h, DFF, DM);
    transpose_h_kernel<<<dim3(DOUT/32,DM/32),  tb, 0, st1>>>(W2,  w2h,  DM,  DOUT);
    cudaEventRecord(evT1, st1);

    // main stream
    transpose_h_kernel<<<dim3(DM/32, DIN/32), tb>>>(W1, w1h, DIN, DM);
    pad_split_kernel<<<(BSZ*NTOK*(DIN/4) + 255)/256, 256>>>(x);
    tc_gemm(0, sh, w1h, b1, nullptr, h, nullptr, DM, DIN, 1);
    ln_kernel<<<BSZ*NTOK/8, 256>>>(h, ln1g, ln1b);
    cudaStreamWaitEvent(0, evT1, 0);
    tc_gemm(0, sh, wqh, nullptr, nullptr, q, nullptr, DM, DM, 0);
    tc_gemm(0, sh, wkh, nullptr, nullptr, k, nullptr, DM, DM, 0);
    tc_gemm(0, sh, wvh, nullptr, nullptr, v, nullptr, DM, DM, 0);
    cudaEventRecord(evQKV, 0);

    // linear-attn chain on st1, local attention on main stream
    cudaStreamWaitEvent(st1, evQKV, 0);
    cudaStreamWaitEvent(st1, evPad, 0);
    kmax_kernel<<<dim3(BSZ*3,4), dim3(32,8), 0, st1>>>();
    ctx_partial_kernel<<<dim3(BSZ*3,8), 256, 0, st1>>>();
    ctx_reduce_kernel<<<(BSZ*3*DH*DH + 255)/256, 256, 0, st1>>>();
    lin_out_kernel<<<dim3(BSZ*3, 94), 256, 0, st1>>>();
    cudaEventRecord(evLin, st1);

    cudaStreamWaitEvent(0, evPad, 0);
    local_attn_kernel<<<BSZ*94, 1024>>>();
    cudaStreamWaitEvent(0, evLin, 0);

    // tail on main stream
    tc_gemm(0, sh, woh, bo, h, h, nullptr, DM, DM, 0);
    ln_kernel<<<BSZ*NTOK/8, 256>>>(h, ln2g, ln2b);
    tc_gemm(0, sh, wf1h, bf1, nullptr, nullptr, s2h, DFF, DM, 2);
    tc_gemm(0, s2h, wf2h, bf2, h, nullptr, sh, DM, DFF, 0);
    tc_gemm(0, sh, w2h, b2, nullptr, out, nullptr, DOUT, DM, 0, NTOK);
}

// round 10
// speedup vs baseline: 5.1582x; 1.0911x over previous
#include <cuda_runtime.h>
#include <cuda_fp16.h>
#include <math.h>
#include <stdint.h>

#define BSZ   8
#define SEQ   4096
#define NTOK  3000
#define DIN   128
#define DM    512
#define DFF   2048
#define DOUT  64
#define DH    128
#define MTOT  (BSZ*SEQ)
#define MTPB  24                     // M-tiles per batch: ceil(3000/128)
#define SCALE 0.08838834764831845f   // 1/sqrt(128)
#define GEMM_SMEM (3*32768)          // 3 stages x (2 subchunks x 2 arrays x 8KB)
#define LA_SMEM   57344              // tile 32KB + qs 16KB + scores 8KB + pad
#define EXPF(x) __expf(x)

typedef __half fp16;

// ---------------- scratch (static device globals: no allocation) -------------
__device__ float g_h[MTOT*DM];
__device__ float g_q[MTOT*DM];
__device__ float g_k[MTOT*DM];
__device__ float g_v[MTOT*DM];
__device__ float g_kmax[BSZ*3*DH];
__device__ float g_lsep[BSZ*3*8*DH];
__device__ float g_ctxp[BSZ*3*8*DH*DH];
__device__ float g_ctx[BSZ*3*DH*DH];
__device__ float g_lnpad[DM];
__device__ float g_kpad[DM];
__device__ float g_vpad[DM];
// fp16 activation buffers
__device__ fp16 g_sh[MTOT*DM];
__device__ fp16 g_s2h[MTOT*DFF];
// transposed weights [N][K], fp16
__device__ fp16 g_w1h[DM*DIN];
__device__ fp16 g_wqh[DM*DM];
__device__ fp16 g_wkh[DM*DM];
__device__ fp16 g_wvh[DM*DM];
__device__ fp16 g_woh[DM*DM];
__device__ fp16 g_wf1h[DFF*DM];
__device__ fp16 g_wf2h[DM*DFF];
__device__ fp16 g_w2h[DOUT*DM];

// ---------------- helpers ----------------
__device__ __forceinline__ uint32_t smem_u32(const void* p) {
    uint32_t a;
    asm("{ .reg .u64 t; cvta.to.shared.u64 t, %1; cvt.u32.u64 %0, t; }" : "=r"(a) : "l"(p));
    return a;
}
__device__ __forceinline__ uint32_t pack2h(float x, float y) {
    __half2 h = __floats2half2_rn(x, y);
    return *reinterpret_cast<uint32_t*>(&h);
}

#define LDSM_X4(r0,r1,r2,r3,addr) \
    asm volatile("ldmatrix.sync.aligned.m8n8.x4.shared.b16 {%0,%1,%2,%3}, [%4];" \
        : "=r"(r0),"=r"(r1),"=r"(r2),"=r"(r3) : "r"(addr))
#define MMA16816(d, a0,a1,a2,a3, b0,b1) \
    asm volatile("mma.sync.aligned.m16n8k16.row.col.f32.f16.f16.f32 " \
        "{%0,%1,%2,%3},{%4,%5,%6,%7},{%8,%9},{%0,%1,%2,%3};" \
        : "+f"((d)[0]),"+f"((d)[1]),"+f"((d)[2]),"+f"((d)[3]) \
        : "r"(a0),"r"(a1),"r"(a2),"r"(a3),"r"(b0),"r"(b1))
#define CP_ASYNC16(dst, src, sz) \
    asm volatile("cp.async.cg.shared.global [%0], [%1], 16, %2;" :: "r"(dst), "l"(src), "r"(sz))
#define CP_COMMIT()  asm volatile("cp.async.commit_group;" ::: "memory")
#define CP_WAIT0()   asm volatile("cp.async.wait_group 0;" ::: "memory")
#define CP_WAIT1()   asm volatile("cp.async.wait_group 1;" ::: "memory")

// ---------------- weight transpose + fp16: T[n][k] = h(W[k][n]) --------------
__global__ void transpose_h_kernel(const float* __restrict__ W,
                                   fp16* __restrict__ Th, int K, int N) {
    __shared__ float t[32][33];
    int bx = blockIdx.x * 32, by = blockIdx.y * 32;
    int x = bx + threadIdx.x;
    #pragma unroll
    for (int i = 0; i < 32; i += 8) {
        int y = by + threadIdx.y + i;
        if (x < N && y < K) t[threadIdx.y + i][threadIdx.x] = W[(size_t)y * N + x];
    }
    __syncthreads();
    int xk = by + threadIdx.x;
    #pragma unroll
    for (int i = 0; i < 32; i += 8) {
        int yn = bx + threadIdx.y + i;
        if (xk < K && yn < N)
            Th[(size_t)yn * K + xk] = __float2half_rn(t[threadIdx.x][threadIdx.y + i]);
    }
}

// ---------------- x (real rows only) -> g_sh fp16 ----------------------------
__global__ void pad_split_kernel(const float* __restrict__ x) {
    int idx = blockIdx.x*256 + threadIdx.x;
    const int total = BSZ*NTOK*(DIN/4);
    if (idx >= total) return;
    int rr = idx >> 5;
    int c4 = idx & 31;
    int b = rr / NTOK, t = rr - b*NTOK;
    float4 val = reinterpret_cast<const float4*>(x)[(size_t)rr*32 + c4];
    uint2 hv;
    hv.x = pack2h(val.x, val.y);
    hv.y = pack2h(val.z, val.w);
    *reinterpret_cast<uint2*>(g_sh + (size_t)(b*SEQ + t)*DIN + c4*4) = hv;
}

// ---------------- pad-row LN: lnpad = LN(tanh(b1)) ---------------------------
__global__ void pad_ln_kernel(const float* __restrict__ b1, const float* __restrict__ gam,
                              const float* __restrict__ bet) {
    __shared__ float ss[16], ss2[16], stat[2];
    int t = threadIdx.x;
    float h = tanhf(b1[t]);
    float s = h, s2 = h*h;
    #pragma unroll
    for (int o=16;o;o>>=1) { s += __shfl_xor_sync(~0u,s,o); s2 += __shfl_xor_sync(~0u,s2,o); }
    if ((t & 31) == 0) { ss[t>>5] = s; ss2[t>>5] = s2; }
    __syncthreads();
    if (t == 0) {
        float S=0.f, S2=0.f;
        #pragma unroll
        for (int i=0;i<16;i++) { S += ss[i]; S2 += ss2[i]; }
        float mu = S*(1.f/512.f);
        float var = S2*(1.f/512.f) - mu*mu;
        stat[0] = mu; stat[1] = rsqrtf(var + 1e-5f);
    }
    __syncthreads();
    g_lnpad[t] = (h - stat[0])*stat[1]*gam[t] + bet[t];
}

// ---------------- pad-row k/v ------------------------------------------------
__global__ void pad_kv_kernel(const float* __restrict__ Wk, const float* __restrict__ Wv) {
    int d = blockIdx.x*256 + threadIdx.x;
    if (d >= 2*DM) return;
    const float* W = (d < DM) ? Wk : Wv;
    int dd = d & (DM-1);
    float s = 0.f;
    for (int kk = 0; kk < DM; kk++) s += g_lnpad[kk] * W[(size_t)kk*DM + dd];
    if (d < DM) g_kpad[dd] = s; else g_vpad[dd] = s;
}

// ---------------- broadcast pad k/v rows -------------------------------------
__global__ void padfill_kernel() {
    int idx = blockIdx.x*256 + threadIdx.x;
    const int per = (SEQ-NTOK)*(DM/4);
    if (idx >= BSZ*per) return;
    int b = idx / per, r = idx - b*per;
    int t = NTOK + r/(DM/4), c4 = r % (DM/4);
    size_t off = (size_t)(b*SEQ + t)*DM + c4*4;
    *reinterpret_cast<float4*>(g_k + off) = *reinterpret_cast<const float4*>(g_kpad + c4*4);
    *reinterpret_cast<float4*>(g_v + off) = *reinterpret_cast<const float4*>(g_vpad + c4*4);
}

// ---------------- fp16 tensor-core GEMM, K-chunk 64 (real rows) --------------
__global__ __launch_bounds__(256, 2) void tc_gemm_kernel(
    const fp16* __restrict__ A, const fp16* __restrict__ B,
    const float* __restrict__ bias, const float* __restrict__ res,
    float* __restrict__ C, fp16* __restrict__ Ch,
    int N, int K, int act, int omul)
{
    extern __shared__ __align__(1024) char smc[];
    uint32_t sbase = smem_u32(smc);
    int tid = threadIdx.x;
    int mtile = blockIdx.y;
    int bb = mtile / MTPB, t0 = (mtile - bb*MTPB) << 7;
    int bm = bb*SEQ + t0;
    int alim = NTOK - t0;
    int rowlim = bm + alim;
    int odelta = bb*(omul - SEQ);
    int bn = blockIdx.x << 7;
    int lane = tid & 31, w = tid >> 5;
    int wm = w & 1, wn = w >> 1;
    int grp = lane >> 2, qp = lane & 3;

    uint32_t swz = (lane >> 1) & 3;
    uint32_t a_base = (uint32_t)(wm*64 + (lane & 15))*64 + (((uint32_t)(lane >> 4) ^ swz) << 4);
    uint32_t b_base = (uint32_t)(wn*32 + ((lane >> 4) & 1)*8 + (lane & 7))*64
                    + ((((uint32_t)(lane >> 3) & 1) ^ swz) << 4);

    float acc[4][4][4];
    #pragma unroll
    for (int i=0;i<4;i++)
        #pragma unroll
        for (int j=0;j<4;j++)
            #pragma unroll
            for (int r=0;r<4;r++) acc[i][j][r] = 0.f;

    const int NC = K >> 6;   // 64-wide K chunks

    #define STAGE_LOAD(c_, buf_) do { \
        uint32_t sb = sbase + (uint32_t)(buf_)*32768u; \
        _Pragma("unroll") \
        for (int i_ = 0; i_ < 8; i_++) { \
            const int sub_ = i_ >> 2; \
            const int arr_ = (i_ >> 1) & 1; \
            int j_ = ((i_ & 1) << 8) + tid; \
            int r_ = j_ >> 2, cc_ = j_ & 3; \
            int k0 = ((c_) << 6) + sub_*32; \
            uint32_t dst_ = sb + (uint32_t)sub_*16384u + (uint32_t)arr_*8192u \
                          + (uint32_t)r_*64u + ((uint32_t)(cc_ ^ ((r_ >> 1) & 3)) << 4); \
            const fp16* g_; int sz_ = 16; \
            if (arr_ == 0) { \
                if (r_ < alim) g_ = A + (size_t)(bm + r_)*K + k0 + cc_*8; \
                else { g_ = A; sz_ = 0; } \
            } else { \
                int rowv_ = bn + r_; \
                if (rowv_ < N) g_ = B + (size_t)rowv_*K + k0 + cc_*8; \
                else { g_ = B; sz_ = 0; } \
            } \
            CP_ASYNC16(dst_, g_, sz_); \
        } \
        CP_COMMIT(); \
    } while (0)

    STAGE_LOAD(0, 0);
    if (NC > 1) STAGE_LOAD(1, 1);

    int buf = 0, bufn = 2;
    for (int c = 0; c < NC; c++) {
        if (c + 1 < NC) CP_WAIT1(); else CP_WAIT0();
        __syncthreads();
        if (c + 2 < NC) {
            STAGE_LOAD(c + 2, bufn);
            bufn = (bufn == 2) ? 0 : bufn + 1;
        }
        uint32_t stg = sbase + (uint32_t)buf*32768u;
        buf = (buf == 2) ? 0 : buf + 1;

        #pragma unroll
        for (int sub = 0; sub < 2; sub++) {
            uint32_t sA = stg + (uint32_t)sub*16384u;
            uint32_t sB = sA + 8192u;
            #pragma unroll
            for (int ks = 0; ks < 2; ks++) {
                uint32_t kx = ks ? 32u : 0u;
                uint32_t bh[4][2], a[4][4];
                #pragma unroll
                for (int p = 0; p < 2; p++)
                    LDSM_X4(bh[2*p][0], bh[2*p][1], bh[2*p+1][0], bh[2*p+1][1],
                            sB + ((b_base + p*1024u) ^ kx));
                #pragma unroll
                for (int mt = 0; mt < 4; mt++)
                    LDSM_X4(a[mt][0], a[mt][1], a[mt][2], a[mt][3],
                            sA + ((a_base + mt*1024u) ^ kx));
                #pragma unroll
                for (int mt = 0; mt < 4; mt++)
                    #pragma unroll
                    for (int nt = 0; nt < 4; nt++)
                        MMA16816(acc[mt][nt], a[mt][0],a[mt][1],a[mt][2],a[mt][3],
                                 bh[nt][0],bh[nt][1]);
            }
        }
    }
    #undef STAGE_LOAD

    // ---- epilogue (valid rows only) ----
    #pragma unroll
    for (int mt = 0; mt < 4; mt++) {
        #pragma unroll
        for (int nt = 0; nt < 4; nt++) {
            int c0 = bn + wn*32 + nt*8 + qp*2;
            if (c0 >= N) continue;
            int rbase = bm + wm*64 + mt*16 + grp;
            float bs0 = 0.f, bs1 = 0.f;
            if (bias) { bs0 = bias[c0]; bs1 = bias[c0 + 1]; }
            #pragma unroll
            for (int half = 0; half < 2; half++) {
                int r = rbase + half*8;
                if (r >= rowlim) continue;
                float v0 = acc[mt][nt][half*2 + 0] + bs0;
                float v1 = acc[mt][nt][half*2 + 1] + bs1;
                if (act == 1) { v0 = tanhf(v0); v1 = tanhf(v1); }
                else if (act == 2) {
                    v0 = 0.5f*v0*(1.f + erff(v0*0.7071067811865476f));
                    v1 = 0.5f*v1*(1.f + erff(v1*0.7071067811865476f));
                }
                if (res) {
                    v0 += res[(size_t)r*N + c0];
                    v1 += res[(size_t)r*N + c0 + 1];
                }
                size_t orow = (size_t)(r + odelta);
                if (Ch) {
                    *reinterpret_cast<uint32_t*>(Ch + orow*N + c0) = pack2h(v0, v1);
                } else {
                    float2 o; o.x = v0; o.y = v1;
                    *reinterpret_cast<float2*>(C + orow*N + c0) = o;
                }
            }
        }
    }
}

// ---------------- LayerNorm (real rows) -> fp16 ------------------------------
__global__ void ln_kernel(const float* __restrict__ in, const float* __restrict__ gam,
                          const float* __restrict__ bet) {
    int gw = (blockIdx.x*blockDim.x + threadIdx.x) >> 5;
    int lane = threadIdx.x & 31;
    if (gw >= BSZ*NTOK) return;
    int b = gw / NTOK, t = gw - b*NTOK;
    size_t row = (size_t)(b*SEQ + t);
    const float4* rp = reinterpret_cast<const float4*>(in + row*DM);
    float4 v[4];
    float s=0.f, s2=0.f;
    #pragma unroll
    for (int i=0;i<4;i++) {
        v[i] = rp[lane + 32*i];
        s  += v[i].x+v[i].y+v[i].z+v[i].w;
        s2 += v[i].x*v[i].x + v[i].y*v[i].y + v[i].z*v[i].z + v[i].w*v[i].w;
    }
    #pragma unroll
    for (int o=16;o;o>>=1) { s += __shfl_xor_sync(~0u,s,o); s2 += __shfl_xor_sync(~0u,s2,o); }
    float mu  = s*(1.f/512.f);
    float var = s2*(1.f/512.f) - mu*mu;
    float r = rsqrtf(var + 1e-5f);
    #pragma unroll
    for (int i=0;i<4;i++) {
        int c = (lane + 32*i)*4;
        float4 g4 = *reinterpret_cast<const float4*>(gam + c);
        float4 b4 = *reinterpret_cast<const float4*>(bet + c);
        uint2 hv;
        hv.x = pack2h((v[i].x-mu)*r*g4.x + b4.x, (v[i].y-mu)*r*g4.y + b4.y);
        hv.y = pack2h((v[i].z-mu)*r*g4.z + b4.z, (v[i].w-mu)*r*g4.w + b4.w);
        *reinterpret_cast<uint2*>(g_sh + row*DM + c) = hv;
    }
}

// ---------------- local attention, head 0 (shuffle-free scores) -------------
// dyn smem: tile[64][128] @0 (32KB), qs[32][128] @8192 floats (16KB),
//           scores[32][64] @12288 floats (8KB)
__global__ __launch_bounds__(1024) void local_attn_kernel() {
    extern __shared__ float dyn[];
    float* tile   = dyn;            // [64][128]
    float* qs     = dyn + 8192;     // [32][128]
    float* scores = dyn + 12288;    // [32][64]
    int b   = blockIdx.x / 94;
    int blk = blockIdx.x - b*94;
    int win = blk >> 2;
    int qc  = blk & 3;
    int warp = threadIdx.x >> 5, lane = threadIdx.x & 31;
    int qt = win*128 + qc*32 + warp;
    size_t qoff = (size_t)(b*SEQ + qt)*DM;
    {
        float4 q4 = *reinterpret_cast<const float4*>(g_q + qoff + lane*4);
        *reinterpret_cast<float4*>(qs + warp*128 + lane*4) = q4;
    }
    __syncwarp();
    float m = -1e30f, l = 0.f;
    float4 acc = make_float4(0.f,0.f,0.f,0.f);
    int kbase = win*128 - 128;
    for (int ch=0; ch<6; ch++) {
        int t0 = kbase + ch*64;
        __syncthreads();
        #pragma unroll
        for (int it=0; it<2; it++) {
            int idx = it*1024 + threadIdx.x;
            int r = idx >> 5, c4 = idx & 31;
            int t = t0 + r;
            float4 kv = make_float4(0.f,0.f,0.f,0.f);
            if (t >= 0 && t < SEQ)
                kv = *reinterpret_cast<const float4*>(g_k + (size_t)(b*SEQ+t)*DM + c4*4);
            *reinterpret_cast<float4*>(tile + r*128 + c4*4) = kv;
        }
        __syncthreads();
        // per-lane complete dot products for keys j0=lane, j1=lane+32
        float s0 = 0.f, s1 = 0.f;
        const float* qrow = qs + warp*128;
        #pragma unroll
        for (int it=0; it<32; it++) {
            int d4 = ((it + lane) & 31)*4;
            float4 qv = *reinterpret_cast<const float4*>(qrow + d4);
            float4 k0 = *reinterpret_cast<const float4*>(tile + lane*128 + d4);
            float4 k1 = *reinterpret_cast<const float4*>(tile + (lane+32)*128 + d4);
            s0 = fmaf(qv.x,k0.x, fmaf(qv.y,k0.y, fmaf(qv.z,k0.z, fmaf(qv.w,k0.w, s0))));
            s1 = fmaf(qv.x,k1.x, fmaf(qv.y,k1.y, fmaf(qv.z,k1.z, fmaf(qv.w,k1.w, s1))));
        }
        {
            int ta = t0 + lane, tb = t0 + lane + 32;
            s0 = (ta >= 0 && ta < SEQ) ? s0*SCALE : -1e38f;
            s1 = (tb >= 0 && tb < SEQ) ? s1*SCALE : -1e38f;
        }
        __syncthreads();    // all warps done reading K tile
        #pragma unroll
        for (int it=0; it<2; it++) {
            int idx = it*1024 + threadIdx.x;
            int r = idx >> 5, c4 = idx & 31;
            int t = t0 + r;
            float4 vv = make_float4(0.f,0.f,0.f,0.f);
            if (t >= 0 && t < SEQ)
                vv = *reinterpret_cast<const float4*>(g_v + (size_t)(b*SEQ+t)*DM + c4*4);
            *reinterpret_cast<float4*>(tile + r*128 + c4*4) = vv;
        }
        float cm = fmaxf(s0, s1);
        #pragma unroll
        for (int o=16;o;o>>=1) cm = fmaxf(cm, __shfl_xor_sync(~0u,cm,o));
        float mn = fmaxf(m, cm);
        float corr = EXPF(m - mn);
        l *= corr; acc.x*=corr; acc.y*=corr; acc.z*=corr; acc.w*=corr;
        float p0 = EXPF(s0 - mn), p1 = EXPF(s1 - mn);
        l += p0 + p1;
        scores[warp*64 + lane] = p0;
        scores[warp*64 + lane + 32] = p1;
        __syncthreads();    // V tile + scores ready
        for (int j=0; j<64; j++) {
            float p = scores[warp*64 + j];
            float4 vv = *reinterpret_cast<const float4*>(tile + j*128 + lane*4);
            acc.x = fmaf(p, vv.x, acc.x);
            acc.y = fmaf(p, vv.y, acc.y);
            acc.z = fmaf(p, vv.z, acc.z);
            acc.w = fmaf(p, vv.w, acc.w);
        }
        m = mn;
    }
    #pragma unroll
    for (int o=16;o;o>>=1) l += __shfl_xor_sync(~0u,l,o);
    float inv = 1.f/l;
    uint2 hv;
    hv.x = pack2h(acc.x*inv, acc.y*inv);
    hv.y = pack2h(acc.z*inv, acc.w*inv);
    *reinterpret_cast<uint2*>(g_sh + qoff + lane*4) = hv;
}

// ---------------- k column max (heads 1..3) ----------------------------------
__global__ void kmax_kernel() {
    int bh = blockIdx.x;
    int b = bh/3, hh = bh%3 + 1;
    int d = blockIdx.y*32 + threadIdx.x;
    int ty = threadIdx.y;
    int col = hh*DH + d;
    float m = -1e30f;
    for (int t = ty; t < SEQ; t += 8)
        m = fmaxf(m, g_k[(size_t)(b*SEQ+t)*DM + col]);
    __shared__ float sm[8][32];
    sm[ty][threadIdx.x] = m;
    __syncthreads();
    if (ty == 0) {
        #pragma unroll
        for (int r=1;r<8;r++) m = fmaxf(m, sm[r][threadIdx.x]);
        g_kmax[bh*DH + d] = m;
    }
}

// ---------------- ctx partial: unnormalized e@v + lse partials ---------------
__global__ __launch_bounds__(256) void ctx_partial_kernel() {
    __shared__ float kt[32][132];
    __shared__ float vt[32][132];
    __shared__ float smax[DH];
    int bh = blockIdx.x, ks = blockIdx.y;
    int b = bh/3, hh = bh%3 + 1;
    if (threadIdx.x < DH)
        smax[threadIdx.x] = g_kmax[bh*DH + threadIdx.x];
    int tx = threadIdx.x & 15, ty = threadIdx.x >> 4;
    int lr0 = threadIdx.x >> 5, lc4 = threadIdx.x & 31;
    float acc[8][8];
    float4 lacc = make_float4(0.f,0.f,0.f,0.f);
    #pragma unroll
    for (int i=0;i<8;i++)
        #pragma unroll
        for (int j=0;j<8;j++) acc[i][j]=0.f;

    for (int t0=0; t0<512; t0+=32) {
        __syncthreads();
        #pragma unroll
        for (int i=0;i<4;i++) {
            int r = lr0 + 8*i;
            int t = ks*512 + t0 + r;
            size_t off = (size_t)(b*SEQ+t)*DM + hh*DH + lc4*4;
            float4 kv = *reinterpret_cast<const float4*>(g_k + off);
            float4 vv = *reinterpret_cast<const float4*>(g_v + off);
            int d0 = lc4*4;
            float e0 = EXPF(kv.x - smax[d0+0]);
            float e1 = EXPF(kv.y - smax[d0+1]);
            float e2 = EXPF(kv.z - smax[d0+2]);
            float e3 = EXPF(kv.w - smax[d0+3]);
            kt[r][d0+0] = e0; kt[r][d0+1] = e1; kt[r][d0+2] = e2; kt[r][d0+3] = e3;
            lacc.x += e0; lacc.y += e1; lacc.z += e2; lacc.w += e3;
            *reinterpret_cast<float4*>(&vt[r][d0]) = vv;
        }
        __syncthreads();
        #pragma unroll
        for (int kk=0; kk<32; kk++) {
            float a[8], bb[8];
            *reinterpret_cast<float4*>(&a[0])  = *reinterpret_cast<const float4*>(&kt[kk][ty*8]);
            *reinterpret_cast<float4*>(&a[4])  = *reinterpret_cast<const float4*>(&kt[kk][ty*8+4]);
            *reinterpret_cast<float4*>(&bb[0]) = *reinterpret_cast<const float4*>(&vt[kk][tx*8]);
            *reinterpret_cast<float4*>(&bb[4]) = *reinterpret_cast<const float4*>(&vt[kk][tx*8+4]);
            #pragma unroll
            for (int i=0;i<8;i++)
                #pragma unroll
                for (int j=0;j<8;j++)
                    acc[i][j] = fmaf(a[i], bb[j], acc[i][j]);
        }
    }
    __syncthreads();
    *reinterpret_cast<float4*>(&kt[lr0][lc4*4]) = lacc;
    __syncthreads();
    if (threadIdx.x < DH) {
        float s = 0.f;
        #pragma unroll
        for (int j=0;j<8;j++) s += kt[j][threadIdx.x];
        g_lsep[(bh*8 + ks)*DH + threadIdx.x] = s;
    }
    float* op = g_ctxp + ((size_t)bh*8 + ks)*DH*DH;
    #pragma unroll
    for (int i=0;i<8;i++)
        #pragma unroll
        for (int j=0;j<8;j+=4) {
            float4 o4 = make_float4(acc[i][j],acc[i][j+1],acc[i][j+2],acc[i][j+3]);
            *reinterpret_cast<float4*>(op + (size_t)(ty*8+i)*DH + tx*8 + j) = o4;
        }
}

// ---------------- ctx reduce + normalize by lse ------------------------------
__global__ void ctx_reduce_kernel() {
    int idx = blockIdx.x*256 + threadIdx.x;
    if (idx >= BSZ*3*DH*DH) return;
    int bh = idx / (DH*DH);
    int de = idx - bh*DH*DH;
    int d = de >> 7;
    float s = 0.f, ls = 0.f;
    #pragma unroll
    for (int ks=0;ks<8;ks++) {
        s  += g_ctxp[((size_t)bh*8+ks)*DH*DH + de];
        ls += g_lsep[(bh*8+ks)*DH + d];
    }
    g_ctx[idx] = s / ls;
}

// ---------------- linear-attn output -> fp16 ---------------------------------
__global__ __launch_bounds__(256) void lin_out_kernel() {
    __shared__ float sctx[64][DH];
    int bh = blockIdx.x;
    int b = bh/3, hh = bh%3 + 1;
    int warp = threadIdx.x >> 5, lane = threadIdx.x & 31;
    const float* ctxp = g_ctx + (size_t)bh*DH*DH;
    float pr[4][4], o[4][4];
    int tbase = blockIdx.y*32 + warp*4;
    #pragma unroll
    for (int tt=0;tt<4;tt++) {
        int t = tbase + tt;
        const float* qp = g_q + (size_t)(b*SEQ+t)*DM + hh*DH;
        float4 q4 = *reinterpret_cast<const float4*>(qp + lane*4);
        float mx = fmaxf(fmaxf(q4.x,q4.y),fmaxf(q4.z,q4.w));
        #pragma unroll
        for (int s=16;s;s>>=1) mx = fmaxf(mx, __shfl_xor_sync(~0u,mx,s));
        float e0=EXPF(q4.x-mx), e1=EXPF(q4.y-mx), e2=EXPF(q4.z-mx), e3=EXPF(q4.w-mx);
        float sm = e0+e1+e2+e3;
        #pragma unroll
        for (int s=16;s;s>>=1) sm += __shfl_xor_sync(~0u,sm,s);
        float inv = SCALE/sm;
        pr[tt][0]=e0*inv; pr[tt][1]=e1*inv; pr[tt][2]=e2*inv; pr[tt][3]=e3*inv;
        o[tt][0]=0.f; o[tt][1]=0.f; o[tt][2]=0.f; o[tt][3]=0.f;
    }
    for (int ph=0; ph<2; ph++) {
        __syncthreads();
        #pragma unroll
        for (int i=0;i<8;i++) {
            int idx = i*256 + threadIdx.x;
            int r = idx >> 5, c4 = idx & 31;
            *reinterpret_cast<float4*>(&sctx[r][c4*4]) =
                *reinterpret_cast<const float4*>(ctxp + (size_t)(ph*64+r)*DH + c4*4);
        }
        __syncthreads();
        #pragma unroll
        for (int dl=0; dl<16; dl++) {
            int src = ph*16 + dl;
            #pragma unroll
            for (int tt=0;tt<4;tt++) {
                float b0 = __shfl_sync(~0u, pr[tt][0], src);
                float b1 = __shfl_sync(~0u, pr[tt][1], src);
                float b2 = __shfl_sync(~0u, pr[tt][2], src);
                float b3 = __shfl_sync(~0u, pr[tt][3], src);
                float4 c0 = *reinterpret_cast<const float4*>(&sctx[dl*4+0][lane*4]);
                float4 c1 = *reinterpret_cast<const float4*>(&sctx[dl*4+1][lane*4]);
                float4 c2 = *reinterpret_cast<const float4*>(&sctx[dl*4+2][lane*4]);
                float4 c3 = *reinterpret_cast<const float4*>(&sctx[dl*4+3][lane*4]);
                o[tt][0] += b0*c0.x + b1*c1.x + b2*c2.x + b3*c3.x;
                o[tt][1] += b0*c0.y + b1*c1.y + b2*c2.y + b3*c3.y;
                o[tt][2] += b0*c0.z + b1*c1.z + b2*c2.z + b3*c3.z;
                o[tt][3] += b0*c0.w + b1*c1.w + b2*c2.w + b3*c3.w;
            }
        }
    }
    #pragma unroll
    for (int tt=0;tt<4;tt++) {
        int t = tbase + tt;
        uint2 hv;
        hv.x = pack2h(o[tt][0], o[tt][1]);
        hv.y = pack2h(o[tt][2], o[tt][3]);
        *reinterpret_cast<uint2*>(g_sh + (size_t)(b*SEQ+t)*DM + hh*DH + lane*4) = hv;
    }
}

// ---------------- host ---------------------------------------------------
static inline void tc_gemm(cudaStream_t st, const fp16* A, const fp16* B,
                           const float* bias, const float* res,
                           float* C, fp16* Ch, int N, int K, int act, int omul = SEQ) {
    dim3 grid((N + 127) / 128, BSZ*MTPB);
    tc_gemm_kernel<<<grid, 256, GEMM_SMEM, st>>>(A, B, bias, res, C, Ch, N, K, act, omul);
}

extern "C" void kernel_launch(void* const* d_in, const int* in_sizes, int n_in,
                              void* d_out, int out_size) {
    const float* x    = (const float*)d_in[0];
    const float* W1   = (const float*)d_in[1];
    const float* b1   = (const float*)d_in[2];
    const float* ln1g = (const float*)d_in[3];
    const float* ln1b = (const float*)d_in[4];
    const float* Wq   = (const float*)d_in[5];
    const float* Wk   = (const float*)d_in[6];
    const float* Wv   = (const float*)d_in[7];
    const float* Wo   = (const float*)d_in[8];
    const float* bo   = (const float*)d_in[9];
    const float* ln2g = (const float*)d_in[10];
    const float* ln2b = (const float*)d_in[11];
    const float* Wf1  = (const float*)d_in[12];
    const float* bf1  = (const float*)d_in[13];
    const float* Wf2  = (const float*)d_in[14];
    const float* bf2  = (const float*)d_in[15];
    const float* W2   = (const float*)d_in[16];
    const float* b2   = (const float*)d_in[17];
    float* out = (float*)d_out;

    static int init_done = 0;
    static cudaStream_t st1, st2;
    static cudaEvent_t evStart, evT1, evQKV, evPad, evLin;
    if (!init_done) {
        cudaFuncSetAttribute(tc_gemm_kernel, cudaFuncAttributeMaxDynamicSharedMemorySize, GEMM_SMEM);
        cudaFuncSetAttribute(local_attn_kernel, cudaFuncAttributeMaxDynamicSharedMemorySize, LA_SMEM);
        cudaStreamCreateWithFlags(&st1, cudaStreamNonBlocking);
        cudaStreamCreateWithFlags(&st2, cudaStreamNonBlocking);
        cudaEventCreateWithFlags(&evStart, cudaEventDisableTiming);
        cudaEventCreateWithFlags(&evT1,    cudaEventDisableTiming);
        cudaEventCreateWithFlags(&evQKV,   cudaEventDisableTiming);
        cudaEventCreateWithFlags(&evPad,   cudaEventDisableTiming);
        cudaEventCreateWithFlags(&evLin,   cudaEventDisableTiming);
        init_done = 1;
    }

    float *h,*q,*k,*v;
    fp16 *sh,*s2h;
    fp16 *w1h,*wqh,*wkh,*wvh,*woh,*wf1h,*wf2h,*w2h;
    cudaGetSymbolAddress((void**)&h,    g_h);
    cudaGetSymbolAddress((void**)&q,    g_q);
    cudaGetSymbolAddress((void**)&k,    g_k);
    cudaGetSymbolAddress((void**)&v,    g_v);
    cudaGetSymbolAddress((void**)&sh,   g_sh);
    cudaGetSymbolAddress((void**)&s2h,  g_s2h);
    cudaGetSymbolAddress((void**)&w1h,  g_w1h);
    cudaGetSymbolAddress((void**)&wqh,  g_wqh);
    cudaGetSymbolAddress((void**)&wkh,  g_wkh);
    cudaGetSymbolAddress((void**)&wvh,  g_wvh);
    cudaGetSymbolAddress((void**)&woh,  g_woh);
    cudaGetSymbolAddress((void**)&wf1h, g_wf1h);
    cudaGetSymbolAddress((void**)&wf2h, g_wf2h);
    cudaGetSymbolAddress((void**)&w2h,  g_w2h);

    dim3 tb(32, 8);

    // fork: pad-row chain (st2) and weight transposes (st1)
    cudaEventRecord(evStart, 0);
    cudaStreamWaitEvent(st2, evStart, 0);
    pad_ln_kernel<<<1, 512, 0, st2>>>(b1, ln1g, ln1b);
    pad_kv_kernel<<<4, 256, 0, st2>>>(Wk, Wv);
    padfill_kernel<<<(BSZ*(SEQ-NTOK)*(DM/4) + 255)/256, 256, 0, st2>>>();
    cudaEventRecord(evPad, st2);

    cudaStreamWaitEvent(st1, evStart, 0);
    transpose_h_kernel<<<dim3(DM/32,  DM/32),  tb, 0, st1>>>(Wq,  wqh,  DM,  DM);
    transpose_h_kernel<<<dim3(DM/32,  DM/32),  tb, 0, st1>>>(Wk,  wkh,  DM,  DM);
    transpose_h_kernel<<<dim3(DM/32,  DM/32),  tb, 0, st1>>>(Wv,  wvh,  DM,  DM);
    transpose_h_kernel<<<dim3(DM/32,  DM/32),  tb, 0, st1>>>(Wo,  woh,  DM,  DM);
    transpose_h_kernel<<<dim3(DFF/32, DM/32),  tb, 0, st1>>>(Wf1, wf1h, DM,  DFF);
    transpose_h_kernel<<<dim3(DM/32,  DFF/32), tb, 0, st1>>>(Wf2, wf2h, DFF, DM);
    transpose_h_kernel<<<dim3(DOUT/32,DM/32),  tb, 0, st1>>>(W2,  w2h,  DM,  DOUT);
    cudaEventRecord(evT1, st1);

    // main stream
    transpose_h_kernel<<<dim3(DM/32, DIN/32), tb>>>(W1, w1h, DIN, DM);
    pad_split_kernel<<<(BSZ*NTOK*(DIN/4) + 255)/256, 256>>>(x);
    tc_gemm(0, sh, w1h, b1, nullptr, h, nullptr, DM, DIN, 1);
    ln_kernel<<<BSZ*NTOK/8, 256>>>(h, ln1g, ln1b);
    cudaStreamWaitEvent(0, evT1, 0);
    tc_gemm(0, sh, wqh, nullptr, nullptr, q, nullptr, DM, DM, 0);
    tc_gemm(0, sh, wkh, nullptr, nullptr, k, nullptr, DM, DM, 0);
    tc_gemm(0, sh, wvh, nullptr, nullptr, v, nullptr, DM, DM, 0);
    cudaEventRecord(evQKV, 0);

    // linear-attn chain on st1, local attention on main stream
    cudaStreamWaitEvent(st1, evQKV, 0);
    cudaStreamWaitEvent(st1, evPad, 0);
    kmax_kernel<<<dim3(BSZ*3,4), dim3(32,8), 0, st1>>>();
    ctx_partial_kernel<<<dim3(BSZ*3,8), 256, 0, st1>>>();
    ctx_reduce_kernel<<<(BSZ*3*DH*DH + 255)/256, 256, 0, st1>>>();
    lin_out_kernel<<<dim3(BSZ*3, 94), 256, 0, st1>>>();
    cudaEventRecord(evLin, st1);

    cudaStreamWaitEvent(0, evPad, 0);
    local_attn_kernel<<<BSZ*94, 1024, LA_SMEM>>>();
    cudaStreamWaitEvent(0, evLin, 0);

    // tail on main stream
    tc_gemm(0, sh, woh, bo, h, h, nullptr, DM, DM, 0);
    ln_kernel<<<BSZ*NTOK/8, 256>>>(h, ln2g, ln2b);
    tc_gemm(0, sh, wf1h, bf1, nullptr, nullptr, s2h, DFF, DM, 2);
    tc_gemm(0, s2h, wf2h, bf2, h, nullptr, sh, DM, DFF, 0);
    tc_gemm(0, sh, w2h, b2, nullptr, out, nullptr, DOUT, DM, 0, NTOK);
}